// round 1
// baseline (speedup 1.0000x reference)
#include <cuda_runtime.h>
#include <math.h>

typedef unsigned long long U64;

constexpr int Bb  = 8;
constexpr int Cc  = 512;
constexpr int Nn  = 3136;   // 56*56 = 49 * 64
constexpr int ICc = 256;

// ---------------- scratch (static device memory; no allocations) ----------------
__device__ __align__(256) float g_Q[Bb * Nn * ICc];   // [b][n][ic]
__device__ __align__(256) float g_K[Bb * Nn * ICc];   // [b][n][ic]
__device__ __align__(256) float g_V[Bb * Nn * ICc];   // [b][n][ic]
__device__ __align__(256) float g_Y[Bb * Nn * ICc];   // attention out [b][n][ic]
__device__ __align__(256) float g_Z[Bb * Cc * Nn];    // pre-BN y, [b][c][n]
__device__ float g_scaleC[Cc];
__device__ float g_shiftC[Cc];

// ---------------- packed f32x2 helpers ----------------
__device__ __forceinline__ U64 pk2(float a, float b) {
    U64 r; asm("mov.b64 %0, {%1, %2};" : "=l"(r) : "f"(a), "f"(b)); return r;
}
__device__ __forceinline__ void up2(U64 v, float& a, float& b) {
    asm("mov.b64 {%0, %1}, %2;" : "=f"(a), "=f"(b) : "l"(v));
}
__device__ __forceinline__ void fma2(U64& d, U64 a, U64 b) {
    asm("fma.rn.f32x2 %0, %1, %2, %0;" : "+l"(d) : "l"(a), "l"(b));
}
__device__ __forceinline__ U64 mul2(U64 a, U64 b) {
    U64 r; asm("mul.rn.f32x2 %0, %1, %2;" : "=l"(r) : "l"(a), "l"(b)); return r;
}

// =====================================================================
// K1: QKV projection.  out[b][n][i] = sum_c x[b][c][n] * W[i][c] + bias[i]
// x is [C][N] per batch = A^T already -> direct coalesced A-tile loads.
// Tiles: BM=64 (n), BN=64 (i), BK=16 (c). 256 threads, 4x4 outputs/thread
// as 4 rows x 2 f32x2 column-pairs (i = 2tx, 2tx+1, 2tx+32, 2tx+33).
// =====================================================================
__global__ __launch_bounds__(256) void qkv_kernel(
    const float* __restrict__ x, const float* __restrict__ W,
    const float* __restrict__ bias, int sel)
{
    float* out = (sel == 0) ? g_Q : (sel == 1) ? g_K : g_V;

    __shared__ float As[16][64];   // [c][n]
    __shared__ float Bs[16][68];   // [c][i]  (stride 68: 16B-aligned rows)

    const int t  = threadIdx.x;
    const int tx = t & 15, ty = t >> 4;
    const int n0 = blockIdx.x * 64;
    const int i0 = blockIdx.y * 64;
    const int b  = blockIdx.z;
    const float* xb = x + (size_t)b * Cc * Nn;

    U64 acc0[4], acc1[4];
#pragma unroll
    for (int r = 0; r < 4; r++) { acc0[r] = 0ull; acc1[r] = 0ull; }

    const int lc  = t >> 4;   // A load: c row 0..15
    const int lnq = t & 15;   // A load: float4 col
    const int li  = t >> 2;   // B load: i row 0..63
    const int lcq = t & 3;    // B load: c quad

    for (int ck = 0; ck < Cc; ck += 16) {
        // A tile (coalesced)
        float4 av = *reinterpret_cast<const float4*>(xb + (size_t)(ck + lc) * Nn + n0 + lnq * 4);
        *reinterpret_cast<float4*>(&As[lc][lnq * 4]) = av;
        // B tile (transpose scatter)
        float4 wv = *reinterpret_cast<const float4*>(W + (size_t)(i0 + li) * Cc + ck + lcq * 4);
        Bs[lcq * 4 + 0][li] = wv.x;
        Bs[lcq * 4 + 1][li] = wv.y;
        Bs[lcq * 4 + 2][li] = wv.z;
        Bs[lcq * 4 + 3][li] = wv.w;
        __syncthreads();

#pragma unroll
        for (int c = 0; c < 16; c++) {
            float4 a = *reinterpret_cast<const float4*>(&As[c][ty * 4]);
            U64 b0 = *reinterpret_cast<const U64*>(&Bs[c][2 * tx]);
            U64 b1 = *reinterpret_cast<const U64*>(&Bs[c][2 * tx + 32]);
            U64 a0 = pk2(a.x, a.x), a1 = pk2(a.y, a.y);
            U64 a2 = pk2(a.z, a.z), a3 = pk2(a.w, a.w);
            fma2(acc0[0], a0, b0); fma2(acc1[0], a0, b1);
            fma2(acc0[1], a1, b0); fma2(acc1[1], a1, b1);
            fma2(acc0[2], a2, b0); fma2(acc1[2], a2, b1);
            fma2(acc0[3], a3, b0); fma2(acc1[3], a3, b1);
        }
        __syncthreads();
    }

    const float b0a = bias[i0 + 2 * tx],      b0b = bias[i0 + 2 * tx + 1];
    const float b1a = bias[i0 + 2 * tx + 32], b1b = bias[i0 + 2 * tx + 33];
    float* ob = out + (size_t)b * Nn * ICc;
#pragma unroll
    for (int r = 0; r < 4; r++) {
        float s0, s1, s2, s3;
        up2(acc0[r], s0, s1); up2(acc1[r], s2, s3);
        float* row = ob + (size_t)(n0 + ty * 4 + r) * ICc + i0;
        *reinterpret_cast<float2*>(row + 2 * tx)      = make_float2(s0 + b0a, s1 + b0b);
        *reinterpret_cast<float2*>(row + 2 * tx + 32) = make_float2(s2 + b1a, s3 + b1b);
    }
}

// =====================================================================
// K2: flash attention (fp32). Block = (b, 64-query tile), 256 threads.
// smem: Qs[d][q] (256x68), Ks[d][k] (256x66), Vs[k][d] (64x264), Ps[q][k] (64x66)
// Thread owns q rows ty*4..+3; k cols {2tx,2tx+1,2tx+32,2tx+33};
// O cols d = 2tx + 32j (j=0..7) -> conflict-free f32x2 LDS for V.
// =====================================================================
constexpr int QS_S = 68;
constexpr int KS_S = 66;
constexpr int VS_S = 264;
constexpr int PS_S = 66;
constexpr int ATTN_SMEM = (256 * QS_S + 256 * KS_S + 64 * VS_S + 64 * PS_S) * 4; // 221696 B

__global__ __launch_bounds__(256, 1) void attn_kernel()
{
    extern __shared__ float sm[];
    float* Qs = sm;                      // [256][68]
    float* Ks = Qs + 256 * QS_S;         // [256][66]
    float* Vs = Ks + 256 * KS_S;         // [64][264]
    float* Ps = Vs + 64 * VS_S;          // [64][66]

    const int t  = threadIdx.x;
    const int tx = t & 15, ty = t >> 4;
    const int qt = blockIdx.x, b = blockIdx.y;
    const int n0 = qt * 64;

    const float* Qg = g_Q + ((size_t)b * Nn + n0) * ICc;
    const float* Kg = g_K + (size_t)b * Nn * ICc;
    const float* Vg = g_V + (size_t)b * Nn * ICc;

    // load Q transposed: Qs[d][q]
#pragma unroll
    for (int it = 0; it < 16; it++) {
        int idx = it * 256 + t;
        int q = idx >> 6, dq = idx & 63;
        float4 v = *reinterpret_cast<const float4*>(Qg + (size_t)q * ICc + dq * 4);
        Qs[(dq * 4 + 0) * QS_S + q] = v.x;
        Qs[(dq * 4 + 1) * QS_S + q] = v.y;
        Qs[(dq * 4 + 2) * QS_S + q] = v.z;
        Qs[(dq * 4 + 3) * QS_S + q] = v.w;
    }

    U64 o[4][8];
#pragma unroll
    for (int r = 0; r < 4; r++)
#pragma unroll
        for (int j = 0; j < 8; j++) o[r][j] = 0ull;

    float m[4], l[4];
    const float NEG_INF = __int_as_float(0xff800000);
#pragma unroll
    for (int r = 0; r < 4; r++) { m[r] = NEG_INF; l[r] = 0.f; }

    for (int kt = 0; kt < Nn / 64; kt++) {
        __syncthreads();   // prior PV (and initial Q store) done before overwriting tiles
        const float* Kt = Kg + (size_t)kt * 64 * ICc;
        const float* Vt = Vg + (size_t)kt * 64 * ICc;
#pragma unroll
        for (int it = 0; it < 16; it++) {
            int idx = it * 256 + t;
            int k = idx >> 6, dq = idx & 63;
            float4 kv = *reinterpret_cast<const float4*>(Kt + (size_t)k * ICc + dq * 4);
            Ks[(dq * 4 + 0) * KS_S + k] = kv.x;
            Ks[(dq * 4 + 1) * KS_S + k] = kv.y;
            Ks[(dq * 4 + 2) * KS_S + k] = kv.z;
            Ks[(dq * 4 + 3) * KS_S + k] = kv.w;
            float4 vv = *reinterpret_cast<const float4*>(Vt + (size_t)k * ICc + dq * 4);
            *reinterpret_cast<float4*>(&Vs[k * VS_S + dq * 4]) = vv;
        }
        __syncthreads();

        // ---- S = Q K^T (64x64) ----
        U64 s0[4], s1[4];
#pragma unroll
        for (int r = 0; r < 4; r++) { s0[r] = 0ull; s1[r] = 0ull; }
        const float* qb = Qs + ty * 4;
        const float* kb = Ks + 2 * tx;
#pragma unroll 4
        for (int d = 0; d < 256; d++) {
            float4 a = *reinterpret_cast<const float4*>(qb + d * QS_S);
            U64 k0 = *reinterpret_cast<const U64*>(kb + d * KS_S);
            U64 k1 = *reinterpret_cast<const U64*>(kb + d * KS_S + 32);
            U64 a0 = pk2(a.x, a.x), a1 = pk2(a.y, a.y);
            U64 a2 = pk2(a.z, a.z), a3 = pk2(a.w, a.w);
            fma2(s0[0], a0, k0); fma2(s1[0], a0, k1);
            fma2(s0[1], a1, k0); fma2(s1[1], a1, k1);
            fma2(s0[2], a2, k0); fma2(s1[2], a2, k1);
            fma2(s0[3], a3, k0); fma2(s1[3], a3, k1);
        }

        // ---- online softmax ----
#pragma unroll
        for (int r = 0; r < 4; r++) {
            float e0, e1, e2, e3;
            up2(s0[r], e0, e1); up2(s1[r], e2, e3);
            float mx = fmaxf(fmaxf(e0, e1), fmaxf(e2, e3));
            mx = fmaxf(mx, __shfl_xor_sync(0xffffffffu, mx, 1));
            mx = fmaxf(mx, __shfl_xor_sync(0xffffffffu, mx, 2));
            mx = fmaxf(mx, __shfl_xor_sync(0xffffffffu, mx, 4));
            mx = fmaxf(mx, __shfl_xor_sync(0xffffffffu, mx, 8));
            float nm = fmaxf(m[r], mx);
            float cf = __expf(m[r] - nm);
            m[r] = nm;
            float p0 = __expf(e0 - nm), p1 = __expf(e1 - nm);
            float p2 = __expf(e2 - nm), p3 = __expf(e3 - nm);
            float ps = (p0 + p1) + (p2 + p3);
            ps += __shfl_xor_sync(0xffffffffu, ps, 1);
            ps += __shfl_xor_sync(0xffffffffu, ps, 2);
            ps += __shfl_xor_sync(0xffffffffu, ps, 4);
            ps += __shfl_xor_sync(0xffffffffu, ps, 8);
            l[r] = l[r] * cf + ps;
            U64 cf2 = pk2(cf, cf);
#pragma unroll
            for (int j = 0; j < 8; j++) o[r][j] = mul2(o[r][j], cf2);
            float* pr = Ps + (ty * 4 + r) * PS_S + 2 * tx;
            pr[0] = p0; pr[1] = p1; pr[32] = p2; pr[33] = p3;
        }
        __syncthreads();

        // ---- O += P V ----
        const float* vb = Vs + 2 * tx;
        const float* pb = Ps + (ty * 4) * PS_S;
#pragma unroll 2
        for (int k = 0; k < 64; k++) {
            float q0 = pb[k], q1 = pb[PS_S + k], q2 = pb[2 * PS_S + k], q3 = pb[3 * PS_S + k];
            U64 w0 = pk2(q0, q0), w1 = pk2(q1, q1), w2 = pk2(q2, q2), w3 = pk2(q3, q3);
            const float* vk = vb + k * VS_S;
#pragma unroll
            for (int j = 0; j < 8; j++) {
                U64 v = *reinterpret_cast<const U64*>(vk + 32 * j);
                fma2(o[0][j], w0, v);
                fma2(o[1][j], w1, v);
                fma2(o[2][j], w2, v);
                fma2(o[3][j], w3, v);
            }
        }
    }

    // ---- epilogue: O / l -> g_Y ----
    float* Yb = g_Y + ((size_t)b * Nn + n0) * ICc;
#pragma unroll
    for (int r = 0; r < 4; r++) {
        float inv = 1.0f / l[r];
        U64 inv2 = pk2(inv, inv);
        float* row = Yb + (size_t)(ty * 4 + r) * ICc;
#pragma unroll
        for (int j = 0; j < 8; j++) {
            U64 val = mul2(o[r][j], inv2);
            float va, vb2; up2(val, va, vb2);
            *reinterpret_cast<float2*>(row + 2 * tx + 32 * j) = make_float2(va, vb2);
        }
    }
}

// =====================================================================
// K3: Wz projection + transposed store.
// Z[b][c][n] = sum_i Y[b][n][i] * wz_w[c][i] + wz_b[c]
// Tiles BM=64 (n), BN=64 (c), BK=16 (i); transposed write staged via smem.
// =====================================================================
__global__ __launch_bounds__(256) void wz_kernel(
    const float* __restrict__ wzw, const float* __restrict__ wzb)
{
    __shared__ float As[16][68];   // [i][n]
    __shared__ float Bs[16][68];   // [i][c]
    __shared__ float Cs[64][65];   // [c][n] staging

    const int t  = threadIdx.x;
    const int tx = t & 15, ty = t >> 4;
    const int n0 = blockIdx.x * 64;
    const int c0 = blockIdx.y * 64;
    const int b  = blockIdx.z;
    const float* Yb = g_Y + (size_t)b * Nn * ICc;

    U64 acc0[4], acc1[4];
#pragma unroll
    for (int r = 0; r < 4; r++) { acc0[r] = 0ull; acc1[r] = 0ull; }

    const int lr = t >> 2;   // 0..63
    const int lq = t & 3;

    for (int ik = 0; ik < ICc; ik += 16) {
        float4 a = *reinterpret_cast<const float4*>(Yb + (size_t)(n0 + lr) * ICc + ik + 4 * lq);
        As[4 * lq + 0][lr] = a.x; As[4 * lq + 1][lr] = a.y;
        As[4 * lq + 2][lr] = a.z; As[4 * lq + 3][lr] = a.w;
        float4 w = *reinterpret_cast<const float4*>(wzw + (size_t)(c0 + lr) * ICc + ik + 4 * lq);
        Bs[4 * lq + 0][lr] = w.x; Bs[4 * lq + 1][lr] = w.y;
        Bs[4 * lq + 2][lr] = w.z; Bs[4 * lq + 3][lr] = w.w;
        __syncthreads();

#pragma unroll
        for (int i = 0; i < 16; i++) {
            float4 a4 = *reinterpret_cast<const float4*>(&As[i][ty * 4]);
            U64 b0 = *reinterpret_cast<const U64*>(&Bs[i][2 * tx]);
            U64 b1 = *reinterpret_cast<const U64*>(&Bs[i][2 * tx + 32]);
            U64 a0 = pk2(a4.x, a4.x), a1 = pk2(a4.y, a4.y);
            U64 a2 = pk2(a4.z, a4.z), a3 = pk2(a4.w, a4.w);
            fma2(acc0[0], a0, b0); fma2(acc1[0], a0, b1);
            fma2(acc0[1], a1, b0); fma2(acc1[1], a1, b1);
            fma2(acc0[2], a2, b0); fma2(acc1[2], a2, b1);
            fma2(acc0[3], a3, b0); fma2(acc1[3], a3, b1);
        }
        __syncthreads();
    }

    const float wb0 = wzb[c0 + 2 * tx],      wb1 = wzb[c0 + 2 * tx + 1];
    const float wb2 = wzb[c0 + 2 * tx + 32], wb3 = wzb[c0 + 2 * tx + 33];
#pragma unroll
    for (int r = 0; r < 4; r++) {
        float s0v, s1v, s2v, s3v;
        up2(acc0[r], s0v, s1v); up2(acc1[r], s2v, s3v);
        int n = ty * 4 + r;
        Cs[2 * tx][n]      = s0v + wb0;
        Cs[2 * tx + 1][n]  = s1v + wb1;
        Cs[2 * tx + 32][n] = s2v + wb2;
        Cs[2 * tx + 33][n] = s3v + wb3;
    }
    __syncthreads();

    float* Zb = g_Z + (size_t)b * Cc * Nn;
#pragma unroll
    for (int r2 = 0; r2 < 16; r2++) {
        int idx = r2 * 256 + t;
        int cl = idx >> 6, nl = idx & 63;
        Zb[(size_t)(c0 + cl) * Nn + n0 + nl] = Cs[cl][nl];
    }
}

// =====================================================================
// K4: deterministic BN stats per channel -> fused scale/shift
// =====================================================================
__global__ __launch_bounds__(256) void bnstats_kernel(
    const float* __restrict__ bnw, const float* __restrict__ bnb)
{
    const int c = blockIdx.x;
    const int t = threadIdx.x;
    float s = 0.f, q = 0.f;
    for (int b = 0; b < Bb; b++) {
        const float4* row = reinterpret_cast<const float4*>(g_Z + ((size_t)b * Cc + c) * Nn);
        for (int n4 = t; n4 < Nn / 4; n4 += 256) {
            float4 v = row[n4];
            s += (v.x + v.y) + (v.z + v.w);
            q += (v.x * v.x + v.y * v.y) + (v.z * v.z + v.w * v.w);
        }
    }
    __shared__ float ss[256], qs[256];
    ss[t] = s; qs[t] = q;
    __syncthreads();
    for (int o = 128; o > 0; o >>= 1) {
        if (t < o) { ss[t] += ss[t + o]; qs[t] += qs[t + o]; }
        __syncthreads();
    }
    if (t == 0) {
        const float inv_n = 1.0f / (float)(Bb * Nn);
        float mean = ss[0] * inv_n;
        float var  = qs[0] * inv_n - mean * mean;
        float sc   = bnw[c] * rsqrtf(var + 1e-5f);
        g_scaleC[c] = sc;
        g_shiftC[c] = bnb[c] - mean * sc;
    }
}

// =====================================================================
// K5: out = Z*scale[c] + shift[c] + x   (float4 elementwise)
// =====================================================================
__global__ __launch_bounds__(256) void final_kernel(
    const float* __restrict__ x, float* __restrict__ out)
{
    int i = blockIdx.x * 256 + threadIdx.x;          // float4 index
    int c = (i / (Nn / 4)) & (Cc - 1);
    float sc = g_scaleC[c], sh = g_shiftC[c];
    float4 z  = reinterpret_cast<const float4*>(g_Z)[i];
    float4 xv = reinterpret_cast<const float4*>(x)[i];
    float4 o;
    o.x = fmaf(z.x, sc, sh) + xv.x;
    o.y = fmaf(z.y, sc, sh) + xv.y;
    o.z = fmaf(z.z, sc, sh) + xv.z;
    o.w = fmaf(z.w, sc, sh) + xv.w;
    reinterpret_cast<float4*>(out)[i] = o;
}

// =====================================================================
extern "C" void kernel_launch(void* const* d_in, const int* in_sizes, int n_in,
                              void* d_out, int out_size)
{
    (void)in_sizes; (void)n_in; (void)out_size;
    const float* x   = (const float*)d_in[0];
    const float* thw = (const float*)d_in[1];
    const float* thb = (const float*)d_in[2];
    const float* phw = (const float*)d_in[3];
    const float* phb = (const float*)d_in[4];
    const float* gw  = (const float*)d_in[5];
    const float* gbb = (const float*)d_in[6];
    const float* wzw = (const float*)d_in[7];
    const float* wzb = (const float*)d_in[8];
    const float* bnw = (const float*)d_in[9];
    const float* bnb = (const float*)d_in[10];
    float* out = (float*)d_out;

    cudaFuncSetAttribute(attn_kernel, cudaFuncAttributeMaxDynamicSharedMemorySize, ATTN_SMEM);

    dim3 gq(Nn / 64, ICc / 64, Bb);            // (49, 4, 8)
    qkv_kernel<<<gq, 256>>>(x, thw, thb, 0);
    qkv_kernel<<<gq, 256>>>(x, phw, phb, 1);
    qkv_kernel<<<gq, 256>>>(x, gw,  gbb, 2);

    attn_kernel<<<dim3(Nn / 64, Bb), 256, ATTN_SMEM>>>();

    wz_kernel<<<dim3(Nn / 64, Cc / 64, Bb), 256>>>(wzw, wzb);

    bnstats_kernel<<<Cc, 256>>>(bnw, bnb);

    final_kernel<<<(Bb * Cc * Nn / 4) / 256, 256>>>(x, out);
}

// round 3
// speedup vs baseline: 1.0579x; 1.0579x over previous
#include <cuda_runtime.h>
#include <math.h>

typedef unsigned long long U64;

constexpr int Bb  = 8;
constexpr int Cc  = 512;
constexpr int Nn  = 3136;   // 49 * 64
constexpr int ICc = 256;

// ---------------- scratch ----------------
__device__ __align__(256) float g_Qt[Bb * ICc * Nn];  // [b][ic][n]
__device__ __align__(256) float g_Kt[Bb * ICc * Nn];  // [b][ic][n]
__device__ __align__(256) float g_V [Bb * Nn * ICc];  // [b][n][ic]
__device__ __align__(256) float g_Y [Bb * Nn * ICc];  // [b][n][ic]
__device__ __align__(256) float g_Z [Bb * Cc * Nn];   // [b][c][n]
__device__ float g_scaleC[Cc];
__device__ float g_shiftC[Cc];

// ---------------- packed f32x2 helpers ----------------
__device__ __forceinline__ U64 pk2(float a, float b) {
    U64 r; asm("mov.b64 %0, {%1, %2};" : "=l"(r) : "f"(a), "f"(b)); return r;
}
__device__ __forceinline__ void up2(U64 v, float& a, float& b) {
    asm("mov.b64 {%0, %1}, %2;" : "=f"(a), "=f"(b) : "l"(v));
}
__device__ __forceinline__ void fma2(U64& d, U64 a, U64 b) {
    asm("fma.rn.f32x2 %0, %1, %2, %0;" : "+l"(d) : "l"(a), "l"(b));
}
__device__ __forceinline__ U64 mul2(U64 a, U64 b) {
    U64 r; asm("mul.rn.f32x2 %0, %1, %2;" : "=l"(r) : "l"(a), "l"(b)); return r;
}

// =====================================================================
// K1: fused QKV. Tile: 64 n x 128 i, BK=16 c. 256 threads.
// Thread (ty=t>>5 rows 8ty..8ty+7, tx=t&31 cols 4tx..4tx+3), 3 weights.
// 48 fma2 per c-step for 80B LDS = 1.67 B/fma2.
// Q,K written transposed [b][ic][n] via smem staging; V direct [b][n][ic].
// =====================================================================
constexpr int QKV_AS = 16 * 64;        // As[c][n]
constexpr int QKV_BS = 3 * 16 * 128;   // Bs[w][c][i]
constexpr int QKV_CS = 128 * 68;       // Cs[i][n] staging
constexpr int QKV_SMEM = (QKV_AS + QKV_BS + QKV_CS) * 4;

__global__ __launch_bounds__(256) void qkv_kernel(
    const float* __restrict__ x,
    const float* __restrict__ thw, const float* __restrict__ thb,
    const float* __restrict__ phw, const float* __restrict__ phb,
    const float* __restrict__ gw,  const float* __restrict__ gb)
{
    extern __shared__ float smq[];
    float* As = smq;                 // [16][64]
    float* Bs = As + QKV_AS;         // [3][16][128]
    float* Cs = Bs + QKV_BS;         // [128][68]

    const int t  = threadIdx.x;
    const int tx = t & 31, ty = t >> 5;
    const int n0 = blockIdx.x * 64;
    const int i0 = blockIdx.y * 128;
    const int b  = blockIdx.z;
    const float* xb = x + (size_t)b * Cc * Nn;
    const float* Wp[3] = { thw, phw, gw };

    U64 acc[3][8][2];
#pragma unroll
    for (int w = 0; w < 3; w++)
#pragma unroll
        for (int r = 0; r < 8; r++) { acc[w][r][0] = 0ull; acc[w][r][1] = 0ull; }

    const int lc  = t >> 4;   // A: c row 0..15
    const int lnq = t & 15;   // A: float4 col

    for (int ck = 0; ck < Cc; ck += 16) {
        *reinterpret_cast<float4*>(As + lc * 64 + 4 * lnq) =
            *reinterpret_cast<const float4*>(xb + (size_t)(ck + lc) * Nn + n0 + 4 * lnq);
#pragma unroll
        for (int w = 0; w < 3; w++) {
            const float* W = Wp[w];
#pragma unroll
            for (int it = 0; it < 2; it++) {
                int idx = it * 256 + t;
                int li = idx >> 2, lq = idx & 3;
                float4 wv = *reinterpret_cast<const float4*>(W + (size_t)(i0 + li) * Cc + ck + 4 * lq);
                float* brow = Bs + w * (16 * 128);
                brow[(4 * lq + 0) * 128 + li] = wv.x;
                brow[(4 * lq + 1) * 128 + li] = wv.y;
                brow[(4 * lq + 2) * 128 + li] = wv.z;
                brow[(4 * lq + 3) * 128 + li] = wv.w;
            }
        }
        __syncthreads();

#pragma unroll
        for (int c = 0; c < 16; c++) {
            float4 a0 = *reinterpret_cast<const float4*>(As + c * 64 + 8 * ty);
            float4 a1 = *reinterpret_cast<const float4*>(As + c * 64 + 8 * ty + 4);
            float av[8] = { a0.x, a0.y, a0.z, a0.w, a1.x, a1.y, a1.z, a1.w };
            ulonglong2 bb[3];
#pragma unroll
            for (int w = 0; w < 3; w++)
                bb[w] = *reinterpret_cast<const ulonglong2*>(Bs + (w * 16 + c) * 128 + 4 * tx);
#pragma unroll
            for (int r = 0; r < 8; r++) {
                U64 a = pk2(av[r], av[r]);
                fma2(acc[0][r][0], a, bb[0].x); fma2(acc[0][r][1], a, bb[0].y);
                fma2(acc[1][r][0], a, bb[1].x); fma2(acc[1][r][1], a, bb[1].y);
                fma2(acc[2][r][0], a, bb[2].x); fma2(acc[2][r][1], a, bb[2].y);
            }
        }
        __syncthreads();
    }

    // ---- V: direct store [b][n][ic] ----
    {
        float b0 = gb[i0 + 4 * tx], b1 = gb[i0 + 4 * tx + 1];
        float b2 = gb[i0 + 4 * tx + 2], b3 = gb[i0 + 4 * tx + 3];
#pragma unroll
        for (int r = 0; r < 8; r++) {
            float v0, v1, v2, v3;
            up2(acc[2][r][0], v0, v1); up2(acc[2][r][1], v2, v3);
            float4 o = make_float4(v0 + b0, v1 + b1, v2 + b2, v3 + b3);
            *reinterpret_cast<float4*>(g_V + ((size_t)b * Nn + n0 + 8 * ty + r) * ICc + i0 + 4 * tx) = o;
        }
    }

    // ---- Q then K: staged transpose -> [b][ic][n] ----
#pragma unroll
    for (int w = 0; w < 2; w++) {
        const float* bias = (w == 0) ? thb : phb;
        float bi[4];
#pragma unroll
        for (int jj = 0; jj < 4; jj++) bi[jj] = bias[i0 + 4 * tx + jj];
        __syncthreads();
#pragma unroll
        for (int r = 0; r < 8; r++) {
            float v0, v1, v2, v3;
            up2(acc[w][r][0], v0, v1); up2(acc[w][r][1], v2, v3);
            int n = 8 * ty + r;
            Cs[(4 * tx + 0) * 68 + n] = v0 + bi[0];
            Cs[(4 * tx + 1) * 68 + n] = v1 + bi[1];
            Cs[(4 * tx + 2) * 68 + n] = v2 + bi[2];
            Cs[(4 * tx + 3) * 68 + n] = v3 + bi[3];
        }
        __syncthreads();
        float* dst = (w == 0) ? g_Qt : g_Kt;
#pragma unroll
        for (int it = 0; it < 8; it++) {
            int idx = it * 256 + t;
            int irow = idx >> 4, c4 = idx & 15;
            *reinterpret_cast<float4*>(dst + ((size_t)b * ICc + i0 + irow) * Nn + n0 + 4 * c4) =
                *reinterpret_cast<const float4*>(Cs + irow * 68 + 4 * c4);
        }
    }
}

// =====================================================================
// K2: flash attention. Block = (64-q tile, b), 256 threads = 8 warps.
// S-tile 64q x 256k, thread = 8q x 8k (2 B/fma2). K streamed in 32-d
// chunks, V in 32-k chunks through 2 ping-pong 32KB buffers.
// smem: Qs[256][64] 64KB + Ps[64][256] 64KB + 2 x [32][256] 64KB = 192KB
// =====================================================================
constexpr int ATTN_SMEM = (256 * 64 + 64 * 256 + 2 * 32 * 256) * 4; // 196608

__device__ __forceinline__ void load_K_chunk(float* buf, const float* Kb,
                                             int n0k, int dbase, int t) {
#pragma unroll
    for (int it = 0; it < 8; it++) {
        int idx = it * 256 + t;
        int row = idx >> 6, c4 = idx & 63;
        int col = n0k + 4 * c4; col = min(col, Nn - 4);
        *reinterpret_cast<float4*>(buf + row * 256 + 4 * c4) =
            *reinterpret_cast<const float4*>(Kb + (size_t)(dbase + row) * Nn + col);
    }
}
__device__ __forceinline__ void load_V_chunk(float* buf, const float* Vb,
                                             int kbase, int t) {
#pragma unroll
    for (int it = 0; it < 8; it++) {
        int idx = it * 256 + t;
        int row = idx >> 6, c4 = idx & 63;
        int kr = min(kbase + row, Nn - 1);
        *reinterpret_cast<float4*>(buf + row * 256 + 4 * c4) =
            *reinterpret_cast<const float4*>(Vb + (size_t)kr * ICc + 4 * c4);
    }
}

__device__ __forceinline__ void qk_chunk(const float* Qp, const float* cur, int tc,
                                         U64 sA[8][2], U64 sB[8][2]) {
#pragma unroll 4
    for (int d = 0; d < 32; d++) {
        const float* qr = Qp + d * 64;
        float4 q0 = *reinterpret_cast<const float4*>(qr);
        float4 q1 = *reinterpret_cast<const float4*>(qr + 4);
        ulonglong2 ka = *reinterpret_cast<const ulonglong2*>(cur + d * 256 + 4 * tc);
        ulonglong2 kb = *reinterpret_cast<const ulonglong2*>(cur + d * 256 + 128 + 4 * tc);
        float qv[8] = { q0.x, q0.y, q0.z, q0.w, q1.x, q1.y, q1.z, q1.w };
#pragma unroll
        for (int r = 0; r < 8; r++) {
            U64 a = pk2(qv[r], qv[r]);
            fma2(sA[r][0], a, ka.x); fma2(sA[r][1], a, ka.y);
            fma2(sB[r][0], a, kb.x); fma2(sB[r][1], a, kb.y);
        }
    }
}

__device__ __forceinline__ void pv_chunk(const float* Pp, const float* cur, int tc,
                                         U64 oA[8][2], U64 oB[8][2]) {
#pragma unroll 4
    for (int k = 0; k < 32; k++) {
        ulonglong2 va = *reinterpret_cast<const ulonglong2*>(cur + k * 256 + 4 * tc);
        ulonglong2 vb = *reinterpret_cast<const ulonglong2*>(cur + k * 256 + 128 + 4 * tc);
#pragma unroll
        for (int r = 0; r < 8; r++) {
            float p = Pp[r * 256 + k];
            U64 w = pk2(p, p);
            fma2(oA[r][0], w, va.x); fma2(oA[r][1], w, va.y);
            fma2(oB[r][0], w, vb.x); fma2(oB[r][1], w, vb.y);
        }
    }
}

__global__ __launch_bounds__(256, 1) void attn_kernel()
{
    extern __shared__ float sm[];
    float* Qs  = sm;                  // [256][64]
    float* Ps  = Qs + 256 * 64;       // [64][256]
    float* Bf0 = Ps + 64 * 256;       // [32][256]
    float* Bf1 = Bf0 + 32 * 256;      // [32][256]

    const int t  = threadIdx.x;
    const int wr = t >> 5;            // warp = q-group (8 rows)
    const int tc = t & 31;            // k/d column group
    const int qt = blockIdx.x, b = blockIdx.y;
    const int n0 = qt * 64;

    const float* Qg = g_Qt + (size_t)b * ICc * Nn + n0;
    const float* Kb = g_Kt + (size_t)b * ICc * Nn;
    const float* Vb = g_V  + (size_t)b * Nn * ICc;

    // Q resident: Qs[d][q]
#pragma unroll
    for (int it = 0; it < 16; it++) {
        int idx = it * 256 + t;
        int d = idx >> 4, c4 = idx & 15;
        *reinterpret_cast<float4*>(Qs + d * 64 + 4 * c4) =
            *reinterpret_cast<const float4*>(Qg + (size_t)d * Nn + 4 * c4);
    }

    U64 oA[8][2], oB[8][2];
    float m[8], l[8];
#pragma unroll
    for (int r = 0; r < 8; r++) {
        oA[r][0] = oA[r][1] = 0ull; oB[r][0] = oB[r][1] = 0ull;
        m[r] = -1e30f; l[r] = 0.f;
    }

    load_K_chunk(Bf0, Kb, 0, 0, t);
    __syncthreads();

    const int NT = 13;  // ceil(3136/256)
    for (int kt = 0; kt < NT; kt++) {
        const int n0k = kt * 256;

        U64 sA[8][2], sB[8][2];
#pragma unroll
        for (int r = 0; r < 8; r++) { sA[r][0] = sA[r][1] = 0ull; sB[r][0] = sB[r][1] = 0ull; }

        // ---- QK over 8 d-chunks ----
        for (int c = 0; c < 8; c++) {
            float* cur = (c & 1) ? Bf1 : Bf0;
            float* nxt = (c & 1) ? Bf0 : Bf1;
            if (c < 7) load_K_chunk(nxt, Kb, n0k, (c + 1) * 32, t);
            else       load_V_chunk(nxt, Vb, n0k, t);
            qk_chunk(Qs + (c * 32) * 64 + 8 * wr, cur, tc, sA, sB);
            __syncthreads();
        }

        // ---- online softmax ----
        const bool lastT = (kt == NT - 1);
#pragma unroll
        for (int r = 0; r < 8; r++) {
            float e0, e1, e2, e3, e4, e5, e6, e7;
            up2(sA[r][0], e0, e1); up2(sA[r][1], e2, e3);
            up2(sB[r][0], e4, e5); up2(sB[r][1], e6, e7);
            if (lastT) {
                if (tc >= 16) { e0 = e1 = e2 = e3 = -1e30f; }
                e4 = e5 = e6 = e7 = -1e30f;
            }
            float mx = fmaxf(fmaxf(fmaxf(e0, e1), fmaxf(e2, e3)),
                             fmaxf(fmaxf(e4, e5), fmaxf(e6, e7)));
#pragma unroll
            for (int o = 1; o < 32; o <<= 1)
                mx = fmaxf(mx, __shfl_xor_sync(0xffffffffu, mx, o));
            float nm = fmaxf(m[r], mx);
            float cf = __expf(m[r] - nm);
            m[r] = nm;
            float p0 = __expf(e0 - nm), p1 = __expf(e1 - nm);
            float p2 = __expf(e2 - nm), p3 = __expf(e3 - nm);
            float p4 = __expf(e4 - nm), p5 = __expf(e5 - nm);
            float p6 = __expf(e6 - nm), p7 = __expf(e7 - nm);
            float ps = ((p0 + p1) + (p2 + p3)) + ((p4 + p5) + (p6 + p7));
#pragma unroll
            for (int o = 1; o < 32; o <<= 1)
                ps += __shfl_xor_sync(0xffffffffu, ps, o);
            l[r] = l[r] * cf + ps;
            U64 c2 = pk2(cf, cf);
            oA[r][0] = mul2(oA[r][0], c2); oA[r][1] = mul2(oA[r][1], c2);
            oB[r][0] = mul2(oB[r][0], c2); oB[r][1] = mul2(oB[r][1], c2);
            float* pr = Ps + (8 * wr + r) * 256;
            *reinterpret_cast<float4*>(pr + 4 * tc)       = make_float4(p0, p1, p2, p3);
            *reinterpret_cast<float4*>(pr + 128 + 4 * tc) = make_float4(p4, p5, p6, p7);
        }
        __syncthreads();

        // ---- PV over 8 k-chunks ----
        for (int c = 0; c < 8; c++) {
            float* cur = (c & 1) ? Bf1 : Bf0;
            float* nxt = (c & 1) ? Bf0 : Bf1;
            if (c < 7)           load_V_chunk(nxt, Vb, n0k + (c + 1) * 32, t);
            else if (kt < NT - 1) load_K_chunk(nxt, Kb, n0k + 256, 0, t);
            pv_chunk(Ps + (8 * wr) * 256 + c * 32, cur, tc, oA, oB);
            __syncthreads();
        }
    }

    // ---- epilogue: O / l -> g_Y [b][n][ic] ----
    float* Yp = g_Y + ((size_t)b * Nn + n0 + 8 * wr) * ICc + 4 * tc;
#pragma unroll
    for (int r = 0; r < 8; r++) {
        float inv = 1.0f / l[r];
        U64 i2 = pk2(inv, inv);
        U64 a0 = mul2(oA[r][0], i2), a1 = mul2(oA[r][1], i2);
        U64 b0 = mul2(oB[r][0], i2), b1 = mul2(oB[r][1], i2);
        float x0, x1, x2, x3;
        up2(a0, x0, x1); up2(a1, x2, x3);
        *reinterpret_cast<float4*>(Yp + (size_t)r * ICc)       = make_float4(x0, x1, x2, x3);
        up2(b0, x0, x1); up2(b1, x2, x3);
        *reinterpret_cast<float4*>(Yp + (size_t)r * ICc + 128) = make_float4(x0, x1, x2, x3);
    }
}

// =====================================================================
// K3: Wz projection + transposed store (unchanged from R1).
// =====================================================================
__global__ __launch_bounds__(256) void wz_kernel(
    const float* __restrict__ wzw, const float* __restrict__ wzb)
{
    __shared__ float As[16][68];
    __shared__ float Bs[16][68];
    __shared__ float Cs[64][65];

    const int t  = threadIdx.x;
    const int tx = t & 15, ty = t >> 4;
    const int n0 = blockIdx.x * 64;
    const int c0 = blockIdx.y * 64;
    const int b  = blockIdx.z;
    const float* Yb = g_Y + (size_t)b * Nn * ICc;

    U64 acc0[4], acc1[4];
#pragma unroll
    for (int r = 0; r < 4; r++) { acc0[r] = 0ull; acc1[r] = 0ull; }

    const int lr = t >> 2;
    const int lq = t & 3;

    for (int ik = 0; ik < ICc; ik += 16) {
        float4 a = *reinterpret_cast<const float4*>(Yb + (size_t)(n0 + lr) * ICc + ik + 4 * lq);
        As[4 * lq + 0][lr] = a.x; As[4 * lq + 1][lr] = a.y;
        As[4 * lq + 2][lr] = a.z; As[4 * lq + 3][lr] = a.w;
        float4 w = *reinterpret_cast<const float4*>(wzw + (size_t)(c0 + lr) * ICc + ik + 4 * lq);
        Bs[4 * lq + 0][lr] = w.x; Bs[4 * lq + 1][lr] = w.y;
        Bs[4 * lq + 2][lr] = w.z; Bs[4 * lq + 3][lr] = w.w;
        __syncthreads();

#pragma unroll
        for (int i = 0; i < 16; i++) {
            float4 a4 = *reinterpret_cast<const float4*>(&As[i][ty * 4]);
            U64 b0 = *reinterpret_cast<const U64*>(&Bs[i][2 * tx]);
            U64 b1 = *reinterpret_cast<const U64*>(&Bs[i][2 * tx + 32]);
            U64 a0 = pk2(a4.x, a4.x), a1 = pk2(a4.y, a4.y);
            U64 a2 = pk2(a4.z, a4.z), a3 = pk2(a4.w, a4.w);
            fma2(acc0[0], a0, b0); fma2(acc1[0], a0, b1);
            fma2(acc0[1], a1, b0); fma2(acc1[1], a1, b1);
            fma2(acc0[2], a2, b0); fma2(acc1[2], a2, b1);
            fma2(acc0[3], a3, b0); fma2(acc1[3], a3, b1);
        }
        __syncthreads();
    }

    const float wb0 = wzb[c0 + 2 * tx],      wb1 = wzb[c0 + 2 * tx + 1];
    const float wb2 = wzb[c0 + 2 * tx + 32], wb3 = wzb[c0 + 2 * tx + 33];
#pragma unroll
    for (int r = 0; r < 4; r++) {
        float s0v, s1v, s2v, s3v;
        up2(acc0[r], s0v, s1v); up2(acc1[r], s2v, s3v);
        int n = ty * 4 + r;
        Cs[2 * tx][n]      = s0v + wb0;
        Cs[2 * tx + 1][n]  = s1v + wb1;
        Cs[2 * tx + 32][n] = s2v + wb2;
        Cs[2 * tx + 33][n] = s3v + wb3;
    }
    __syncthreads();

    float* Zb = g_Z + (size_t)b * Cc * Nn;
#pragma unroll
    for (int r2 = 0; r2 < 16; r2++) {
        int idx = r2 * 256 + t;
        int cl = idx >> 6, nl = idx & 63;
        Zb[(size_t)(c0 + cl) * Nn + n0 + nl] = Cs[cl][nl];
    }
}

// =====================================================================
// K4: BN stats (unchanged)
// =====================================================================
__global__ __launch_bounds__(256) void bnstats_kernel(
    const float* __restrict__ bnw, const float* __restrict__ bnb)
{
    const int c = blockIdx.x;
    const int t = threadIdx.x;
    float s = 0.f, q = 0.f;
    for (int b = 0; b < Bb; b++) {
        const float4* row = reinterpret_cast<const float4*>(g_Z + ((size_t)b * Cc + c) * Nn);
        for (int n4 = t; n4 < Nn / 4; n4 += 256) {
            float4 v = row[n4];
            s += (v.x + v.y) + (v.z + v.w);
            q += (v.x * v.x + v.y * v.y) + (v.z * v.z + v.w * v.w);
        }
    }
    __shared__ float ss[256], qs[256];
    ss[t] = s; qs[t] = q;
    __syncthreads();
    for (int o = 128; o > 0; o >>= 1) {
        if (t < o) { ss[t] += ss[t + o]; qs[t] += qs[t + o]; }
        __syncthreads();
    }
    if (t == 0) {
        const float inv_n = 1.0f / (float)(Bb * Nn);
        float mean = ss[0] * inv_n;
        float var  = qs[0] * inv_n - mean * mean;
        float sc   = bnw[c] * rsqrtf(var + 1e-5f);
        g_scaleC[c] = sc;
        g_shiftC[c] = bnb[c] - mean * sc;
    }
}

// =====================================================================
// K5: final elementwise (unchanged)
// =====================================================================
__global__ __launch_bounds__(256) void final_kernel(
    const float* __restrict__ x, float* __restrict__ out)
{
    int i = blockIdx.x * 256 + threadIdx.x;
    int c = (i / (Nn / 4)) & (Cc - 1);
    float sc = g_scaleC[c], sh = g_shiftC[c];
    float4 z  = reinterpret_cast<const float4*>(g_Z)[i];
    float4 xv = reinterpret_cast<const float4*>(x)[i];
    float4 o;
    o.x = fmaf(z.x, sc, sh) + xv.x;
    o.y = fmaf(z.y, sc, sh) + xv.y;
    o.z = fmaf(z.z, sc, sh) + xv.z;
    o.w = fmaf(z.w, sc, sh) + xv.w;
    reinterpret_cast<float4*>(out)[i] = o;
}

// =====================================================================
extern "C" void kernel_launch(void* const* d_in, const int* in_sizes, int n_in,
                              void* d_out, int out_size)
{
    (void)in_sizes; (void)n_in; (void)out_size;
    const float* x   = (const float*)d_in[0];
    const float* thw = (const float*)d_in[1];
    const float* thb = (const float*)d_in[2];
    const float* phw = (const float*)d_in[3];
    const float* phb = (const float*)d_in[4];
    const float* gw  = (const float*)d_in[5];
    const float* gbb = (const float*)d_in[6];
    const float* wzw = (const float*)d_in[7];
    const float* wzb = (const float*)d_in[8];
    const float* bnw = (const float*)d_in[9];
    const float* bnb = (const float*)d_in[10];
    float* out = (float*)d_out;

    cudaFuncSetAttribute(qkv_kernel,  cudaFuncAttributeMaxDynamicSharedMemorySize, QKV_SMEM);
    cudaFuncSetAttribute(attn_kernel, cudaFuncAttributeMaxDynamicSharedMemorySize, ATTN_SMEM);

    qkv_kernel<<<dim3(Nn / 64, ICc / 128, Bb), 256, QKV_SMEM>>>(
        x, thw, thb, phw, phb, gw, gbb);

    attn_kernel<<<dim3(Nn / 64, Bb), 256, ATTN_SMEM>>>();

    wz_kernel<<<dim3(Nn / 64, Cc / 64, Bb), 256>>>(wzw, wzb);

    bnstats_kernel<<<Cc, 256>>>(bnw, bnb);

    final_kernel<<<(Bb * Cc * Nn / 4) / 256, 256>>>(x, out);
}

// round 6
// speedup vs baseline: 1.8238x; 1.7240x over previous
#include <cuda_runtime.h>
#include <cuda_bf16.h>
#include <math.h>
#include <cstdint>

typedef unsigned long long U64;

constexpr int Bb  = 8;
constexpr int Cc  = 512;
constexpr int Nn  = 3136;
constexpr int ICc = 256;
constexpr int Np  = 3200;   // 25*128

__device__ __align__(256) __nv_bfloat16 g_Qh[Bb*Np*ICc];
__device__ __align__(256) __nv_bfloat16 g_Ql[Bb*Np*ICc];
__device__ __align__(256) __nv_bfloat16 g_Kh[Bb*Np*ICc];
__device__ __align__(256) __nv_bfloat16 g_Kl[Bb*Np*ICc];
__device__ __align__(256) __nv_bfloat16 g_Vth[Bb*ICc*Np];   // [b][d][n]
__device__ __align__(256) __nv_bfloat16 g_Vtl[Bb*ICc*Np];
__device__ __align__(256) float         g_S [(size_t)Bb*Np*Np];
__device__ __align__(256) __nv_bfloat16 g_Ph[(size_t)Bb*Np*Np];
__device__ __align__(256) __nv_bfloat16 g_Pl[(size_t)Bb*Np*Np];
__device__ __align__(256) float g_Y[(size_t)Bb*Np*ICc];     // [b][n(pad)][ic]
__device__ __align__(256) float g_Z[Bb*Cc*Nn];              // [b][c][n]
__device__ float g_scaleC[Cc];
__device__ float g_shiftC[Cc];

// ---------------- f32x2 helpers (qkv / wz) ----------------
__device__ __forceinline__ U64 pk2(float a, float b) {
    U64 r; asm("mov.b64 %0, {%1, %2};" : "=l"(r) : "f"(a), "f"(b)); return r;
}
__device__ __forceinline__ void up2(U64 v, float& a, float& b) {
    asm("mov.b64 {%0, %1}, %2;" : "=f"(a), "=f"(b) : "l"(v));
}
__device__ __forceinline__ void fma2(U64& d, U64 a, U64 b) {
    asm("fma.rn.f32x2 %0, %1, %2, %0;" : "+l"(d) : "l"(a), "l"(b));
}

// ---------------- mma.sync helpers ----------------
__device__ __forceinline__ uint32_t smem_u32(const void* p) {
    uint32_t a;
    asm("{ .reg .u64 t; cvta.to.shared.u64 t, %1; cvt.u32.u64 %0, t; }" : "=r"(a) : "l"(p));
    return a;
}
__device__ __forceinline__ void ldsm_x4(uint32_t* r, uint32_t addr) {
    asm volatile("ldmatrix.sync.aligned.m8n8.x4.shared.b16 {%0,%1,%2,%3}, [%4];"
                 : "=r"(r[0]), "=r"(r[1]), "=r"(r[2]), "=r"(r[3]) : "r"(addr));
}
__device__ __forceinline__ void mma_bf16(float* d, const uint32_t* a, const uint32_t* b) {
    asm volatile("mma.sync.aligned.m16n8k16.row.col.f32.bf16.bf16.f32 "
                 "{%0,%1,%2,%3}, {%4,%5,%6,%7}, {%8,%9}, {%0,%1,%2,%3};"
                 : "+f"(d[0]), "+f"(d[1]), "+f"(d[2]), "+f"(d[3])
                 : "r"(a[0]), "r"(a[1]), "r"(a[2]), "r"(a[3]), "r"(b[0]), "r"(b[1]));
}

__device__ __forceinline__ void bsplit(float v, __nv_bfloat16& h, __nv_bfloat16& l) {
    h = __float2bfloat16(v);
    l = __float2bfloat16(v - __bfloat162float(h));
}
__device__ __forceinline__ uint2 pk4b(__nv_bfloat16 a, __nv_bfloat16 b, __nv_bfloat16 c, __nv_bfloat16 d) {
    __nv_bfloat162 p0 = __halves2bfloat162(a, b), p1 = __halves2bfloat162(c, d);
    uint2 r;
    r.x = *reinterpret_cast<unsigned int*>(&p0);
    r.y = *reinterpret_cast<unsigned int*>(&p1);
    return r;
}

constexpr int TSTR = 40;  // smem row stride (bf16) — conflict-free ldmatrix

// load 128x32 bf16 tile, gmem row-major (ldg) -> smem [128][TSTR]
__device__ __forceinline__ void ld32(__nv_bfloat16* dst, const __nv_bfloat16* src, int ldg, int t) {
#pragma unroll
    for (int i = 0; i < 2; i++) {
        int u = t + 256 * i;          // 0..511
        int row = u >> 2, cq = u & 3;
        *reinterpret_cast<float4*>(dst + row * TSTR + cq * 8) =
            *reinterpret_cast<const float4*>(src + (size_t)row * ldg + cq * 8);
    }
}

// one 32-k chunk: 3-pass split-bf16 mma on 128x128 tile (8 warps, warp=64x32)
__device__ __forceinline__ void gemm_chunk(
    const __nv_bfloat16* Ah, const __nv_bfloat16* Al,
    const __nv_bfloat16* Bh, const __nv_bfloat16* Bl,
    int wm, int wn, int lane, float acc[4][4][4])
{
    const int lr = lane & 15, lc = lane >> 4;
#pragma unroll
    for (int kk = 0; kk < 32; kk += 16) {
        uint32_t ah[4][4], al[4][4], bh[4][2], bl[4][2];
#pragma unroll
        for (int i = 0; i < 4; i++) {
            ldsm_x4(ah[i], smem_u32(Ah + (wm*64 + i*16 + lr) * TSTR + kk + lc*8));
            ldsm_x4(al[i], smem_u32(Al + (wm*64 + i*16 + lr) * TSTR + kk + lc*8));
        }
#pragma unroll
        for (int jp = 0; jp < 2; jp++) {
            uint32_t r[4];
            ldsm_x4(r, smem_u32(Bh + (wn*32 + jp*16 + lr) * TSTR + kk + lc*8));
            bh[2*jp][0] = r[0]; bh[2*jp][1] = r[2];
            bh[2*jp+1][0] = r[1]; bh[2*jp+1][1] = r[3];
            ldsm_x4(r, smem_u32(Bl + (wn*32 + jp*16 + lr) * TSTR + kk + lc*8));
            bl[2*jp][0] = r[0]; bl[2*jp][1] = r[2];
            bl[2*jp+1][0] = r[1]; bl[2*jp+1][1] = r[3];
        }
#pragma unroll
        for (int i = 0; i < 4; i++)
#pragma unroll
            for (int j = 0; j < 4; j++) {
                mma_bf16(acc[i][j], ah[i], bh[j]);
                mma_bf16(acc[i][j], ah[i], bl[j]);
                mma_bf16(acc[i][j], al[i], bh[j]);
            }
    }
}

// =====================================================================
// K1: fused QKV -> bf16 splits. Q,K [b][n][d]; V^T [b][d][n].
// =====================================================================
constexpr int QKV_AS = 16*64, QKV_BS = 3*16*128, QKV_CS = 128*68;
constexpr int QKV_SMEM = (QKV_AS + QKV_BS + QKV_CS) * 4;

__global__ __launch_bounds__(256) void qkv_kernel(
    const float* __restrict__ x,
    const float* __restrict__ thw, const float* __restrict__ thb,
    const float* __restrict__ phw, const float* __restrict__ phb,
    const float* __restrict__ gw,  const float* __restrict__ gb)
{
    extern __shared__ float smq[];
    float* As = smq;
    float* Bs = As + QKV_AS;
    float* Cs = Bs + QKV_BS;

    const int t = threadIdx.x, tx = t & 31, ty = t >> 5;
    const int n0 = blockIdx.x * 64, i0 = blockIdx.y * 128, b = blockIdx.z;
    const float* xb = x + (size_t)b * Cc * Nn;
    const float* Wp[3] = { thw, phw, gw };

    U64 acc[3][8][2];
#pragma unroll
    for (int w = 0; w < 3; w++)
#pragma unroll
        for (int r = 0; r < 8; r++) { acc[w][r][0] = 0ull; acc[w][r][1] = 0ull; }

    const int lc = t >> 4, lnq = t & 15;
    for (int ck = 0; ck < Cc; ck += 16) {
        *reinterpret_cast<float4*>(As + lc * 64 + 4 * lnq) =
            *reinterpret_cast<const float4*>(xb + (size_t)(ck + lc) * Nn + n0 + 4 * lnq);
#pragma unroll
        for (int w = 0; w < 3; w++) {
#pragma unroll
            for (int it = 0; it < 2; it++) {
                int idx = it * 256 + t, li = idx >> 2, lq = idx & 3;
                float4 wv = *reinterpret_cast<const float4*>(Wp[w] + (size_t)(i0 + li) * Cc + ck + 4 * lq);
                float* br = Bs + w * 2048;
                br[(4*lq+0)*128+li] = wv.x; br[(4*lq+1)*128+li] = wv.y;
                br[(4*lq+2)*128+li] = wv.z; br[(4*lq+3)*128+li] = wv.w;
            }
        }
        __syncthreads();
#pragma unroll
        for (int c = 0; c < 16; c++) {
            float4 a0 = *reinterpret_cast<const float4*>(As + c*64 + 8*ty);
            float4 a1 = *reinterpret_cast<const float4*>(As + c*64 + 8*ty + 4);
            float av[8] = { a0.x,a0.y,a0.z,a0.w, a1.x,a1.y,a1.z,a1.w };
            ulonglong2 bb[3];
#pragma unroll
            for (int w = 0; w < 3; w++)
                bb[w] = *reinterpret_cast<const ulonglong2*>(Bs + (w*16+c)*128 + 4*tx);
#pragma unroll
            for (int r = 0; r < 8; r++) {
                U64 a = pk2(av[r], av[r]);
                fma2(acc[0][r][0], a, bb[0].x); fma2(acc[0][r][1], a, bb[0].y);
                fma2(acc[1][r][0], a, bb[1].x); fma2(acc[1][r][1], a, bb[1].y);
                fma2(acc[2][r][0], a, bb[2].x); fma2(acc[2][r][1], a, bb[2].y);
            }
        }
        __syncthreads();
    }

    // Q (w=0), K (w=1): split bf16 [b][n][d]
#pragma unroll
    for (int w = 0; w < 2; w++) {
        const float* bias = w ? phb : thb;
        float bi0 = bias[i0+4*tx], bi1 = bias[i0+4*tx+1], bi2 = bias[i0+4*tx+2], bi3 = bias[i0+4*tx+3];
        __nv_bfloat16* dh = w ? g_Kh : g_Qh;
        __nv_bfloat16* dl = w ? g_Kl : g_Ql;
#pragma unroll
        for (int r = 0; r < 8; r++) {
            float v0,v1,v2,v3;
            up2(acc[w][r][0], v0, v1); up2(acc[w][r][1], v2, v3);
            v0 += bi0; v1 += bi1; v2 += bi2; v3 += bi3;
            __nv_bfloat16 h0,h1,h2,h3,l0,l1,l2,l3;
            bsplit(v0,h0,l0); bsplit(v1,h1,l1); bsplit(v2,h2,l2); bsplit(v3,h3,l3);
            size_t off = ((size_t)b*Np + n0 + 8*ty + r) * ICc + i0 + 4*tx;
            *reinterpret_cast<uint2*>(dh + off) = pk4b(h0,h1,h2,h3);
            *reinterpret_cast<uint2*>(dl + off) = pk4b(l0,l1,l2,l3);
        }
    }
    // V: stage transpose -> split [b][d][n]
    {
        float b0 = gb[i0+4*tx], b1 = gb[i0+4*tx+1], b2 = gb[i0+4*tx+2], b3 = gb[i0+4*tx+3];
        __syncthreads();
#pragma unroll
        for (int r = 0; r < 8; r++) {
            float v0,v1,v2,v3;
            up2(acc[2][r][0], v0, v1); up2(acc[2][r][1], v2, v3);
            int n = 8*ty + r;
            Cs[(4*tx+0)*68+n] = v0+b0; Cs[(4*tx+1)*68+n] = v1+b1;
            Cs[(4*tx+2)*68+n] = v2+b2; Cs[(4*tx+3)*68+n] = v3+b3;
        }
        __syncthreads();
#pragma unroll
        for (int it = 0; it < 8; it++) {
            int idx = it*256 + t, ir = idx >> 4, c4 = idx & 15;
            float4 v = *reinterpret_cast<const float4*>(Cs + ir*68 + 4*c4);
            __nv_bfloat16 h0,h1,h2,h3,l0,l1,l2,l3;
            bsplit(v.x,h0,l0); bsplit(v.y,h1,l1); bsplit(v.z,h2,l2); bsplit(v.w,h3,l3);
            size_t off = ((size_t)b*ICc + i0 + ir) * Np + n0 + 4*c4;
            *reinterpret_cast<uint2*>(g_Vth + off) = pk4b(h0,h1,h2,h3);
            *reinterpret_cast<uint2*>(g_Vtl + off) = pk4b(l0,l1,l2,l3);
        }
    }
}

// =====================================================================
// K2: S = Q K^T via mma.sync (3-pass split-bf16). CTA=(qt,nt,b), 128x128.
// =====================================================================
__global__ __launch_bounds__(256) void sgemm_kernel()
{
    __shared__ __nv_bfloat16 Ah[128*TSTR], Al[128*TSTR], Bh[128*TSTR], Bl[128*TSTR];
    const int t = threadIdx.x, lane = t & 31, wid = t >> 5;
    const int wm = wid & 1, wn = wid >> 1;
    const int q0 = blockIdx.x * 128, n0 = blockIdx.y * 128, b = blockIdx.z;
    const __nv_bfloat16* Qh = g_Qh + ((size_t)b*Np + q0) * ICc;
    const __nv_bfloat16* Ql = g_Ql + ((size_t)b*Np + q0) * ICc;
    const __nv_bfloat16* Kh = g_Kh + ((size_t)b*Np + n0) * ICc;
    const __nv_bfloat16* Kl = g_Kl + ((size_t)b*Np + n0) * ICc;

    float acc[4][4][4] = {};
    for (int ck = 0; ck < ICc; ck += 32) {
        __syncthreads();
        ld32(Ah, Qh + ck, ICc, t); ld32(Al, Ql + ck, ICc, t);
        ld32(Bh, Kh + ck, ICc, t); ld32(Bl, Kl + ck, ICc, t);
        __syncthreads();
        gemm_chunk(Ah, Al, Bh, Bl, wm, wn, lane, acc);
    }

    float* So = g_S + ((size_t)b*Np + q0) * Np + n0;
    const int r0 = wm*64 + (lane >> 2), cb = wn*32 + 2*(lane & 3);
#pragma unroll
    for (int i = 0; i < 4; i++)
#pragma unroll
        for (int j = 0; j < 4; j++) {
            *reinterpret_cast<float2*>(So + (size_t)(r0 + i*16) * Np + cb + j*8) =
                make_float2(acc[i][j][0], acc[i][j][1]);
            *reinterpret_cast<float2*>(So + (size_t)(r0 + i*16 + 8) * Np + cb + j*8) =
                make_float2(acc[i][j][2], acc[i][j][3]);
        }
}

// =====================================================================
// K3: row softmax -> P hi/lo (1/sum folded)
// =====================================================================
__global__ __launch_bounds__(128) void softmax_kernel()
{
    const int r = blockIdx.x, b = blockIdx.y, t = threadIdx.x;
    const float* Sr = g_S + ((size_t)b*Np + r) * Np;
    float v[25], mx = -1e30f;
#pragma unroll
    for (int i = 0; i < 25; i++) {
        int c = t + 128*i;
        v[i] = Sr[c];
        if (c < Nn) mx = fmaxf(mx, v[i]);
    }
    __shared__ float rd[4], rd2[4];
    float m = mx;
#pragma unroll
    for (int o = 16; o; o >>= 1) m = fmaxf(m, __shfl_xor_sync(0xffffffffu, m, o));
    if ((t & 31) == 0) rd[t >> 5] = m;
    __syncthreads();
    m = fmaxf(fmaxf(rd[0], rd[1]), fmaxf(rd[2], rd[3]));
    float s = 0.f;
#pragma unroll
    for (int i = 0; i < 25; i++) {
        int c = t + 128*i;
        float p = (c < Nn) ? __expf(v[i] - m) : 0.f;
        v[i] = p; s += p;
    }
#pragma unroll
    for (int o = 16; o; o >>= 1) s += __shfl_xor_sync(0xffffffffu, s, o);
    if ((t & 31) == 0) rd2[t >> 5] = s;
    __syncthreads();
    s = (rd2[0] + rd2[1]) + (rd2[2] + rd2[3]);
    float inv = 1.0f / s;
    __nv_bfloat16* Ph = g_Ph + ((size_t)b*Np + r) * Np;
    __nv_bfloat16* Pl = g_Pl + ((size_t)b*Np + r) * Np;
#pragma unroll
    for (int i = 0; i < 25; i++) {
        int c = t + 128*i;
        __nv_bfloat16 h, l;
        bsplit(v[i] * inv, h, l);
        Ph[c] = h; Pl[c] = l;
    }
}

// =====================================================================
// K4: Y = P V via mma.sync. CTA=(qt, d-half, b), 128x128, K=3200.
// =====================================================================
__global__ __launch_bounds__(256) void pv_kernel()
{
    __shared__ __nv_bfloat16 Ah[128*TSTR], Al[128*TSTR], Bh[128*TSTR], Bl[128*TSTR];
    const int t = threadIdx.x, lane = t & 31, wid = t >> 5;
    const int wm = wid & 1, wn = wid >> 1;
    const int q0 = blockIdx.x * 128, d0 = blockIdx.y * 128, b = blockIdx.z;
    const __nv_bfloat16* Ph = g_Ph + ((size_t)b*Np + q0) * Np;
    const __nv_bfloat16* Pl = g_Pl + ((size_t)b*Np + q0) * Np;
    const __nv_bfloat16* Vh = g_Vth + ((size_t)b*ICc + d0) * Np;
    const __nv_bfloat16* Vl = g_Vtl + ((size_t)b*ICc + d0) * Np;

    float acc[4][4][4] = {};
    for (int ck = 0; ck < Np; ck += 32) {
        __syncthreads();
        ld32(Ah, Ph + ck, Np, t); ld32(Al, Pl + ck, Np, t);
        ld32(Bh, Vh + ck, Np, t); ld32(Bl, Vl + ck, Np, t);
        __syncthreads();
        gemm_chunk(Ah, Al, Bh, Bl, wm, wn, lane, acc);
    }

    float* Yo = g_Y + ((size_t)b*Np + q0) * ICc + d0;
    const int r0 = wm*64 + (lane >> 2), cb = wn*32 + 2*(lane & 3);
#pragma unroll
    for (int i = 0; i < 4; i++)
#pragma unroll
        for (int j = 0; j < 4; j++) {
            *reinterpret_cast<float2*>(Yo + (size_t)(r0 + i*16) * ICc + cb + j*8) =
                make_float2(acc[i][j][0], acc[i][j][1]);
            *reinterpret_cast<float2*>(Yo + (size_t)(r0 + i*16 + 8) * ICc + cb + j*8) =
                make_float2(acc[i][j][2], acc[i][j][3]);
        }
}

// =====================================================================
// K5: Wz projection + transposed store (Y now has Np row stride)
// =====================================================================
__global__ __launch_bounds__(256) void wz_kernel(
    const float* __restrict__ wzw, const float* __restrict__ wzb)
{
    __shared__ float As[16][68], Bs[16][68], Cs[64][65];
    const int t = threadIdx.x, tx = t & 15, ty = t >> 4;
    const int n0 = blockIdx.x * 64, c0 = blockIdx.y * 64, b = blockIdx.z;
    const float* Yb = g_Y + (size_t)b * Np * ICc;

    U64 acc0[4], acc1[4];
#pragma unroll
    for (int r = 0; r < 4; r++) { acc0[r] = 0ull; acc1[r] = 0ull; }
    const int lr = t >> 2, lq = t & 3;

    for (int ik = 0; ik < ICc; ik += 16) {
        float4 a = *reinterpret_cast<const float4*>(Yb + (size_t)(n0+lr)*ICc + ik + 4*lq);
        As[4*lq+0][lr] = a.x; As[4*lq+1][lr] = a.y; As[4*lq+2][lr] = a.z; As[4*lq+3][lr] = a.w;
        float4 w = *reinterpret_cast<const float4*>(wzw + (size_t)(c0+lr)*ICc + ik + 4*lq);
        Bs[4*lq+0][lr] = w.x; Bs[4*lq+1][lr] = w.y; Bs[4*lq+2][lr] = w.z; Bs[4*lq+3][lr] = w.w;
        __syncthreads();
#pragma unroll
        for (int i = 0; i < 16; i++) {
            float4 a4 = *reinterpret_cast<const float4*>(&As[i][ty*4]);
            U64 b0 = *reinterpret_cast<const U64*>(&Bs[i][2*tx]);
            U64 b1 = *reinterpret_cast<const U64*>(&Bs[i][2*tx+32]);
            U64 a0 = pk2(a4.x,a4.x), a1 = pk2(a4.y,a4.y), a2 = pk2(a4.z,a4.z), a3 = pk2(a4.w,a4.w);
            fma2(acc0[0],a0,b0); fma2(acc1[0],a0,b1);
            fma2(acc0[1],a1,b0); fma2(acc1[1],a1,b1);
            fma2(acc0[2],a2,b0); fma2(acc1[2],a2,b1);
            fma2(acc0[3],a3,b0); fma2(acc1[3],a3,b1);
        }
        __syncthreads();
    }
    const float wb0 = wzb[c0+2*tx], wb1 = wzb[c0+2*tx+1], wb2 = wzb[c0+2*tx+32], wb3 = wzb[c0+2*tx+33];
#pragma unroll
    for (int r = 0; r < 4; r++) {
        float s0,s1,s2,s3;
        up2(acc0[r],s0,s1); up2(acc1[r],s2,s3);
        int n = ty*4 + r;
        Cs[2*tx][n] = s0+wb0; Cs[2*tx+1][n] = s1+wb1;
        Cs[2*tx+32][n] = s2+wb2; Cs[2*tx+33][n] = s3+wb3;
    }
    __syncthreads();
    float* Zb = g_Z + (size_t)b * Cc * Nn;
#pragma unroll
    for (int r2 = 0; r2 < 16; r2++) {
        int idx = r2*256 + t, cl = idx >> 6, nl = idx & 63;
        Zb[(size_t)(c0+cl)*Nn + n0 + nl] = Cs[cl][nl];
    }
}

// =====================================================================
// K6: BN stats ; K7: final elementwise
// =====================================================================
__global__ __launch_bounds__(256) void bnstats_kernel(
    const float* __restrict__ bnw, const float* __restrict__ bnb)
{
    const int c = blockIdx.x, t = threadIdx.x;
    float s = 0.f, q = 0.f;
    for (int b = 0; b < Bb; b++) {
        const float4* row = reinterpret_cast<const float4*>(g_Z + ((size_t)b*Cc + c) * Nn);
        for (int n4 = t; n4 < Nn/4; n4 += 256) {
            float4 v = row[n4];
            s += (v.x+v.y)+(v.z+v.w);
            q += (v.x*v.x+v.y*v.y)+(v.z*v.z+v.w*v.w);
        }
    }
    __shared__ float ss[256], qs[256];
    ss[t] = s; qs[t] = q;
    __syncthreads();
    for (int o = 128; o > 0; o >>= 1) {
        if (t < o) { ss[t] += ss[t+o]; qs[t] += qs[t+o]; }
        __syncthreads();
    }
    if (t == 0) {
        const float inv_n = 1.0f / (float)(Bb * Nn);
        float mean = ss[0]*inv_n, var = qs[0]*inv_n - mean*mean;
        float sc = bnw[c] * rsqrtf(var + 1e-5f);
        g_scaleC[c] = sc;
        g_shiftC[c] = bnb[c] - mean*sc;
    }
}

__global__ __launch_bounds__(256) void final_kernel(
    const float* __restrict__ x, float* __restrict__ out)
{
    int i = blockIdx.x * 256 + threadIdx.x;
    int c = (i / (Nn/4)) & (Cc-1);
    float sc = g_scaleC[c], sh = g_shiftC[c];
    float4 z = reinterpret_cast<const float4*>(g_Z)[i];
    float4 xv = reinterpret_cast<const float4*>(x)[i];
    float4 o;
    o.x = fmaf(z.x, sc, sh) + xv.x; o.y = fmaf(z.y, sc, sh) + xv.y;
    o.z = fmaf(z.z, sc, sh) + xv.z; o.w = fmaf(z.w, sc, sh) + xv.w;
    reinterpret_cast<float4*>(out)[i] = o;
}

// =====================================================================
extern "C" void kernel_launch(void* const* d_in, const int* in_sizes, int n_in,
                              void* d_out, int out_size)
{
    (void)in_sizes; (void)n_in; (void)out_size;
    const float* x   = (const float*)d_in[0];
    const float* thw = (const float*)d_in[1];
    const float* thb = (const float*)d_in[2];
    const float* phw = (const float*)d_in[3];
    const float* phb = (const float*)d_in[4];
    const float* gw  = (const float*)d_in[5];
    const float* gbb = (const float*)d_in[6];
    const float* wzw = (const float*)d_in[7];
    const float* wzb = (const float*)d_in[8];
    const float* bnw = (const float*)d_in[9];
    const float* bnb = (const float*)d_in[10];
    float* out = (float*)d_out;

    cudaFuncSetAttribute(qkv_kernel, cudaFuncAttributeMaxDynamicSharedMemorySize, QKV_SMEM);

    qkv_kernel<<<dim3(Nn/64, ICc/128, Bb), 256, QKV_SMEM>>>(x, thw, thb, phw, phb, gw, gbb);
    sgemm_kernel<<<dim3(Np/128, Np/128, Bb), 256>>>();
    softmax_kernel<<<dim3(Nn, Bb), 128>>>();
    pv_kernel<<<dim3(Np/128, ICc/128, Bb), 256>>>();
    wz_kernel<<<dim3(Nn/64, Cc/64, Bb), 256>>>(wzw, wzb);
    bnstats_kernel<<<Cc, 256>>>(bnw, bnb);
    final_kernel<<<(Bb*Cc*Nn/4)/256, 256>>>(x, out);
}

// round 7
// speedup vs baseline: 1.9993x; 1.0962x over previous
#include <cuda_runtime.h>
#include <cuda_bf16.h>
#include <math.h>
#include <cstdint>

typedef unsigned long long U64;

constexpr int Bb  = 8;
constexpr int Cc  = 512;
constexpr int Nn  = 3136;
constexpr int ICc = 256;
constexpr int Np  = 3200;   // 25*128

__device__ __align__(256) __nv_bfloat16 g_Qh[Bb*Np*ICc];
__device__ __align__(256) __nv_bfloat16 g_Ql[Bb*Np*ICc];
__device__ __align__(256) __nv_bfloat16 g_Kh[Bb*Np*ICc];
__device__ __align__(256) __nv_bfloat16 g_Kl[Bb*Np*ICc];
__device__ __align__(256) __nv_bfloat16 g_Vth[Bb*ICc*Np];   // [b][d][n]
__device__ __align__(256) __nv_bfloat16 g_Vtl[Bb*ICc*Np];
__device__ __align__(256) float         g_S [(size_t)Bb*Np*Np];
__device__ __align__(256) __nv_bfloat16 g_Ph[(size_t)Bb*Np*Np];
__device__ __align__(256) __nv_bfloat16 g_Pl[(size_t)Bb*Np*Np];
__device__ __align__(256) float g_Y[(size_t)Bb*Np*ICc];     // [b][n(pad)][ic]
__device__ __align__(256) float g_Z[Bb*Cc*Nn];              // [b][c][n]
__device__ float g_scaleC[Cc];
__device__ float g_shiftC[Cc];

// ---------------- f32x2 helpers (qkv / wz) ----------------
__device__ __forceinline__ U64 pk2(float a, float b) {
    U64 r; asm("mov.b64 %0, {%1, %2};" : "=l"(r) : "f"(a), "f"(b)); return r;
}
__device__ __forceinline__ void up2(U64 v, float& a, float& b) {
    asm("mov.b64 {%0, %1}, %2;" : "=f"(a), "=f"(b) : "l"(v));
}
__device__ __forceinline__ void fma2(U64& d, U64 a, U64 b) {
    asm("fma.rn.f32x2 %0, %1, %2, %0;" : "+l"(d) : "l"(a), "l"(b));
}

// ---------------- mma.sync helpers ----------------
__device__ __forceinline__ uint32_t smem_u32(const void* p) {
    uint32_t a;
    asm("{ .reg .u64 t; cvta.to.shared.u64 t, %1; cvt.u32.u64 %0, t; }" : "=r"(a) : "l"(p));
    return a;
}
__device__ __forceinline__ void ldsm_x4(uint32_t* r, uint32_t addr) {
    asm volatile("ldmatrix.sync.aligned.m8n8.x4.shared.b16 {%0,%1,%2,%3}, [%4];"
                 : "=r"(r[0]), "=r"(r[1]), "=r"(r[2]), "=r"(r[3]) : "r"(addr));
}
__device__ __forceinline__ void mma_bf16(float* d, const uint32_t* a, const uint32_t* b) {
    asm volatile("mma.sync.aligned.m16n8k16.row.col.f32.bf16.bf16.f32 "
                 "{%0,%1,%2,%3}, {%4,%5,%6,%7}, {%8,%9}, {%0,%1,%2,%3};"
                 : "+f"(d[0]), "+f"(d[1]), "+f"(d[2]), "+f"(d[3])
                 : "r"(a[0]), "r"(a[1]), "r"(a[2]), "r"(a[3]), "r"(b[0]), "r"(b[1]));
}
#define CP16(sm, gp)  asm volatile("cp.async.ca.shared.global [%0], [%1], 16;" :: "r"(sm), "l"(gp) : "memory")
#define CP_COMMIT()   asm volatile("cp.async.commit_group;" ::: "memory")
#define CP_WAIT1()    asm volatile("cp.async.wait_group 1;" ::: "memory")
#define CP_WAIT0()    asm volatile("cp.async.wait_group 0;" ::: "memory")

__device__ __forceinline__ void bsplit(float v, __nv_bfloat16& h, __nv_bfloat16& l) {
    h = __float2bfloat16(v);
    l = __float2bfloat16(v - __bfloat162float(h));
}
__device__ __forceinline__ uint2 pk4b(__nv_bfloat16 a, __nv_bfloat16 b, __nv_bfloat16 c, __nv_bfloat16 d) {
    __nv_bfloat162 p0 = __halves2bfloat162(a, b), p1 = __halves2bfloat162(c, d);
    uint2 r;
    r.x = *reinterpret_cast<unsigned int*>(&p0);
    r.y = *reinterpret_cast<unsigned int*>(&p1);
    return r;
}

constexpr int TSTR = 40;                 // smem row stride (bf16)
constexpr int BUF_E = 128 * TSTR;        // 5120 bf16 per buffer
constexpr int STAGE_E = 4 * BUF_E;       // 20480 bf16 per stage
constexpr int GEMM_SMEM = 2 * STAGE_E * 2;  // 81920 bytes

// async load of 128x32 bf16 tile (row-major ldg) -> smem [128][TSTR]
__device__ __forceinline__ void ld32a(uint32_t dsm, const __nv_bfloat16* src, int ldg, int t) {
#pragma unroll
    for (int i = 0; i < 2; i++) {
        int u = t + 256 * i, row = u >> 2, cq = u & 3;
        CP16(dsm + row * (TSTR * 2) + cq * 16, src + (size_t)row * ldg + cq * 8);
    }
}

// one 32-k chunk: 3-pass split-bf16 mma on 128x128 tile (8 warps, warp=64x32)
__device__ __forceinline__ void gemm_chunk(
    const __nv_bfloat16* Ah, const __nv_bfloat16* Al,
    const __nv_bfloat16* Bh, const __nv_bfloat16* Bl,
    int wm, int wn, int lane, float acc[4][4][4])
{
    const int lr = lane & 15, lc = lane >> 4;
#pragma unroll
    for (int kk = 0; kk < 32; kk += 16) {
        uint32_t ah[4][4], al[4][4], bh[4][2], bl[4][2];
#pragma unroll
        for (int i = 0; i < 4; i++) {
            ldsm_x4(ah[i], smem_u32(Ah + (wm*64 + i*16 + lr) * TSTR + kk + lc*8));
            ldsm_x4(al[i], smem_u32(Al + (wm*64 + i*16 + lr) * TSTR + kk + lc*8));
        }
#pragma unroll
        for (int jp = 0; jp < 2; jp++) {
            uint32_t r[4];
            ldsm_x4(r, smem_u32(Bh + (wn*32 + jp*16 + lr) * TSTR + kk + lc*8));
            bh[2*jp][0] = r[0]; bh[2*jp][1] = r[2];
            bh[2*jp+1][0] = r[1]; bh[2*jp+1][1] = r[3];
            ldsm_x4(r, smem_u32(Bl + (wn*32 + jp*16 + lr) * TSTR + kk + lc*8));
            bl[2*jp][0] = r[0]; bl[2*jp][1] = r[2];
            bl[2*jp+1][0] = r[1]; bl[2*jp+1][1] = r[3];
        }
#pragma unroll
        for (int i = 0; i < 4; i++)
#pragma unroll
            for (int j = 0; j < 4; j++) {
                mma_bf16(acc[i][j], ah[i], bh[j]);
                mma_bf16(acc[i][j], ah[i], bl[j]);
                mma_bf16(acc[i][j], al[i], bh[j]);
            }
    }
}

// =====================================================================
// K1: fused QKV -> bf16 splits. Q,K [b][n][d]; V^T [b][d][n].
// =====================================================================
constexpr int QKV_AS = 16*64, QKV_BS = 3*16*128, QKV_CS = 128*68;
constexpr int QKV_SMEM = (QKV_AS + QKV_BS + QKV_CS) * 4;

__global__ __launch_bounds__(256) void qkv_kernel(
    const float* __restrict__ x,
    const float* __restrict__ thw, const float* __restrict__ thb,
    const float* __restrict__ phw, const float* __restrict__ phb,
    const float* __restrict__ gw,  const float* __restrict__ gb)
{
    extern __shared__ float smq[];
    float* As = smq;
    float* Bs = As + QKV_AS;
    float* Cs = Bs + QKV_BS;

    const int t = threadIdx.x, tx = t & 31, ty = t >> 5;
    const int n0 = blockIdx.x * 64, i0 = blockIdx.y * 128, b = blockIdx.z;
    const float* xb = x + (size_t)b * Cc * Nn;
    const float* Wp[3] = { thw, phw, gw };

    U64 acc[3][8][2];
#pragma unroll
    for (int w = 0; w < 3; w++)
#pragma unroll
        for (int r = 0; r < 8; r++) { acc[w][r][0] = 0ull; acc[w][r][1] = 0ull; }

    const int lc = t >> 4, lnq = t & 15;
    for (int ck = 0; ck < Cc; ck += 16) {
        *reinterpret_cast<float4*>(As + lc * 64 + 4 * lnq) =
            *reinterpret_cast<const float4*>(xb + (size_t)(ck + lc) * Nn + n0 + 4 * lnq);
#pragma unroll
        for (int w = 0; w < 3; w++) {
#pragma unroll
            for (int it = 0; it < 2; it++) {
                int idx = it * 256 + t, li = idx >> 2, lq = idx & 3;
                float4 wv = *reinterpret_cast<const float4*>(Wp[w] + (size_t)(i0 + li) * Cc + ck + 4 * lq);
                float* br = Bs + w * 2048;
                br[(4*lq+0)*128+li] = wv.x; br[(4*lq+1)*128+li] = wv.y;
                br[(4*lq+2)*128+li] = wv.z; br[(4*lq+3)*128+li] = wv.w;
            }
        }
        __syncthreads();
#pragma unroll
        for (int c = 0; c < 16; c++) {
            float4 a0 = *reinterpret_cast<const float4*>(As + c*64 + 8*ty);
            float4 a1 = *reinterpret_cast<const float4*>(As + c*64 + 8*ty + 4);
            float av[8] = { a0.x,a0.y,a0.z,a0.w, a1.x,a1.y,a1.z,a1.w };
            ulonglong2 bb[3];
#pragma unroll
            for (int w = 0; w < 3; w++)
                bb[w] = *reinterpret_cast<const ulonglong2*>(Bs + (w*16+c)*128 + 4*tx);
#pragma unroll
            for (int r = 0; r < 8; r++) {
                U64 a = pk2(av[r], av[r]);
                fma2(acc[0][r][0], a, bb[0].x); fma2(acc[0][r][1], a, bb[0].y);
                fma2(acc[1][r][0], a, bb[1].x); fma2(acc[1][r][1], a, bb[1].y);
                fma2(acc[2][r][0], a, bb[2].x); fma2(acc[2][r][1], a, bb[2].y);
            }
        }
        __syncthreads();
    }

#pragma unroll
    for (int w = 0; w < 2; w++) {
        const float* bias = w ? phb : thb;
        float bi0 = bias[i0+4*tx], bi1 = bias[i0+4*tx+1], bi2 = bias[i0+4*tx+2], bi3 = bias[i0+4*tx+3];
        __nv_bfloat16* dh = w ? g_Kh : g_Qh;
        __nv_bfloat16* dl = w ? g_Kl : g_Ql;
#pragma unroll
        for (int r = 0; r < 8; r++) {
            float v0,v1,v2,v3;
            up2(acc[w][r][0], v0, v1); up2(acc[w][r][1], v2, v3);
            v0 += bi0; v1 += bi1; v2 += bi2; v3 += bi3;
            __nv_bfloat16 h0,h1,h2,h3,l0,l1,l2,l3;
            bsplit(v0,h0,l0); bsplit(v1,h1,l1); bsplit(v2,h2,l2); bsplit(v3,h3,l3);
            size_t off = ((size_t)b*Np + n0 + 8*ty + r) * ICc + i0 + 4*tx;
            *reinterpret_cast<uint2*>(dh + off) = pk4b(h0,h1,h2,h3);
            *reinterpret_cast<uint2*>(dl + off) = pk4b(l0,l1,l2,l3);
        }
    }
    {
        float b0 = gb[i0+4*tx], b1 = gb[i0+4*tx+1], b2 = gb[i0+4*tx+2], b3 = gb[i0+4*tx+3];
        __syncthreads();
#pragma unroll
        for (int r = 0; r < 8; r++) {
            float v0,v1,v2,v3;
            up2(acc[2][r][0], v0, v1); up2(acc[2][r][1], v2, v3);
            int n = 8*ty + r;
            Cs[(4*tx+0)*68+n] = v0+b0; Cs[(4*tx+1)*68+n] = v1+b1;
            Cs[(4*tx+2)*68+n] = v2+b2; Cs[(4*tx+3)*68+n] = v3+b3;
        }
        __syncthreads();
#pragma unroll
        for (int it = 0; it < 8; it++) {
            int idx = it*256 + t, ir = idx >> 4, c4 = idx & 15;
            float4 v = *reinterpret_cast<const float4*>(Cs + ir*68 + 4*c4);
            __nv_bfloat16 h0,h1,h2,h3,l0,l1,l2,l3;
            bsplit(v.x,h0,l0); bsplit(v.y,h1,l1); bsplit(v.z,h2,l2); bsplit(v.w,h3,l3);
            size_t off = ((size_t)b*ICc + i0 + ir) * Np + n0 + 4*c4;
            *reinterpret_cast<uint2*>(g_Vth + off) = pk4b(h0,h1,h2,h3);
            *reinterpret_cast<uint2*>(g_Vtl + off) = pk4b(l0,l1,l2,l3);
        }
    }
}

// =====================================================================
// K2: S = Q K^T, cp.async double-buffered, 2 CTAs/SM.
// =====================================================================
__global__ __launch_bounds__(256, 2) void sgemm_kernel()
{
    extern __shared__ __nv_bfloat16 dsm[];
    const uint32_t sb = smem_u32(dsm);
    const int t = threadIdx.x, lane = t & 31, wid = t >> 5;
    const int wm = wid & 1, wn = wid >> 1;
    const int q0 = blockIdx.x * 128, n0 = blockIdx.y * 128, b = blockIdx.z;
    const __nv_bfloat16* Qh = g_Qh + ((size_t)b*Np + q0) * ICc;
    const __nv_bfloat16* Ql = g_Ql + ((size_t)b*Np + q0) * ICc;
    const __nv_bfloat16* Kh = g_Kh + ((size_t)b*Np + n0) * ICc;
    const __nv_bfloat16* Kl = g_Kl + ((size_t)b*Np + n0) * ICc;

    float acc[4][4][4] = {};
    constexpr int NC = ICc / 32;  // 8

    // prologue
    {
        uint32_t d0 = sb;
        ld32a(d0,                Qh, ICc, t);
        ld32a(d0 + 2*BUF_E,      Ql, ICc, t);
        ld32a(d0 + 2*2*BUF_E,    Kh, ICc, t);
        ld32a(d0 + 2*3*BUF_E,    Kl, ICc, t);
        CP_COMMIT();
    }
    for (int c = 0; c < NC; c++) {
        if (c + 1 < NC) {
            uint32_t ds = sb + ((c+1) & 1) * (2*STAGE_E);
            ld32a(ds,             Qh + (c+1)*32, ICc, t);
            ld32a(ds + 2*BUF_E,   Ql + (c+1)*32, ICc, t);
            ld32a(ds + 2*2*BUF_E, Kh + (c+1)*32, ICc, t);
            ld32a(ds + 2*3*BUF_E, Kl + (c+1)*32, ICc, t);
            CP_COMMIT();
            CP_WAIT1();
        } else {
            CP_WAIT0();
        }
        __syncthreads();
        const __nv_bfloat16* st = dsm + (c & 1) * STAGE_E;
        gemm_chunk(st, st + BUF_E, st + 2*BUF_E, st + 3*BUF_E, wm, wn, lane, acc);
        __syncthreads();
    }

    float* So = g_S + ((size_t)b*Np + q0) * Np + n0;
    const int r0 = wm*64 + (lane >> 2), cb = wn*32 + 2*(lane & 3);
#pragma unroll
    for (int i = 0; i < 4; i++)
#pragma unroll
        for (int j = 0; j < 4; j++) {
            *reinterpret_cast<float2*>(So + (size_t)(r0 + i*16) * Np + cb + j*8) =
                make_float2(acc[i][j][0], acc[i][j][1]);
            *reinterpret_cast<float2*>(So + (size_t)(r0 + i*16 + 8) * Np + cb + j*8) =
                make_float2(acc[i][j][2], acc[i][j][3]);
        }
}

// =====================================================================
// K3: row softmax (float4) -> P hi/lo (1/sum folded). Pad cols -> 0.
// =====================================================================
__global__ __launch_bounds__(256) void softmax_kernel()
{
    const int r = blockIdx.x, b = blockIdx.y, t = threadIdx.x;
    const float4* Sr = reinterpret_cast<const float4*>(g_S + ((size_t)b*Np + r) * Np);
    float4 v[4];
    float mx = -1e30f;
#pragma unroll
    for (int i = 0; i < 4; i++) {
        int idx = t + 256*i;
        if (idx < 784) {
            v[i] = Sr[idx];
            mx = fmaxf(mx, fmaxf(fmaxf(v[i].x, v[i].y), fmaxf(v[i].z, v[i].w)));
        }
    }
    __shared__ float rd[8], rd2[8];
    float m = mx;
#pragma unroll
    for (int o = 16; o; o >>= 1) m = fmaxf(m, __shfl_xor_sync(0xffffffffu, m, o));
    if ((t & 31) == 0) rd[t >> 5] = m;
    __syncthreads();
    m = rd[0];
#pragma unroll
    for (int w = 1; w < 8; w++) m = fmaxf(m, rd[w]);
    float s = 0.f;
#pragma unroll
    for (int i = 0; i < 4; i++) {
        int idx = t + 256*i;
        if (idx < 784) {
            v[i].x = __expf(v[i].x - m); v[i].y = __expf(v[i].y - m);
            v[i].z = __expf(v[i].z - m); v[i].w = __expf(v[i].w - m);
            s += (v[i].x + v[i].y) + (v[i].z + v[i].w);
        }
    }
#pragma unroll
    for (int o = 16; o; o >>= 1) s += __shfl_xor_sync(0xffffffffu, s, o);
    if ((t & 31) == 0) rd2[t >> 5] = s;
    __syncthreads();
    s = rd2[0];
#pragma unroll
    for (int w = 1; w < 8; w++) s += rd2[w];
    float inv = 1.0f / s;
    __nv_bfloat16* Ph = g_Ph + ((size_t)b*Np + r) * Np;
    __nv_bfloat16* Pl = g_Pl + ((size_t)b*Np + r) * Np;
#pragma unroll
    for (int i = 0; i < 4; i++) {
        int idx = t + 256*i;
        if (idx < 784) {
            __nv_bfloat16 h0,h1,h2,h3,l0,l1,l2,l3;
            bsplit(v[i].x*inv,h0,l0); bsplit(v[i].y*inv,h1,l1);
            bsplit(v[i].z*inv,h2,l2); bsplit(v[i].w*inv,h3,l3);
            *reinterpret_cast<uint2*>(Ph + 4*idx) = pk4b(h0,h1,h2,h3);
            *reinterpret_cast<uint2*>(Pl + 4*idx) = pk4b(l0,l1,l2,l3);
        } else if (idx < 800) {
            uint2 z = make_uint2(0u, 0u);
            *reinterpret_cast<uint2*>(Ph + 4*idx) = z;
            *reinterpret_cast<uint2*>(Pl + 4*idx) = z;
        }
    }
}

// =====================================================================
// K4: Y = P V, cp.async double-buffered, 2 CTAs/SM. K=3200.
// =====================================================================
__global__ __launch_bounds__(256, 2) void pv_kernel()
{
    extern __shared__ __nv_bfloat16 dsm[];
    const uint32_t sb = smem_u32(dsm);
    const int t = threadIdx.x, lane = t & 31, wid = t >> 5;
    const int wm = wid & 1, wn = wid >> 1;
    const int q0 = blockIdx.x * 128, d0 = blockIdx.y * 128, b = blockIdx.z;
    const __nv_bfloat16* Ph = g_Ph + ((size_t)b*Np + q0) * Np;
    const __nv_bfloat16* Pl = g_Pl + ((size_t)b*Np + q0) * Np;
    const __nv_bfloat16* Vh = g_Vth + ((size_t)b*ICc + d0) * Np;
    const __nv_bfloat16* Vl = g_Vtl + ((size_t)b*ICc + d0) * Np;

    float acc[4][4][4] = {};
    constexpr int NC = Np / 32;  // 100

    {
        uint32_t d0s = sb;
        ld32a(d0s,             Ph, Np, t);
        ld32a(d0s + 2*BUF_E,   Pl, Np, t);
        ld32a(d0s + 2*2*BUF_E, Vh, Np, t);
        ld32a(d0s + 2*3*BUF_E, Vl, Np, t);
        CP_COMMIT();
    }
    for (int c = 0; c < NC; c++) {
        if (c + 1 < NC) {
            uint32_t ds = sb + ((c+1) & 1) * (2*STAGE_E);
            ld32a(ds,             Ph + (c+1)*32, Np, t);
            ld32a(ds + 2*BUF_E,   Pl + (c+1)*32, Np, t);
            ld32a(ds + 2*2*BUF_E, Vh + (c+1)*32, Np, t);
            ld32a(ds + 2*3*BUF_E, Vl + (c+1)*32, Np, t);
            CP_COMMIT();
            CP_WAIT1();
        } else {
            CP_WAIT0();
        }
        __syncthreads();
        const __nv_bfloat16* st = dsm + (c & 1) * STAGE_E;
        gemm_chunk(st, st + BUF_E, st + 2*BUF_E, st + 3*BUF_E, wm, wn, lane, acc);
        __syncthreads();
    }

    float* Yo = g_Y + ((size_t)b*Np + q0) * ICc + d0;
    const int r0 = wm*64 + (lane >> 2), cb = wn*32 + 2*(lane & 3);
#pragma unroll
    for (int i = 0; i < 4; i++)
#pragma unroll
        for (int j = 0; j < 4; j++) {
            *reinterpret_cast<float2*>(Yo + (size_t)(r0 + i*16) * ICc + cb + j*8) =
                make_float2(acc[i][j][0], acc[i][j][1]);
            *reinterpret_cast<float2*>(Yo + (size_t)(r0 + i*16 + 8) * ICc + cb + j*8) =
                make_float2(acc[i][j][2], acc[i][j][3]);
        }
}

// =====================================================================
// K5: Wz projection + transposed store (Y has Np row stride)
// =====================================================================
__global__ __launch_bounds__(256) void wz_kernel(
    const float* __restrict__ wzw, const float* __restrict__ wzb)
{
    __shared__ float As[16][68], Bs[16][68], Cs[64][65];
    const int t = threadIdx.x, tx = t & 15, ty = t >> 4;
    const int n0 = blockIdx.x * 64, c0 = blockIdx.y * 64, b = blockIdx.z;
    const float* Yb = g_Y + (size_t)b * Np * ICc;

    U64 acc0[4], acc1[4];
#pragma unroll
    for (int r = 0; r < 4; r++) { acc0[r] = 0ull; acc1[r] = 0ull; }
    const int lr = t >> 2, lq = t & 3;

    for (int ik = 0; ik < ICc; ik += 16) {
        float4 a = *reinterpret_cast<const float4*>(Yb + (size_t)(n0+lr)*ICc + ik + 4*lq);
        As[4*lq+0][lr] = a.x; As[4*lq+1][lr] = a.y; As[4*lq+2][lr] = a.z; As[4*lq+3][lr] = a.w;
        float4 w = *reinterpret_cast<const float4*>(wzw + (size_t)(c0+lr)*ICc + ik + 4*lq);
        Bs[4*lq+0][lr] = w.x; Bs[4*lq+1][lr] = w.y; Bs[4*lq+2][lr] = w.z; Bs[4*lq+3][lr] = w.w;
        __syncthreads();
#pragma unroll
        for (int i = 0; i < 16; i++) {
            float4 a4 = *reinterpret_cast<const float4*>(&As[i][ty*4]);
            U64 b0 = *reinterpret_cast<const U64*>(&Bs[i][2*tx]);
            U64 b1 = *reinterpret_cast<const U64*>(&Bs[i][2*tx+32]);
            U64 a0 = pk2(a4.x,a4.x), a1 = pk2(a4.y,a4.y), a2 = pk2(a4.z,a4.z), a3 = pk2(a4.w,a4.w);
            fma2(acc0[0],a0,b0); fma2(acc1[0],a0,b1);
            fma2(acc0[1],a1,b0); fma2(acc1[1],a1,b1);
            fma2(acc0[2],a2,b0); fma2(acc1[2],a2,b1);
            fma2(acc0[3],a3,b0); fma2(acc1[3],a3,b1);
        }
        __syncthreads();
    }
    const float wb0 = wzb[c0+2*tx], wb1 = wzb[c0+2*tx+1], wb2 = wzb[c0+2*tx+32], wb3 = wzb[c0+2*tx+33];
#pragma unroll
    for (int r = 0; r < 4; r++) {
        float s0,s1,s2,s3;
        up2(acc0[r],s0,s1); up2(acc1[r],s2,s3);
        int n = ty*4 + r;
        Cs[2*tx][n] = s0+wb0; Cs[2*tx+1][n] = s1+wb1;
        Cs[2*tx+32][n] = s2+wb2; Cs[2*tx+33][n] = s3+wb3;
    }
    __syncthreads();
    float* Zb = g_Z + (size_t)b * Cc * Nn;
#pragma unroll
    for (int r2 = 0; r2 < 16; r2++) {
        int idx = r2*256 + t, cl = idx >> 6, nl = idx & 63;
        Zb[(size_t)(c0+cl)*Nn + n0 + nl] = Cs[cl][nl];
    }
}

// =====================================================================
// K6: BN stats ; K7: final elementwise
// =====================================================================
__global__ __launch_bounds__(256) void bnstats_kernel(
    const float* __restrict__ bnw, const float* __restrict__ bnb)
{
    const int c = blockIdx.x, t = threadIdx.x;
    float s = 0.f, q = 0.f;
    for (int b = 0; b < Bb; b++) {
        const float4* row = reinterpret_cast<const float4*>(g_Z + ((size_t)b*Cc + c) * Nn);
        for (int n4 = t; n4 < Nn/4; n4 += 256) {
            float4 v = row[n4];
            s += (v.x+v.y)+(v.z+v.w);
            q += (v.x*v.x+v.y*v.y)+(v.z*v.z+v.w*v.w);
        }
    }
    __shared__ float ss[256], qs[256];
    ss[t] = s; qs[t] = q;
    __syncthreads();
    for (int o = 128; o > 0; o >>= 1) {
        if (t < o) { ss[t] += ss[t+o]; qs[t] += qs[t+o]; }
        __syncthreads();
    }
    if (t == 0) {
        const float inv_n = 1.0f / (float)(Bb * Nn);
        float mean = ss[0]*inv_n, var = qs[0]*inv_n - mean*mean;
        float sc = bnw[c] * rsqrtf(var + 1e-5f);
        g_scaleC[c] = sc;
        g_shiftC[c] = bnb[c] - mean*sc;
    }
}

__global__ __launch_bounds__(256) void final_kernel(
    const float* __restrict__ x, float* __restrict__ out)
{
    int i = blockIdx.x * 256 + threadIdx.x;
    int c = (i / (Nn/4)) & (Cc-1);
    float sc = g_scaleC[c], sh = g_shiftC[c];
    float4 z = reinterpret_cast<const float4*>(g_Z)[i];
    float4 xv = reinterpret_cast<const float4*>(x)[i];
    float4 o;
    o.x = fmaf(z.x, sc, sh) + xv.x; o.y = fmaf(z.y, sc, sh) + xv.y;
    o.z = fmaf(z.z, sc, sh) + xv.z; o.w = fmaf(z.w, sc, sh) + xv.w;
    reinterpret_cast<float4*>(out)[i] = o;
}

// =====================================================================
extern "C" void kernel_launch(void* const* d_in, const int* in_sizes, int n_in,
                              void* d_out, int out_size)
{
    (void)in_sizes; (void)n_in; (void)out_size;
    const float* x   = (const float*)d_in[0];
    const float* thw = (const float*)d_in[1];
    const float* thb = (const float*)d_in[2];
    const float* phw = (const float*)d_in[3];
    const float* phb = (const float*)d_in[4];
    const float* gw  = (const float*)d_in[5];
    const float* gbb = (const float*)d_in[6];
    const float* wzw = (const float*)d_in[7];
    const float* wzb = (const float*)d_in[8];
    const float* bnw = (const float*)d_in[9];
    const float* bnb = (const float*)d_in[10];
    float* out = (float*)d_out;

    cudaFuncSetAttribute(qkv_kernel,   cudaFuncAttributeMaxDynamicSharedMemorySize, QKV_SMEM);
    cudaFuncSetAttribute(sgemm_kernel, cudaFuncAttributeMaxDynamicSharedMemorySize, GEMM_SMEM);
    cudaFuncSetAttribute(pv_kernel,    cudaFuncAttributeMaxDynamicSharedMemorySize, GEMM_SMEM);

    qkv_kernel<<<dim3(Nn/64, ICc/128, Bb), 256, QKV_SMEM>>>(x, thw, thb, phw, phb, gw, gbb);
    sgemm_kernel<<<dim3(Np/128, Np/128, Bb), 256, GEMM_SMEM>>>();
    softmax_kernel<<<dim3(Nn, Bb), 256>>>();
    pv_kernel<<<dim3(Np/128, ICc/128, Bb), 256, GEMM_SMEM>>>();
    wz_kernel<<<dim3(Nn/64, Cc/64, Bb), 256>>>(wzw, wzb);
    bnstats_kernel<<<Cc, 256>>>(bnw, bnb);
    final_kernel<<<(Bb*Cc*Nn/4)/256, 256>>>(x, out);
}

// round 8
// speedup vs baseline: 2.7196x; 1.3603x over previous
#include <cuda_runtime.h>
#include <cuda_bf16.h>
#include <math.h>
#include <cstdint>

constexpr int Bb  = 8;
constexpr int Cc  = 512;
constexpr int Nn  = 3136;
constexpr int ICc = 256;
constexpr int Np  = 3200;   // 25*128

// ---------------- scratch ----------------
__device__ __align__(256) __nv_bfloat16 g_xh[Bb*Cc*Np];
__device__ __align__(256) __nv_bfloat16 g_xl[Bb*Cc*Np];
__device__ __align__(256) __nv_bfloat16 g_wh[3*ICc*Cc];
__device__ __align__(256) __nv_bfloat16 g_wl[3*ICc*Cc];
__device__ __align__(256) __nv_bfloat16 g_wzh[Cc*ICc];
__device__ __align__(256) __nv_bfloat16 g_wzl[Cc*ICc];
__device__ __align__(256) __nv_bfloat16 g_Qh[Bb*Np*ICc];
__device__ __align__(256) __nv_bfloat16 g_Ql[Bb*Np*ICc];
__device__ __align__(256) __nv_bfloat16 g_Kh[Bb*Np*ICc];
__device__ __align__(256) __nv_bfloat16 g_Kl[Bb*Np*ICc];
__device__ __align__(256) __nv_bfloat16 g_Vth[Bb*ICc*Np];   // [b][d][n]
__device__ __align__(256) __nv_bfloat16 g_Vtl[Bb*ICc*Np];
__device__ __align__(256) float         g_S [(size_t)Bb*Np*Np];
__device__ __align__(256) __nv_bfloat16 g_Ph[(size_t)Bb*Np*Np];
__device__ __align__(256) __nv_bfloat16 g_Pl[(size_t)Bb*Np*Np];
__device__ __align__(256) __nv_bfloat16 g_Yh[Bb*Np*ICc];    // [b][n][ic]
__device__ __align__(256) __nv_bfloat16 g_Yl[Bb*Np*ICc];
__device__ __align__(256) float g_Z[Bb*Cc*Nn];              // [b][c][n]
__device__ float g_scaleC[Cc];
__device__ float g_shiftC[Cc];

// ---------------- helpers ----------------
__device__ __forceinline__ uint32_t smem_u32(const void* p) {
    uint32_t a;
    asm("{ .reg .u64 t; cvta.to.shared.u64 t, %1; cvt.u32.u64 %0, t; }" : "=r"(a) : "l"(p));
    return a;
}
__device__ __forceinline__ void ldsm_x4(uint32_t* r, uint32_t addr) {
    asm volatile("ldmatrix.sync.aligned.m8n8.x4.shared.b16 {%0,%1,%2,%3}, [%4];"
                 : "=r"(r[0]), "=r"(r[1]), "=r"(r[2]), "=r"(r[3]) : "r"(addr));
}
__device__ __forceinline__ void ldsm_x4_t(uint32_t* r, uint32_t addr) {
    asm volatile("ldmatrix.sync.aligned.m8n8.x4.trans.shared.b16 {%0,%1,%2,%3}, [%4];"
                 : "=r"(r[0]), "=r"(r[1]), "=r"(r[2]), "=r"(r[3]) : "r"(addr));
}
__device__ __forceinline__ void mma_bf16(float* d, const uint32_t* a, const uint32_t* b) {
    asm volatile("mma.sync.aligned.m16n8k16.row.col.f32.bf16.bf16.f32 "
                 "{%0,%1,%2,%3}, {%4,%5,%6,%7}, {%8,%9}, {%0,%1,%2,%3};"
                 : "+f"(d[0]), "+f"(d[1]), "+f"(d[2]), "+f"(d[3])
                 : "r"(a[0]), "r"(a[1]), "r"(a[2]), "r"(a[3]), "r"(b[0]), "r"(b[1]));
}
#define CP16(sm, gp)  asm volatile("cp.async.ca.shared.global [%0], [%1], 16;" :: "r"(sm), "l"(gp) : "memory")
#define CP_COMMIT()   asm volatile("cp.async.commit_group;" ::: "memory")
#define CP_WAIT1()    asm volatile("cp.async.wait_group 1;" ::: "memory")
#define CP_WAIT0()    asm volatile("cp.async.wait_group 0;" ::: "memory")

__device__ __forceinline__ void bsplit(float v, __nv_bfloat16& h, __nv_bfloat16& l) {
    h = __float2bfloat16(v);
    l = __float2bfloat16(v - __bfloat162float(h));
}
__device__ __forceinline__ uint32_t pkb2(__nv_bfloat16 a, __nv_bfloat16 b) {
    __nv_bfloat162 p = __halves2bfloat162(a, b);
    return *reinterpret_cast<unsigned int*>(&p);
}
__device__ __forceinline__ uint2 pk4b(__nv_bfloat16 a, __nv_bfloat16 b, __nv_bfloat16 c, __nv_bfloat16 d) {
    return make_uint2(pkb2(a, b), pkb2(c, d));
}

constexpr int TSTR = 40;                    // [rows][k32] tiles
constexpr int BUF_E = 128 * TSTR;
constexpr int STAGE_E = 4 * BUF_E;
constexpr int GEMM_SMEM = 2 * STAGE_E * 2;  // 81920 B

constexpr int XSTR = 136;                   // x-tile [k32][n128] col stride (272B ≡ 16 mod 128: conflict-free trans-ldsm)
constexpr int XBUF = 32 * XSTR;             // 4352 bf16
constexpr int WBUF = 128 * TSTR;            // 5120 bf16
constexpr int QSTAGE = 2 * XBUF + 2 * WBUF; // 18944 bf16
constexpr int QKV_SMEM = 2 * QSTAGE * 2;    // 75776 B (also >= 128*129*4 for V stage)

// async: [128 rows][32 cols] bf16 row-major -> smem [128][TSTR]
__device__ __forceinline__ void ld32a(uint32_t dsm, const __nv_bfloat16* src, int ldg, int t) {
#pragma unroll
    for (int i = 0; i < 2; i++) {
        int u = t + 256 * i, row = u >> 2, cq = u & 3;
        CP16(dsm + row * (TSTR * 2) + cq * 16, src + (size_t)row * ldg + cq * 8);
    }
}
// async: x chunk [32 c-rows][128 n-cols] -> smem [32][XSTR]
__device__ __forceinline__ void ldxa(uint32_t dsm, const __nv_bfloat16* src, int t) {
#pragma unroll
    for (int i = 0; i < 2; i++) {
        int u = t + 256 * i, row = u >> 4, cq = u & 15;
        CP16(dsm + row * (XSTR * 2) + cq * 16, src + (size_t)row * Np + cq * 8);
    }
}

// 32-k chunk, A row-major [128][k], B row-major [128 n][k], 3-pass split
__device__ __forceinline__ void gemm_chunk(
    const __nv_bfloat16* Ah, const __nv_bfloat16* Al,
    const __nv_bfloat16* Bh, const __nv_bfloat16* Bl,
    int wm, int wn, int lane, float acc[4][4][4])
{
    const int lr = lane & 15, lc = lane >> 4;
#pragma unroll
    for (int kk = 0; kk < 32; kk += 16) {
        uint32_t ah[4][4], al[4][4], bh[4][2], bl[4][2];
#pragma unroll
        for (int i = 0; i < 4; i++) {
            ldsm_x4(ah[i], smem_u32(Ah + (wm*64 + i*16 + lr) * TSTR + kk + lc*8));
            ldsm_x4(al[i], smem_u32(Al + (wm*64 + i*16 + lr) * TSTR + kk + lc*8));
        }
#pragma unroll
        for (int jp = 0; jp < 2; jp++) {
            uint32_t r[4];
            ldsm_x4(r, smem_u32(Bh + (wn*32 + jp*16 + lr) * TSTR + kk + lc*8));
            bh[2*jp][0] = r[0]; bh[2*jp][1] = r[2];
            bh[2*jp+1][0] = r[1]; bh[2*jp+1][1] = r[3];
            ldsm_x4(r, smem_u32(Bl + (wn*32 + jp*16 + lr) * TSTR + kk + lc*8));
            bl[2*jp][0] = r[0]; bl[2*jp][1] = r[2];
            bl[2*jp+1][0] = r[1]; bl[2*jp+1][1] = r[3];
        }
#pragma unroll
        for (int i = 0; i < 4; i++)
#pragma unroll
            for (int j = 0; j < 4; j++) {
                mma_bf16(acc[i][j], ah[i], bh[j]);
                mma_bf16(acc[i][j], ah[i], bl[j]);
                mma_bf16(acc[i][j], al[i], bh[j]);
            }
    }
}

// 32-k chunk, A col-major stored [k32][m128] (trans ldsm), B row-major [128 n][k]
__device__ __forceinline__ void gemm_chunk_qkv(
    const __nv_bfloat16* Xh, const __nv_bfloat16* Xl,
    const __nv_bfloat16* Wh, const __nv_bfloat16* Wl,
    int wm, int wn, int lane, float acc[4][4][4])
{
    const int lr = lane & 15, lc = lane >> 4;
    const int kr = (lane & 7) + ((lane >> 4) << 3);
    const int mo = ((lane >> 3) & 1) << 3;
#pragma unroll
    for (int kk = 0; kk < 32; kk += 16) {
        uint32_t ah[4][4], al[4][4], bh[4][2], bl[4][2];
#pragma unroll
        for (int i = 0; i < 4; i++) {
            ldsm_x4_t(ah[i], smem_u32(Xh + (kk + kr) * XSTR + wm*64 + i*16 + mo));
            ldsm_x4_t(al[i], smem_u32(Xl + (kk + kr) * XSTR + wm*64 + i*16 + mo));
        }
#pragma unroll
        for (int jp = 0; jp < 2; jp++) {
            uint32_t r[4];
            ldsm_x4(r, smem_u32(Wh + (wn*32 + jp*16 + lr) * TSTR + kk + lc*8));
            bh[2*jp][0] = r[0]; bh[2*jp][1] = r[2];
            bh[2*jp+1][0] = r[1]; bh[2*jp+1][1] = r[3];
            ldsm_x4(r, smem_u32(Wl + (wn*32 + jp*16 + lr) * TSTR + kk + lc*8));
            bl[2*jp][0] = r[0]; bl[2*jp][1] = r[2];
            bl[2*jp+1][0] = r[1]; bl[2*jp+1][1] = r[3];
        }
#pragma unroll
        for (int i = 0; i < 4; i++)
#pragma unroll
            for (int j = 0; j < 4; j++) {
                mma_bf16(acc[i][j], ah[i], bh[j]);
                mma_bf16(acc[i][j], ah[i], bl[j]);
                mma_bf16(acc[i][j], al[i], bh[j]);
            }
    }
}

// =====================================================================
// K0a: split x -> xh/xl bf16 [b][c][Np] (pads stay 0)
// =====================================================================
__global__ __launch_bounds__(256) void splitx_kernel(const float* __restrict__ x)
{
    const int row = blockIdx.x, t = threadIdx.x;      // row = b*Cc + c
    const float4* src = reinterpret_cast<const float4*>(x + (size_t)row * Nn);
    __nv_bfloat16* dh = g_xh + (size_t)row * Np;
    __nv_bfloat16* dl = g_xl + (size_t)row * Np;
    for (int n4 = t; n4 < Nn/4; n4 += 256) {
        float4 v = src[n4];
        __nv_bfloat16 h0,h1,h2,h3,l0,l1,l2,l3;
        bsplit(v.x,h0,l0); bsplit(v.y,h1,l1); bsplit(v.z,h2,l2); bsplit(v.w,h3,l3);
        *reinterpret_cast<uint2*>(dh + 4*n4) = pk4b(h0,h1,h2,h3);
        *reinterpret_cast<uint2*>(dl + 4*n4) = pk4b(l0,l1,l2,l3);
    }
}

// K0b: split the 4 weight matrices
__global__ __launch_bounds__(256) void splitw_kernel(
    const float* __restrict__ thw, const float* __restrict__ phw,
    const float* __restrict__ gw,  const float* __restrict__ wzw)
{
    int idx = blockIdx.x * 256 + threadIdx.x;         // float4 units; 4*32768 total
    int a = idx >> 15, off = idx & 32767;
    const float* src = (a == 0) ? thw : (a == 1) ? phw : (a == 2) ? gw : wzw;
    __nv_bfloat16* dh = (a < 3) ? g_wh + (size_t)a * ICc * Cc : g_wzh;
    __nv_bfloat16* dl = (a < 3) ? g_wl + (size_t)a * ICc * Cc : g_wzl;
    float4 v = reinterpret_cast<const float4*>(src)[off];
    __nv_bfloat16 h0,h1,h2,h3,l0,l1,l2,l3;
    bsplit(v.x,h0,l0); bsplit(v.y,h1,l1); bsplit(v.z,h2,l2); bsplit(v.w,h3,l3);
    *reinterpret_cast<uint2*>(dh + 4*off) = pk4b(h0,h1,h2,h3);
    *reinterpret_cast<uint2*>(dl + 4*off) = pk4b(l0,l1,l2,l3);
}

// =====================================================================
// K1: QKV via mma. CTA=(nt 25, w*2+it 6, b). out[n][i] = sum_c x[c][n] W[i][c]
// =====================================================================
__global__ __launch_bounds__(256, 2) void qkv_mma_kernel(
    const float* __restrict__ thb, const float* __restrict__ phb,
    const float* __restrict__ gb)
{
    extern __shared__ __nv_bfloat16 dsm[];
    const uint32_t sb = smem_u32(dsm);
    const int t = threadIdx.x, lane = t & 31, wid = t >> 5;
    const int wm = wid & 1, wn = wid >> 1;
    const int nt = blockIdx.x, w = blockIdx.y >> 1, it = blockIdx.y & 1, b = blockIdx.z;
    const int n0 = nt * 128, i0 = it * 128;

    const __nv_bfloat16* Xh = g_xh + (size_t)b * Cc * Np + n0;
    const __nv_bfloat16* Xl = g_xl + (size_t)b * Cc * Np + n0;
    const __nv_bfloat16* Wh = g_wh + (size_t)w * ICc * Cc + (size_t)i0 * Cc;
    const __nv_bfloat16* Wl = g_wl + (size_t)w * ICc * Cc + (size_t)i0 * Cc;

    float acc[4][4][4] = {};
    constexpr int NC = Cc / 32;  // 16

    {
        uint32_t d0 = sb;
        ldxa(d0, Xh, t);                                  // X chunk: + c*Np handled via src base
        ldxa(d0 + 2*XBUF, Xl, t);
        ld32a(d0 + 2*2*XBUF, Wh, Cc, t);
        ld32a(d0 + 2*2*XBUF + 2*WBUF, Wl, Cc, t);
        CP_COMMIT();
    }
    for (int c = 0; c < NC; c++) {
        if (c + 1 < NC) {
            uint32_t ds = sb + ((c+1) & 1) * (2*QSTAGE);
            ldxa(ds,                      Xh + (size_t)(c+1)*32*Np, t);
            ldxa(ds + 2*XBUF,             Xl + (size_t)(c+1)*32*Np, t);
            ld32a(ds + 2*2*XBUF,          Wh + (c+1)*32, Cc, t);
            ld32a(ds + 2*2*XBUF + 2*WBUF, Wl + (c+1)*32, Cc, t);
            CP_COMMIT();
            CP_WAIT1();
        } else {
            CP_WAIT0();
        }
        __syncthreads();
        const __nv_bfloat16* st = dsm + (c & 1) * QSTAGE;
        gemm_chunk_qkv(st, st + XBUF, st + 2*XBUF, st + 2*XBUF + WBUF, wm, wn, lane, acc);
        __syncthreads();
    }

    const float* bias = (w == 0) ? thb : (w == 1) ? phb : gb;
    const int lr4 = lane >> 2, cb = wn*32 + 2*(lane & 3);

    if (w < 2) {
        __nv_bfloat16* dh = (w == 0) ? g_Qh : g_Kh;
        __nv_bfloat16* dl = (w == 0) ? g_Ql : g_Kl;
#pragma unroll
        for (int i = 0; i < 4; i++)
#pragma unroll
            for (int j = 0; j < 4; j++) {
                int gc = i0 + cb + j*8;
                float b0v = bias[gc], b1v = bias[gc+1];
                int gr = n0 + wm*64 + i*16 + lr4;
                if (gr < Nn) {
                    __nv_bfloat16 h0,h1,l0,l1;
                    bsplit(acc[i][j][0] + b0v, h0, l0);
                    bsplit(acc[i][j][1] + b1v, h1, l1);
                    size_t off = ((size_t)b*Np + gr) * ICc + gc;
                    *reinterpret_cast<uint32_t*>(dh + off) = pkb2(h0, h1);
                    *reinterpret_cast<uint32_t*>(dl + off) = pkb2(l0, l1);
                }
                if (gr + 8 < Nn) {
                    __nv_bfloat16 h0,h1,l0,l1;
                    bsplit(acc[i][j][2] + b0v, h0, l0);
                    bsplit(acc[i][j][3] + b1v, h1, l1);
                    size_t off = ((size_t)b*Np + gr + 8) * ICc + gc;
                    *reinterpret_cast<uint32_t*>(dh + off) = pkb2(h0, h1);
                    *reinterpret_cast<uint32_t*>(dl + off) = pkb2(l0, l1);
                }
            }
    } else {
        // V: stage [n][i] fp32 (stride 129), then write transposed [i][n] hi/lo
        float* stg = reinterpret_cast<float*>(dsm);
        __syncthreads();
#pragma unroll
        for (int i = 0; i < 4; i++)
#pragma unroll
            for (int j = 0; j < 4; j++) {
                int ic = cb + j*8;
                float b0v = bias[i0 + ic], b1v = bias[i0 + ic + 1];
                int nl = wm*64 + i*16 + lr4;
                stg[nl*129 + ic]       = acc[i][j][0] + b0v;
                stg[nl*129 + ic + 1]   = acc[i][j][1] + b1v;
                stg[(nl+8)*129 + ic]   = acc[i][j][2] + b0v;
                stg[(nl+8)*129 + ic+1] = acc[i][j][3] + b1v;
            }
        __syncthreads();
#pragma unroll
        for (int k = 0; k < 32; k++) {
            int u = t + 256*k;
            int ir = u >> 6, np2 = u & 63;
            int gn = n0 + 2*np2;
            if (gn < Nn) {
                float v0 = stg[(2*np2)*129 + ir], v1 = stg[(2*np2+1)*129 + ir];
                __nv_bfloat16 h0,h1,l0,l1;
                bsplit(v0, h0, l0); bsplit(v1, h1, l1);
                size_t off = ((size_t)b*ICc + i0 + ir) * Np + gn;
                *reinterpret_cast<uint32_t*>(g_Vth + off) = pkb2(h0, h1);
                *reinterpret_cast<uint32_t*>(g_Vtl + off) = pkb2(l0, l1);
            }
        }
    }
}

// =====================================================================
// K2: S = Q K^T (unchanged mainloop)
// =====================================================================
__global__ __launch_bounds__(256, 2) void sgemm_kernel()
{
    extern __shared__ __nv_bfloat16 dsm[];
    const uint32_t sb = smem_u32(dsm);
    const int t = threadIdx.x, lane = t & 31, wid = t >> 5;
    const int wm = wid & 1, wn = wid >> 1;
    const int q0 = blockIdx.x * 128, n0 = blockIdx.y * 128, b = blockIdx.z;
    const __nv_bfloat16* Qh = g_Qh + ((size_t)b*Np + q0) * ICc;
    const __nv_bfloat16* Ql = g_Ql + ((size_t)b*Np + q0) * ICc;
    const __nv_bfloat16* Kh = g_Kh + ((size_t)b*Np + n0) * ICc;
    const __nv_bfloat16* Kl = g_Kl + ((size_t)b*Np + n0) * ICc;

    float acc[4][4][4] = {};
    constexpr int NC = ICc / 32;

    {
        uint32_t d0 = sb;
        ld32a(d0,             Qh, ICc, t);
        ld32a(d0 + 2*BUF_E,   Ql, ICc, t);
        ld32a(d0 + 2*2*BUF_E, Kh, ICc, t);
        ld32a(d0 + 2*3*BUF_E, Kl, ICc, t);
        CP_COMMIT();
    }
    for (int c = 0; c < NC; c++) {
        if (c + 1 < NC) {
            uint32_t ds = sb + ((c+1) & 1) * (2*STAGE_E);
            ld32a(ds,             Qh + (c+1)*32, ICc, t);
            ld32a(ds + 2*BUF_E,   Ql + (c+1)*32, ICc, t);
            ld32a(ds + 2*2*BUF_E, Kh + (c+1)*32, ICc, t);
            ld32a(ds + 2*3*BUF_E, Kl + (c+1)*32, ICc, t);
            CP_COMMIT();
            CP_WAIT1();
        } else {
            CP_WAIT0();
        }
        __syncthreads();
        const __nv_bfloat16* st = dsm + (c & 1) * STAGE_E;
        gemm_chunk(st, st + BUF_E, st + 2*BUF_E, st + 3*BUF_E, wm, wn, lane, acc);
        __syncthreads();
    }

    float* So = g_S + ((size_t)b*Np + q0) * Np + n0;
    const int r0 = wm*64 + (lane >> 2), cb = wn*32 + 2*(lane & 3);
#pragma unroll
    for (int i = 0; i < 4; i++)
#pragma unroll
        for (int j = 0; j < 4; j++) {
            *reinterpret_cast<float2*>(So + (size_t)(r0 + i*16) * Np + cb + j*8) =
                make_float2(acc[i][j][0], acc[i][j][1]);
            *reinterpret_cast<float2*>(So + (size_t)(r0 + i*16 + 8) * Np + cb + j*8) =
                make_float2(acc[i][j][2], acc[i][j][3]);
        }
}

// =====================================================================
// K3: row softmax -> P hi/lo
// =====================================================================
__global__ __launch_bounds__(256) void softmax_kernel()
{
    const int r = blockIdx.x, b = blockIdx.y, t = threadIdx.x;
    const float4* Sr = reinterpret_cast<const float4*>(g_S + ((size_t)b*Np + r) * Np);
    float4 v[4];
    float mx = -1e30f;
#pragma unroll
    for (int i = 0; i < 4; i++) {
        int idx = t + 256*i;
        if (idx < 784) {
            v[i] = Sr[idx];
            mx = fmaxf(mx, fmaxf(fmaxf(v[i].x, v[i].y), fmaxf(v[i].z, v[i].w)));
        }
    }
    __shared__ float rd[8], rd2[8];
    float m = mx;
#pragma unroll
    for (int o = 16; o; o >>= 1) m = fmaxf(m, __shfl_xor_sync(0xffffffffu, m, o));
    if ((t & 31) == 0) rd[t >> 5] = m;
    __syncthreads();
    m = rd[0];
#pragma unroll
    for (int w = 1; w < 8; w++) m = fmaxf(m, rd[w]);
    float s = 0.f;
#pragma unroll
    for (int i = 0; i < 4; i++) {
        int idx = t + 256*i;
        if (idx < 784) {
            v[i].x = __expf(v[i].x - m); v[i].y = __expf(v[i].y - m);
            v[i].z = __expf(v[i].z - m); v[i].w = __expf(v[i].w - m);
            s += (v[i].x + v[i].y) + (v[i].z + v[i].w);
        }
    }
#pragma unroll
    for (int o = 16; o; o >>= 1) s += __shfl_xor_sync(0xffffffffu, s, o);
    if ((t & 31) == 0) rd2[t >> 5] = s;
    __syncthreads();
    s = rd2[0];
#pragma unroll
    for (int w = 1; w < 8; w++) s += rd2[w];
    float inv = 1.0f / s;
    __nv_bfloat16* Ph = g_Ph + ((size_t)b*Np + r) * Np;
    __nv_bfloat16* Pl = g_Pl + ((size_t)b*Np + r) * Np;
#pragma unroll
    for (int i = 0; i < 4; i++) {
        int idx = t + 256*i;
        if (idx < 784) {
            __nv_bfloat16 h0,h1,h2,h3,l0,l1,l2,l3;
            bsplit(v[i].x*inv,h0,l0); bsplit(v[i].y*inv,h1,l1);
            bsplit(v[i].z*inv,h2,l2); bsplit(v[i].w*inv,h3,l3);
            *reinterpret_cast<uint2*>(Ph + 4*idx) = pk4b(h0,h1,h2,h3);
            *reinterpret_cast<uint2*>(Pl + 4*idx) = pk4b(l0,l1,l2,l3);
        } else if (idx < 800) {
            uint2 z = make_uint2(0u, 0u);
            *reinterpret_cast<uint2*>(Ph + 4*idx) = z;
            *reinterpret_cast<uint2*>(Pl + 4*idx) = z;
        }
    }
}

// =====================================================================
// K4: Y = P V -> Y hi/lo bf16
// =====================================================================
__global__ __launch_bounds__(256, 2) void pv_kernel()
{
    extern __shared__ __nv_bfloat16 dsm[];
    const uint32_t sb = smem_u32(dsm);
    const int t = threadIdx.x, lane = t & 31, wid = t >> 5;
    const int wm = wid & 1, wn = wid >> 1;
    const int q0 = blockIdx.x * 128, d0 = blockIdx.y * 128, b = blockIdx.z;
    const __nv_bfloat16* Ph = g_Ph + ((size_t)b*Np + q0) * Np;
    const __nv_bfloat16* Pl = g_Pl + ((size_t)b*Np + q0) * Np;
    const __nv_bfloat16* Vh = g_Vth + ((size_t)b*ICc + d0) * Np;
    const __nv_bfloat16* Vl = g_Vtl + ((size_t)b*ICc + d0) * Np;

    float acc[4][4][4] = {};
    constexpr int NC = Np / 32;

    {
        uint32_t d0s = sb;
        ld32a(d0s,             Ph, Np, t);
        ld32a(d0s + 2*BUF_E,   Pl, Np, t);
        ld32a(d0s + 2*2*BUF_E, Vh, Np, t);
        ld32a(d0s + 2*3*BUF_E, Vl, Np, t);
        CP_COMMIT();
    }
    for (int c = 0; c < NC; c++) {
        if (c + 1 < NC) {
            uint32_t ds = sb + ((c+1) & 1) * (2*STAGE_E);
            ld32a(ds,             Ph + (c+1)*32, Np, t);
            ld32a(ds + 2*BUF_E,   Pl + (c+1)*32, Np, t);
            ld32a(ds + 2*2*BUF_E, Vh + (c+1)*32, Np, t);
            ld32a(ds + 2*3*BUF_E, Vl + (c+1)*32, Np, t);
            CP_COMMIT();
            CP_WAIT1();
        } else {
            CP_WAIT0();
        }
        __syncthreads();
        const __nv_bfloat16* st = dsm + (c & 1) * STAGE_E;
        gemm_chunk(st, st + BUF_E, st + 2*BUF_E, st + 3*BUF_E, wm, wn, lane, acc);
        __syncthreads();
    }

    const int r0 = wm*64 + (lane >> 2), cb = wn*32 + 2*(lane & 3);
#pragma unroll
    for (int i = 0; i < 4; i++)
#pragma unroll
        for (int j = 0; j < 4; j++) {
            int gc = d0 + cb + j*8;
            {
                int gr = q0 + r0 + i*16;
                __nv_bfloat16 h0,h1,l0,l1;
                bsplit(acc[i][j][0], h0, l0); bsplit(acc[i][j][1], h1, l1);
                size_t off = ((size_t)b*Np + gr) * ICc + gc;
                *reinterpret_cast<uint32_t*>(g_Yh + off) = pkb2(h0, h1);
                *reinterpret_cast<uint32_t*>(g_Yl + off) = pkb2(l0, l1);
            }
            {
                int gr = q0 + r0 + i*16 + 8;
                __nv_bfloat16 h0,h1,l0,l1;
                bsplit(acc[i][j][2], h0, l0); bsplit(acc[i][j][3], h1, l1);
                size_t off = ((size_t)b*Np + gr) * ICc + gc;
                *reinterpret_cast<uint32_t*>(g_Yh + off) = pkb2(h0, h1);
                *reinterpret_cast<uint32_t*>(g_Yl + off) = pkb2(l0, l1);
            }
        }
}

// =====================================================================
// K5: Z[c][n] = Wz Y^T + b via mma. CTA=(ct 4, nt 25, b).
// =====================================================================
__global__ __launch_bounds__(256, 2) void wz_mma_kernel(const float* __restrict__ wzb)
{
    extern __shared__ __nv_bfloat16 dsm[];
    const uint32_t sb = smem_u32(dsm);
    const int t = threadIdx.x, lane = t & 31, wid = t >> 5;
    const int wm = wid & 1, wn = wid >> 1;
    const int c0 = blockIdx.x * 128, n0 = blockIdx.y * 128, b = blockIdx.z;
    const __nv_bfloat16* Ahp = g_wzh + (size_t)c0 * ICc;
    const __nv_bfloat16* Alp = g_wzl + (size_t)c0 * ICc;
    const __nv_bfloat16* Bhp = g_Yh + ((size_t)b*Np + n0) * ICc;
    const __nv_bfloat16* Blp = g_Yl + ((size_t)b*Np + n0) * ICc;

    float acc[4][4][4] = {};
    constexpr int NC = ICc / 32;

    {
        uint32_t d0 = sb;
        ld32a(d0,             Ahp, ICc, t);
        ld32a(d0 + 2*BUF_E,   Alp, ICc, t);
        ld32a(d0 + 2*2*BUF_E, Bhp, ICc, t);
        ld32a(d0 + 2*3*BUF_E, Blp, ICc, t);
        CP_COMMIT();
    }
    for (int c = 0; c < NC; c++) {
        if (c + 1 < NC) {
            uint32_t ds = sb + ((c+1) & 1) * (2*STAGE_E);
            ld32a(ds,             Ahp + (c+1)*32, ICc, t);
            ld32a(ds + 2*BUF_E,   Alp + (c+1)*32, ICc, t);
            ld32a(ds + 2*2*BUF_E, Bhp + (c+1)*32, ICc, t);
            ld32a(ds + 2*3*BUF_E, Blp + (c+1)*32, ICc, t);
            CP_COMMIT();
            CP_WAIT1();
        } else {
            CP_WAIT0();
        }
        __syncthreads();
        const __nv_bfloat16* st = dsm + (c & 1) * STAGE_E;
        gemm_chunk(st, st + BUF_E, st + 2*BUF_E, st + 3*BUF_E, wm, wn, lane, acc);
        __syncthreads();
    }

    float* Zb = g_Z + (size_t)b * Cc * Nn;
    const int r0 = c0 + wm*64 + (lane >> 2), cb = wn*32 + 2*(lane & 3);
#pragma unroll
    for (int i = 0; i < 4; i++) {
        float wb0 = wzb[r0 + i*16], wb1 = wzb[r0 + i*16 + 8];
#pragma unroll
        for (int j = 0; j < 4; j++) {
            int gn = n0 + cb + j*8;
            if (gn < Nn) {
                *reinterpret_cast<float2*>(Zb + (size_t)(r0 + i*16) * Nn + gn) =
                    make_float2(acc[i][j][0] + wb0, acc[i][j][1] + wb0);
                *reinterpret_cast<float2*>(Zb + (size_t)(r0 + i*16 + 8) * Nn + gn) =
                    make_float2(acc[i][j][2] + wb1, acc[i][j][3] + wb1);
            }
        }
    }
}

// =====================================================================
// K6: BN stats ; K7: final elementwise
// =====================================================================
__global__ __launch_bounds__(256) void bnstats_kernel(
    const float* __restrict__ bnw, const float* __restrict__ bnb)
{
    const int c = blockIdx.x, t = threadIdx.x;
    float s = 0.f, q = 0.f;
    for (int b = 0; b < Bb; b++) {
        const float4* row = reinterpret_cast<const float4*>(g_Z + ((size_t)b*Cc + c) * Nn);
        for (int n4 = t; n4 < Nn/4; n4 += 256) {
            float4 v = row[n4];
            s += (v.x+v.y)+(v.z+v.w);
            q += (v.x*v.x+v.y*v.y)+(v.z*v.z+v.w*v.w);
        }
    }
    __shared__ float ss[256], qs[256];
    ss[t] = s; qs[t] = q;
    __syncthreads();
    for (int o = 128; o > 0; o >>= 1) {
        if (t < o) { ss[t] += ss[t+o]; qs[t] += qs[t+o]; }
        __syncthreads();
    }
    if (t == 0) {
        const float inv_n = 1.0f / (float)(Bb * Nn);
        float mean = ss[0]*inv_n, var = qs[0]*inv_n - mean*mean;
        float sc = bnw[c] * rsqrtf(var + 1e-5f);
        g_scaleC[c] = sc;
        g_shiftC[c] = bnb[c] - mean*sc;
    }
}

__global__ __launch_bounds__(256) void final_kernel(
    const float* __restrict__ x, float* __restrict__ out)
{
    int i = blockIdx.x * 256 + threadIdx.x;
    int c = (i / (Nn/4)) & (Cc-1);
    float sc = g_scaleC[c], sh = g_shiftC[c];
    float4 z = reinterpret_cast<const float4*>(g_Z)[i];
    float4 xv = reinterpret_cast<const float4*>(x)[i];
    float4 o;
    o.x = fmaf(z.x, sc, sh) + xv.x; o.y = fmaf(z.y, sc, sh) + xv.y;
    o.z = fmaf(z.z, sc, sh) + xv.z; o.w = fmaf(z.w, sc, sh) + xv.w;
    reinterpret_cast<float4*>(out)[i] = o;
}

// =====================================================================
extern "C" void kernel_launch(void* const* d_in, const int* in_sizes, int n_in,
                              void* d_out, int out_size)
{
    (void)in_sizes; (void)n_in; (void)out_size;
    const float* x   = (const float*)d_in[0];
    const float* thw = (const float*)d_in[1];
    const float* thb = (const float*)d_in[2];
    const float* phw = (const float*)d_in[3];
    const float* phb = (const float*)d_in[4];
    const float* gw  = (const float*)d_in[5];
    const float* gbb = (const float*)d_in[6];
    const float* wzw = (const float*)d_in[7];
    const float* wzb = (const float*)d_in[8];
    const float* bnw = (const float*)d_in[9];
    const float* bnb = (const float*)d_in[10];
    float* out = (float*)d_out;

    cudaFuncSetAttribute(qkv_mma_kernel, cudaFuncAttributeMaxDynamicSharedMemorySize, QKV_SMEM);
    cudaFuncSetAttribute(sgemm_kernel,   cudaFuncAttributeMaxDynamicSharedMemorySize, GEMM_SMEM);
    cudaFuncSetAttribute(pv_kernel,      cudaFuncAttributeMaxDynamicSharedMemorySize, GEMM_SMEM);
    cudaFuncSetAttribute(wz_mma_kernel,  cudaFuncAttributeMaxDynamicSharedMemorySize, GEMM_SMEM);

    splitx_kernel<<<Bb*Cc, 256>>>(x);
    splitw_kernel<<<512, 256>>>(thw, phw, gw, wzw);
    qkv_mma_kernel<<<dim3(Np/128, 6, Bb), 256, QKV_SMEM>>>(thb, phb, gbb);
    sgemm_kernel<<<dim3(Np/128, Np/128, Bb), 256, GEMM_SMEM>>>();
    softmax_kernel<<<dim3(Nn, Bb), 256>>>();
    pv_kernel<<<dim3(Np/128, ICc/128, Bb), 256, GEMM_SMEM>>>();
    wz_mma_kernel<<<dim3(Cc/128, Np/128, Bb), 256, GEMM_SMEM>>>(wzb);
    bnstats_kernel<<<Cc, 256>>>(bnw, bnb);
    final_kernel<<<(Bb*Cc*Nn/4)/256, 256>>>(x, out);
}

// round 9
// speedup vs baseline: 2.7241x; 1.0017x over previous
#include <cuda_runtime.h>
#include <cuda_bf16.h>
#include <math.h>
#include <cstdint>

constexpr int Bb  = 8;
constexpr int Cc  = 512;
constexpr int Nn  = 3136;
constexpr int ICc = 256;
constexpr int Np  = 3200;   // 25*128

// ---------------- scratch ----------------
__device__ __align__(256) __nv_bfloat16 g_xh[Bb*Cc*Np];
__device__ __align__(256) __nv_bfloat16 g_xl[Bb*Cc*Np];
__device__ __align__(256) __nv_bfloat16 g_wh[3*ICc*Cc];
__device__ __align__(256) __nv_bfloat16 g_wl[3*ICc*Cc];
__device__ __align__(256) __nv_bfloat16 g_wzh[Cc*ICc];
__device__ __align__(256) __nv_bfloat16 g_wzl[Cc*ICc];
__device__ __align__(256) __nv_bfloat16 g_Qh[Bb*Np*ICc];
__device__ __align__(256) __nv_bfloat16 g_Ql[Bb*Np*ICc];
__device__ __align__(256) __nv_bfloat16 g_Kh[Bb*Np*ICc];
__device__ __align__(256) __nv_bfloat16 g_Kl[Bb*Np*ICc];
__device__ __align__(256) __nv_bfloat16 g_Vth[Bb*ICc*Np];   // [b][d][n]
__device__ __align__(256) __nv_bfloat16 g_Vtl[Bb*ICc*Np];
__device__ __align__(256) float         g_S [(size_t)Bb*Np*Np];
__device__ __align__(256) __nv_bfloat16 g_Ph[(size_t)Bb*Np*Np];
__device__ __align__(256) __nv_bfloat16 g_Pl[(size_t)Bb*Np*Np];
__device__ __align__(256) __nv_bfloat16 g_Yh[Bb*Np*ICc];    // [b][n][ic]
__device__ __align__(256) __nv_bfloat16 g_Yl[Bb*Np*ICc];
__device__ __align__(256) float g_Z[Bb*Cc*Nn];              // [b][c][n]
__device__ float g_scaleC[Cc];
__device__ float g_shiftC[Cc];

// ---------------- helpers ----------------
__device__ __forceinline__ uint32_t smem_u32(const void* p) {
    uint32_t a;
    asm("{ .reg .u64 t; cvta.to.shared.u64 t, %1; cvt.u32.u64 %0, t; }" : "=r"(a) : "l"(p));
    return a;
}
__device__ __forceinline__ void ldsm_x4(uint32_t* r, uint32_t addr) {
    asm volatile("ldmatrix.sync.aligned.m8n8.x4.shared.b16 {%0,%1,%2,%3}, [%4];"
                 : "=r"(r[0]), "=r"(r[1]), "=r"(r[2]), "=r"(r[3]) : "r"(addr));
}
__device__ __forceinline__ void ldsm_x4_t(uint32_t* r, uint32_t addr) {
    asm volatile("ldmatrix.sync.aligned.m8n8.x4.trans.shared.b16 {%0,%1,%2,%3}, [%4];"
                 : "=r"(r[0]), "=r"(r[1]), "=r"(r[2]), "=r"(r[3]) : "r"(addr));
}
__device__ __forceinline__ void mma_bf16(float* d, const uint32_t* a, const uint32_t* b) {
    asm volatile("mma.sync.aligned.m16n8k16.row.col.f32.bf16.bf16.f32 "
                 "{%0,%1,%2,%3}, {%4,%5,%6,%7}, {%8,%9}, {%0,%1,%2,%3};"
                 : "+f"(d[0]), "+f"(d[1]), "+f"(d[2]), "+f"(d[3])
                 : "r"(a[0]), "r"(a[1]), "r"(a[2]), "r"(a[3]), "r"(b[0]), "r"(b[1]));
}
#define CP16(sm, gp)  asm volatile("cp.async.ca.shared.global [%0], [%1], 16;" :: "r"(sm), "l"(gp) : "memory")
#define CP_COMMIT()   asm volatile("cp.async.commit_group;" ::: "memory")
#define CP_WAIT1()    asm volatile("cp.async.wait_group 1;" ::: "memory")
#define CP_WAIT0()    asm volatile("cp.async.wait_group 0;" ::: "memory")

__device__ __forceinline__ void bsplit(float v, __nv_bfloat16& h, __nv_bfloat16& l) {
    h = __float2bfloat16(v);
    l = __float2bfloat16(v - __bfloat162float(h));
}
__device__ __forceinline__ uint32_t pkb2(__nv_bfloat16 a, __nv_bfloat16 b) {
    __nv_bfloat162 p = __halves2bfloat162(a, b);
    return *reinterpret_cast<unsigned int*>(&p);
}
__device__ __forceinline__ uint2 pk4b(__nv_bfloat16 a, __nv_bfloat16 b, __nv_bfloat16 c, __nv_bfloat16 d) {
    return make_uint2(pkb2(a, b), pkb2(c, d));
}

constexpr int TSTR = 40;                    // [rows][k32] tiles
constexpr int BUF_E = 128 * TSTR;
constexpr int STAGE_E = 4 * BUF_E;
constexpr int GEMM_SMEM = 2 * STAGE_E * 2;  // 81920 B

constexpr int XSTR = 136;                   // x-tile [k32][n128]
constexpr int XBUF = 32 * XSTR;
constexpr int WBUF = 128 * TSTR;
constexpr int QSTAGE = 2 * XBUF + 2 * WBUF;
constexpr int QKV_SMEM = 2 * QSTAGE * 2;    // 75776 B (>= 128*129*4 V stage)

// async: [128 rows][32 cols] bf16 row-major -> smem [128][TSTR]  (128 threads)
__device__ __forceinline__ void ld32a(uint32_t dsm, const __nv_bfloat16* src, int ldg, int t) {
#pragma unroll
    for (int i = 0; i < 4; i++) {
        int u = t + 128 * i, row = u >> 2, cq = u & 3;
        CP16(dsm + row * (TSTR * 2) + cq * 16, src + (size_t)row * ldg + cq * 8);
    }
}
// async: x chunk [32 c-rows][128 n-cols] -> smem [32][XSTR]  (128 threads)
__device__ __forceinline__ void ldxa(uint32_t dsm, const __nv_bfloat16* src, int t) {
#pragma unroll
    for (int i = 0; i < 4; i++) {
        int u = t + 128 * i, row = u >> 4, cq = u & 15;
        CP16(dsm + row * (XSTR * 2) + cq * 16, src + (size_t)row * Np + cq * 8);
    }
}

// 32-k chunk, warp tile 64x64, 3-pass split. 4 warps (wm,wn in {0,1}).
__device__ __forceinline__ void gemm_chunk(
    const __nv_bfloat16* Ah, const __nv_bfloat16* Al,
    const __nv_bfloat16* Bh, const __nv_bfloat16* Bl,
    int wm, int wn, int lane, float acc[4][8][4])
{
    const int lr = lane & 15, lc = lane >> 4;
#pragma unroll
    for (int kk = 0; kk < 32; kk += 16) {
        uint32_t ah[4][4], al[4][4], bh[8][2], bl[8][2];
#pragma unroll
        for (int i = 0; i < 4; i++) {
            ldsm_x4(ah[i], smem_u32(Ah + (wm*64 + i*16 + lr) * TSTR + kk + lc*8));
            ldsm_x4(al[i], smem_u32(Al + (wm*64 + i*16 + lr) * TSTR + kk + lc*8));
        }
#pragma unroll
        for (int jp = 0; jp < 4; jp++) {
            uint32_t r[4];
            ldsm_x4(r, smem_u32(Bh + (wn*64 + jp*16 + lr) * TSTR + kk + lc*8));
            bh[2*jp][0] = r[0]; bh[2*jp][1] = r[2];
            bh[2*jp+1][0] = r[1]; bh[2*jp+1][1] = r[3];
            ldsm_x4(r, smem_u32(Bl + (wn*64 + jp*16 + lr) * TSTR + kk + lc*8));
            bl[2*jp][0] = r[0]; bl[2*jp][1] = r[2];
            bl[2*jp+1][0] = r[1]; bl[2*jp+1][1] = r[3];
        }
#pragma unroll
        for (int i = 0; i < 4; i++)
#pragma unroll
            for (int j = 0; j < 8; j++) {
                mma_bf16(acc[i][j], ah[i], bh[j]);
                mma_bf16(acc[i][j], ah[i], bl[j]);
                mma_bf16(acc[i][j], al[i], bh[j]);
            }
    }
}

// same but A col-major [k32][m128] via trans ldsm (qkv)
__device__ __forceinline__ void gemm_chunk_qkv(
    const __nv_bfloat16* Xh, const __nv_bfloat16* Xl,
    const __nv_bfloat16* Wh, const __nv_bfloat16* Wl,
    int wm, int wn, int lane, float acc[4][8][4])
{
    const int lr = lane & 15, lc = lane >> 4;
    const int kr = (lane & 7) + ((lane >> 4) << 3);
    const int mo = ((lane >> 3) & 1) << 3;
#pragma unroll
    for (int kk = 0; kk < 32; kk += 16) {
        uint32_t ah[4][4], al[4][4], bh[8][2], bl[8][2];
#pragma unroll
        for (int i = 0; i < 4; i++) {
            ldsm_x4_t(ah[i], smem_u32(Xh + (kk + kr) * XSTR + wm*64 + i*16 + mo));
            ldsm_x4_t(al[i], smem_u32(Xl + (kk + kr) * XSTR + wm*64 + i*16 + mo));
        }
#pragma unroll
        for (int jp = 0; jp < 4; jp++) {
            uint32_t r[4];
            ldsm_x4(r, smem_u32(Wh + (wn*64 + jp*16 + lr) * TSTR + kk + lc*8));
            bh[2*jp][0] = r[0]; bh[2*jp][1] = r[2];
            bh[2*jp+1][0] = r[1]; bh[2*jp+1][1] = r[3];
            ldsm_x4(r, smem_u32(Wl + (wn*64 + jp*16 + lr) * TSTR + kk + lc*8));
            bl[2*jp][0] = r[0]; bl[2*jp][1] = r[2];
            bl[2*jp+1][0] = r[1]; bl[2*jp+1][1] = r[3];
        }
#pragma unroll
        for (int i = 0; i < 4; i++)
#pragma unroll
            for (int j = 0; j < 8; j++) {
                mma_bf16(acc[i][j], ah[i], bh[j]);
                mma_bf16(acc[i][j], ah[i], bl[j]);
                mma_bf16(acc[i][j], al[i], bh[j]);
            }
    }
}

// =====================================================================
// K0a: split x -> xh/xl ; K0b: split weights
// =====================================================================
__global__ __launch_bounds__(256) void splitx_kernel(const float* __restrict__ x)
{
    const int row = blockIdx.x, t = threadIdx.x;
    const float4* src = reinterpret_cast<const float4*>(x + (size_t)row * Nn);
    __nv_bfloat16* dh = g_xh + (size_t)row * Np;
    __nv_bfloat16* dl = g_xl + (size_t)row * Np;
    for (int n4 = t; n4 < Nn/4; n4 += 256) {
        float4 v = src[n4];
        __nv_bfloat16 h0,h1,h2,h3,l0,l1,l2,l3;
        bsplit(v.x,h0,l0); bsplit(v.y,h1,l1); bsplit(v.z,h2,l2); bsplit(v.w,h3,l3);
        *reinterpret_cast<uint2*>(dh + 4*n4) = pk4b(h0,h1,h2,h3);
        *reinterpret_cast<uint2*>(dl + 4*n4) = pk4b(l0,l1,l2,l3);
    }
}

__global__ __launch_bounds__(256) void splitw_kernel(
    const float* __restrict__ thw, const float* __restrict__ phw,
    const float* __restrict__ gw,  const float* __restrict__ wzw)
{
    int idx = blockIdx.x * 256 + threadIdx.x;
    int a = idx >> 15, off = idx & 32767;
    const float* src = (a == 0) ? thw : (a == 1) ? phw : (a == 2) ? gw : wzw;
    __nv_bfloat16* dh = (a < 3) ? g_wh + (size_t)a * ICc * Cc : g_wzh;
    __nv_bfloat16* dl = (a < 3) ? g_wl + (size_t)a * ICc * Cc : g_wzl;
    float4 v = reinterpret_cast<const float4*>(src)[off];
    __nv_bfloat16 h0,h1,h2,h3,l0,l1,l2,l3;
    bsplit(v.x,h0,l0); bsplit(v.y,h1,l1); bsplit(v.z,h2,l2); bsplit(v.w,h3,l3);
    *reinterpret_cast<uint2*>(dh + 4*off) = pk4b(h0,h1,h2,h3);
    *reinterpret_cast<uint2*>(dl + 4*off) = pk4b(l0,l1,l2,l3);
}

// =====================================================================
// K1: QKV via mma, 128 threads, warp 64x64
// =====================================================================
__global__ __launch_bounds__(128, 2) void qkv_mma_kernel(
    const float* __restrict__ thb, const float* __restrict__ phb,
    const float* __restrict__ gb)
{
    extern __shared__ __nv_bfloat16 dsm[];
    const uint32_t sb = smem_u32(dsm);
    const int t = threadIdx.x, lane = t & 31, wid = t >> 5;
    const int wm = wid & 1, wn = (wid >> 1) & 1;
    const int nt = blockIdx.x, w = blockIdx.y >> 1, it = blockIdx.y & 1, b = blockIdx.z;
    const int n0 = nt * 128, i0 = it * 128;

    const __nv_bfloat16* Xh = g_xh + (size_t)b * Cc * Np + n0;
    const __nv_bfloat16* Xl = g_xl + (size_t)b * Cc * Np + n0;
    const __nv_bfloat16* Wh = g_wh + (size_t)w * ICc * Cc + (size_t)i0 * Cc;
    const __nv_bfloat16* Wl = g_wl + (size_t)w * ICc * Cc + (size_t)i0 * Cc;

    float acc[4][8][4] = {};
    constexpr int NC = Cc / 32;  // 16

    {
        uint32_t d0 = sb;
        ldxa(d0, Xh, t);
        ldxa(d0 + 2*XBUF, Xl, t);
        ld32a(d0 + 2*2*XBUF, Wh, Cc, t);
        ld32a(d0 + 2*2*XBUF + 2*WBUF, Wl, Cc, t);
        CP_COMMIT();
    }
    for (int c = 0; c < NC; c++) {
        if (c + 1 < NC) {
            uint32_t ds = sb + ((c+1) & 1) * (2*QSTAGE);
            ldxa(ds,                      Xh + (size_t)(c+1)*32*Np, t);
            ldxa(ds + 2*XBUF,             Xl + (size_t)(c+1)*32*Np, t);
            ld32a(ds + 2*2*XBUF,          Wh + (c+1)*32, Cc, t);
            ld32a(ds + 2*2*XBUF + 2*WBUF, Wl + (c+1)*32, Cc, t);
            CP_COMMIT();
            CP_WAIT1();
        } else {
            CP_WAIT0();
        }
        __syncthreads();
        const __nv_bfloat16* st = dsm + (c & 1) * QSTAGE;
        gemm_chunk_qkv(st, st + XBUF, st + 2*XBUF, st + 2*XBUF + WBUF, wm, wn, lane, acc);
        __syncthreads();
    }

    const float* bias = (w == 0) ? thb : (w == 1) ? phb : gb;
    const int lr4 = lane >> 2, cb = wn*64 + 2*(lane & 3);

    if (w < 2) {
        __nv_bfloat16* dh = (w == 0) ? g_Qh : g_Kh;
        __nv_bfloat16* dl = (w == 0) ? g_Ql : g_Kl;
#pragma unroll
        for (int i = 0; i < 4; i++)
#pragma unroll
            for (int j = 0; j < 8; j++) {
                int gc = i0 + cb + j*8;
                float b0v = bias[gc], b1v = bias[gc+1];
                int gr = n0 + wm*64 + i*16 + lr4;
                if (gr < Nn) {
                    __nv_bfloat16 h0,h1,l0,l1;
                    bsplit(acc[i][j][0] + b0v, h0, l0);
                    bsplit(acc[i][j][1] + b1v, h1, l1);
                    size_t off = ((size_t)b*Np + gr) * ICc + gc;
                    *reinterpret_cast<uint32_t*>(dh + off) = pkb2(h0, h1);
                    *reinterpret_cast<uint32_t*>(dl + off) = pkb2(l0, l1);
                }
                if (gr + 8 < Nn) {
                    __nv_bfloat16 h0,h1,l0,l1;
                    bsplit(acc[i][j][2] + b0v, h0, l0);
                    bsplit(acc[i][j][3] + b1v, h1, l1);
                    size_t off = ((size_t)b*Np + gr + 8) * ICc + gc;
                    *reinterpret_cast<uint32_t*>(dh + off) = pkb2(h0, h1);
                    *reinterpret_cast<uint32_t*>(dl + off) = pkb2(l0, l1);
                }
            }
    } else {
        // V: stage [n][i] fp32, then write transposed [i][n] hi/lo
        float* stg = reinterpret_cast<float*>(dsm);
        __syncthreads();
#pragma unroll
        for (int i = 0; i < 4; i++)
#pragma unroll
            for (int j = 0; j < 8; j++) {
                int ic = cb + j*8;
                float b0v = bias[i0 + ic], b1v = bias[i0 + ic + 1];
                int nl = wm*64 + i*16 + lr4;
                stg[nl*129 + ic]       = acc[i][j][0] + b0v;
                stg[nl*129 + ic + 1]   = acc[i][j][1] + b1v;
                stg[(nl+8)*129 + ic]   = acc[i][j][2] + b0v;
                stg[(nl+8)*129 + ic+1] = acc[i][j][3] + b1v;
            }
        __syncthreads();
#pragma unroll
        for (int k = 0; k < 64; k++) {
            int u = t + 128*k;
            int ir = u >> 6, np2 = u & 63;
            int gn = n0 + 2*np2;
            if (gn < Nn) {
                float v0 = stg[(2*np2)*129 + ir], v1 = stg[(2*np2+1)*129 + ir];
                __nv_bfloat16 h0,h1,l0,l1;
                bsplit(v0, h0, l0); bsplit(v1, h1, l1);
                size_t off = ((size_t)b*ICc + i0 + ir) * Np + gn;
                *reinterpret_cast<uint32_t*>(g_Vth + off) = pkb2(h0, h1);
                *reinterpret_cast<uint32_t*>(g_Vtl + off) = pkb2(l0, l1);
            }
        }
    }
}

// =====================================================================
// K2: S = Q K^T, 128 threads, warp 64x64
// =====================================================================
__global__ __launch_bounds__(128, 2) void sgemm_kernel()
{
    extern __shared__ __nv_bfloat16 dsm[];
    const uint32_t sb = smem_u32(dsm);
    const int t = threadIdx.x, lane = t & 31, wid = t >> 5;
    const int wm = wid & 1, wn = (wid >> 1) & 1;
    const int q0 = blockIdx.x * 128, n0 = blockIdx.y * 128, b = blockIdx.z;
    const __nv_bfloat16* Qh = g_Qh + ((size_t)b*Np + q0) * ICc;
    const __nv_bfloat16* Ql = g_Ql + ((size_t)b*Np + q0) * ICc;
    const __nv_bfloat16* Kh = g_Kh + ((size_t)b*Np + n0) * ICc;
    const __nv_bfloat16* Kl = g_Kl + ((size_t)b*Np + n0) * ICc;

    float acc[4][8][4] = {};
    constexpr int NC = ICc / 32;

    {
        uint32_t d0 = sb;
        ld32a(d0,             Qh, ICc, t);
        ld32a(d0 + 2*BUF_E,   Ql, ICc, t);
        ld32a(d0 + 2*2*BUF_E, Kh, ICc, t);
        ld32a(d0 + 2*3*BUF_E, Kl, ICc, t);
        CP_COMMIT();
    }
    for (int c = 0; c < NC; c++) {
        if (c + 1 < NC) {
            uint32_t ds = sb + ((c+1) & 1) * (2*STAGE_E);
            ld32a(ds,             Qh + (c+1)*32, ICc, t);
            ld32a(ds + 2*BUF_E,   Ql + (c+1)*32, ICc, t);
            ld32a(ds + 2*2*BUF_E, Kh + (c+1)*32, ICc, t);
            ld32a(ds + 2*3*BUF_E, Kl + (c+1)*32, ICc, t);
            CP_COMMIT();
            CP_WAIT1();
        } else {
            CP_WAIT0();
        }
        __syncthreads();
        const __nv_bfloat16* st = dsm + (c & 1) * STAGE_E;
        gemm_chunk(st, st + BUF_E, st + 2*BUF_E, st + 3*BUF_E, wm, wn, lane, acc);
        __syncthreads();
    }

    float* So = g_S + ((size_t)b*Np + q0) * Np + n0;
    const int r0 = wm*64 + (lane >> 2), cb = wn*64 + 2*(lane & 3);
#pragma unroll
    for (int i = 0; i < 4; i++)
#pragma unroll
        for (int j = 0; j < 8; j++) {
            *reinterpret_cast<float2*>(So + (size_t)(r0 + i*16) * Np + cb + j*8) =
                make_float2(acc[i][j][0], acc[i][j][1]);
            *reinterpret_cast<float2*>(So + (size_t)(r0 + i*16 + 8) * Np + cb + j*8) =
                make_float2(acc[i][j][2], acc[i][j][3]);
        }
}

// =====================================================================
// K3: row softmax -> P hi/lo
// =====================================================================
__global__ __launch_bounds__(256) void softmax_kernel()
{
    const int r = blockIdx.x, b = blockIdx.y, t = threadIdx.x;
    const float4* Sr = reinterpret_cast<const float4*>(g_S + ((size_t)b*Np + r) * Np);
    float4 v[4];
    float mx = -1e30f;
#pragma unroll
    for (int i = 0; i < 4; i++) {
        int idx = t + 256*i;
        if (idx < 784) {
            v[i] = Sr[idx];
            mx = fmaxf(mx, fmaxf(fmaxf(v[i].x, v[i].y), fmaxf(v[i].z, v[i].w)));
        }
    }
    __shared__ float rd[8], rd2[8];
    float m = mx;
#pragma unroll
    for (int o = 16; o; o >>= 1) m = fmaxf(m, __shfl_xor_sync(0xffffffffu, m, o));
    if ((t & 31) == 0) rd[t >> 5] = m;
    __syncthreads();
    m = rd[0];
#pragma unroll
    for (int w = 1; w < 8; w++) m = fmaxf(m, rd[w]);
    float s = 0.f;
#pragma unroll
    for (int i = 0; i < 4; i++) {
        int idx = t + 256*i;
        if (idx < 784) {
            v[i].x = __expf(v[i].x - m); v[i].y = __expf(v[i].y - m);
            v[i].z = __expf(v[i].z - m); v[i].w = __expf(v[i].w - m);
            s += (v[i].x + v[i].y) + (v[i].z + v[i].w);
        }
    }
#pragma unroll
    for (int o = 16; o; o >>= 1) s += __shfl_xor_sync(0xffffffffu, s, o);
    if ((t & 31) == 0) rd2[t >> 5] = s;
    __syncthreads();
    s = rd2[0];
#pragma unroll
    for (int w = 1; w < 8; w++) s += rd2[w];
    float inv = 1.0f / s;
    __nv_bfloat16* Ph = g_Ph + ((size_t)b*Np + r) * Np;
    __nv_bfloat16* Pl = g_Pl + ((size_t)b*Np + r) * Np;
#pragma unroll
    for (int i = 0; i < 4; i++) {
        int idx = t + 256*i;
        if (idx < 784) {
            __nv_bfloat16 h0,h1,h2,h3,l0,l1,l2,l3;
            bsplit(v[i].x*inv,h0,l0); bsplit(v[i].y*inv,h1,l1);
            bsplit(v[i].z*inv,h2,l2); bsplit(v[i].w*inv,h3,l3);
            *reinterpret_cast<uint2*>(Ph + 4*idx) = pk4b(h0,h1,h2,h3);
            *reinterpret_cast<uint2*>(Pl + 4*idx) = pk4b(l0,l1,l2,l3);
        } else if (idx < 800) {
            uint2 z = make_uint2(0u, 0u);
            *reinterpret_cast<uint2*>(Ph + 4*idx) = z;
            *reinterpret_cast<uint2*>(Pl + 4*idx) = z;
        }
    }
}

// =====================================================================
// K4: Y = P V, 128 threads, warp 64x64
// =====================================================================
__global__ __launch_bounds__(128, 2) void pv_kernel()
{
    extern __shared__ __nv_bfloat16 dsm[];
    const uint32_t sb = smem_u32(dsm);
    const int t = threadIdx.x, lane = t & 31, wid = t >> 5;
    const int wm = wid & 1, wn = (wid >> 1) & 1;
    const int q0 = blockIdx.x * 128, d0 = blockIdx.y * 128, b = blockIdx.z;
    const __nv_bfloat16* Ph = g_Ph + ((size_t)b*Np + q0) * Np;
    const __nv_bfloat16* Pl = g_Pl + ((size_t)b*Np + q0) * Np;
    const __nv_bfloat16* Vh = g_Vth + ((size_t)b*ICc + d0) * Np;
    const __nv_bfloat16* Vl = g_Vtl + ((size_t)b*ICc + d0) * Np;

    float acc[4][8][4] = {};
    constexpr int NC = Np / 32;

    {
        uint32_t d0s = sb;
        ld32a(d0s,             Ph, Np, t);
        ld32a(d0s + 2*BUF_E,   Pl, Np, t);
        ld32a(d0s + 2*2*BUF_E, Vh, Np, t);
        ld32a(d0s + 2*3*BUF_E, Vl, Np, t);
        CP_COMMIT();
    }
    for (int c = 0; c < NC; c++) {
        if (c + 1 < NC) {
            uint32_t ds = sb + ((c+1) & 1) * (2*STAGE_E);
            ld32a(ds,             Ph + (c+1)*32, Np, t);
            ld32a(ds + 2*BUF_E,   Pl + (c+1)*32, Np, t);
            ld32a(ds + 2*2*BUF_E, Vh + (c+1)*32, Np, t);
            ld32a(ds + 2*3*BUF_E, Vl + (c+1)*32, Np, t);
            CP_COMMIT();
            CP_WAIT1();
        } else {
            CP_WAIT0();
        }
        __syncthreads();
        const __nv_bfloat16* st = dsm + (c & 1) * STAGE_E;
        gemm_chunk(st, st + BUF_E, st + 2*BUF_E, st + 3*BUF_E, wm, wn, lane, acc);
        __syncthreads();
    }

    const int r0 = wm*64 + (lane >> 2), cb = wn*64 + 2*(lane & 3);
#pragma unroll
    for (int i = 0; i < 4; i++)
#pragma unroll
        for (int j = 0; j < 8; j++) {
            int gc = d0 + cb + j*8;
            {
                int gr = q0 + r0 + i*16;
                __nv_bfloat16 h0,h1,l0,l1;
                bsplit(acc[i][j][0], h0, l0); bsplit(acc[i][j][1], h1, l1);
                size_t off = ((size_t)b*Np + gr) * ICc + gc;
                *reinterpret_cast<uint32_t*>(g_Yh + off) = pkb2(h0, h1);
                *reinterpret_cast<uint32_t*>(g_Yl + off) = pkb2(l0, l1);
            }
            {
                int gr = q0 + r0 + i*16 + 8;
                __nv_bfloat16 h0,h1,l0,l1;
                bsplit(acc[i][j][2], h0, l0); bsplit(acc[i][j][3], h1, l1);
                size_t off = ((size_t)b*Np + gr) * ICc + gc;
                *reinterpret_cast<uint32_t*>(g_Yh + off) = pkb2(h0, h1);
                *reinterpret_cast<uint32_t*>(g_Yl + off) = pkb2(l0, l1);
            }
        }
}

// =====================================================================
// K5: Z = Wz Y^T + b, 128 threads, warp 64x64
// =====================================================================
__global__ __launch_bounds__(128, 2) void wz_mma_kernel(const float* __restrict__ wzb)
{
    extern __shared__ __nv_bfloat16 dsm[];
    const uint32_t sb = smem_u32(dsm);
    const int t = threadIdx.x, lane = t & 31, wid = t >> 5;
    const int wm = wid & 1, wn = (wid >> 1) & 1;
    const int c0 = blockIdx.x * 128, n0 = blockIdx.y * 128, b = blockIdx.z;
    const __nv_bfloat16* Ahp = g_wzh + (size_t)c0 * ICc;
    const __nv_bfloat16* Alp = g_wzl + (size_t)c0 * ICc;
    const __nv_bfloat16* Bhp = g_Yh + ((size_t)b*Np + n0) * ICc;
    const __nv_bfloat16* Blp = g_Yl + ((size_t)b*Np + n0) * ICc;

    float acc[4][8][4] = {};
    constexpr int NC = ICc / 32;

    {
        uint32_t d0 = sb;
        ld32a(d0,             Ahp, ICc, t);
        ld32a(d0 + 2*BUF_E,   Alp, ICc, t);
        ld32a(d0 + 2*2*BUF_E, Bhp, ICc, t);
        ld32a(d0 + 2*3*BUF_E, Blp, ICc, t);
        CP_COMMIT();
    }
    for (int c = 0; c < NC; c++) {
        if (c + 1 < NC) {
            uint32_t ds = sb + ((c+1) & 1) * (2*STAGE_E);
            ld32a(ds,             Ahp + (c+1)*32, ICc, t);
            ld32a(ds + 2*BUF_E,   Alp + (c+1)*32, ICc, t);
            ld32a(ds + 2*2*BUF_E, Bhp + (c+1)*32, ICc, t);
            ld32a(ds + 2*3*BUF_E, Blp + (c+1)*32, ICc, t);
            CP_COMMIT();
            CP_WAIT1();
        } else {
            CP_WAIT0();
        }
        __syncthreads();
        const __nv_bfloat16* st = dsm + (c & 1) * STAGE_E;
        gemm_chunk(st, st + BUF_E, st + 2*BUF_E, st + 3*BUF_E, wm, wn, lane, acc);
        __syncthreads();
    }

    float* Zb = g_Z + (size_t)b * Cc * Nn;
    const int r0 = c0 + wm*64 + (lane >> 2), cb = wn*64 + 2*(lane & 3);
#pragma unroll
    for (int i = 0; i < 4; i++) {
        float wb0 = wzb[r0 + i*16], wb1 = wzb[r0 + i*16 + 8];
#pragma unroll
        for (int j = 0; j < 8; j++) {
            int gn = n0 + cb + j*8;
            if (gn < Nn) {
                *reinterpret_cast<float2*>(Zb + (size_t)(r0 + i*16) * Nn + gn) =
                    make_float2(acc[i][j][0] + wb0, acc[i][j][1] + wb0);
                *reinterpret_cast<float2*>(Zb + (size_t)(r0 + i*16 + 8) * Nn + gn) =
                    make_float2(acc[i][j][2] + wb1, acc[i][j][3] + wb1);
            }
        }
    }
}

// =====================================================================
// K6: BN stats ; K7: final elementwise
// =====================================================================
__global__ __launch_bounds__(256) void bnstats_kernel(
    const float* __restrict__ bnw, const float* __restrict__ bnb)
{
    const int c = blockIdx.x, t = threadIdx.x;
    float s = 0.f, q = 0.f;
    for (int b = 0; b < Bb; b++) {
        const float4* row = reinterpret_cast<const float4*>(g_Z + ((size_t)b*Cc + c) * Nn);
        for (int n4 = t; n4 < Nn/4; n4 += 256) {
            float4 v = row[n4];
            s += (v.x+v.y)+(v.z+v.w);
            q += (v.x*v.x+v.y*v.y)+(v.z*v.z+v.w*v.w);
        }
    }
    __shared__ float ss[256], qs[256];
    ss[t] = s; qs[t] = q;
    __syncthreads();
    for (int o = 128; o > 0; o >>= 1) {
        if (t < o) { ss[t] += ss[t+o]; qs[t] += qs[t+o]; }
        __syncthreads();
    }
    if (t == 0) {
        const float inv_n = 1.0f / (float)(Bb * Nn);
        float mean = ss[0]*inv_n, var = qs[0]*inv_n - mean*mean;
        float sc = bnw[c] * rsqrtf(var + 1e-5f);
        g_scaleC[c] = sc;
        g_shiftC[c] = bnb[c] - mean*sc;
    }
}

__global__ __launch_bounds__(256) void final_kernel(
    const float* __restrict__ x, float* __restrict__ out)
{
    int i = blockIdx.x * 256 + threadIdx.x;
    int c = (i / (Nn/4)) & (Cc-1);
    float sc = g_scaleC[c], sh = g_shiftC[c];
    float4 z = reinterpret_cast<const float4*>(g_Z)[i];
    float4 xv = reinterpret_cast<const float4*>(x)[i];
    float4 o;
    o.x = fmaf(z.x, sc, sh) + xv.x; o.y = fmaf(z.y, sc, sh) + xv.y;
    o.z = fmaf(z.z, sc, sh) + xv.z; o.w = fmaf(z.w, sc, sh) + xv.w;
    reinterpret_cast<float4*>(out)[i] = o;
}

// =====================================================================
extern "C" void kernel_launch(void* const* d_in, const int* in_sizes, int n_in,
                              void* d_out, int out_size)
{
    (void)in_sizes; (void)n_in; (void)out_size;
    const float* x   = (const float*)d_in[0];
    const float* thw = (const float*)d_in[1];
    const float* thb = (const float*)d_in[2];
    const float* phw = (const float*)d_in[3];
    const float* phb = (const float*)d_in[4];
    const float* gw  = (const float*)d_in[5];
    const float* gbb = (const float*)d_in[6];
    const float* wzw = (const float*)d_in[7];
    const float* wzb = (const float*)d_in[8];
    const float* bnw = (const float*)d_in[9];
    const float* bnb = (const float*)d_in[10];
    float* out = (float*)d_out;

    cudaFuncSetAttribute(qkv_mma_kernel, cudaFuncAttributeMaxDynamicSharedMemorySize, QKV_SMEM);
    cudaFuncSetAttribute(sgemm_kernel,   cudaFuncAttributeMaxDynamicSharedMemorySize, GEMM_SMEM);
    cudaFuncSetAttribute(pv_kernel,      cudaFuncAttributeMaxDynamicSharedMemorySize, GEMM_SMEM);
    cudaFuncSetAttribute(wz_mma_kernel,  cudaFuncAttributeMaxDynamicSharedMemorySize, GEMM_SMEM);

    splitx_kernel<<<Bb*Cc, 256>>>(x);
    splitw_kernel<<<512, 256>>>(thw, phw, gw, wzw);
    qkv_mma_kernel<<<dim3(Np/128, 6, Bb), 128, QKV_SMEM>>>(thb, phb, gbb);
    sgemm_kernel<<<dim3(Np/128, Np/128, Bb), 128, GEMM_SMEM>>>();
    softmax_kernel<<<dim3(Nn, Bb), 256>>>();
    pv_kernel<<<dim3(Np/128, ICc/128, Bb), 128, GEMM_SMEM>>>();
    wz_mma_kernel<<<dim3(Cc/128, Np/128, Bb), 128, GEMM_SMEM>>>(wzb);
    bnstats_kernel<<<Cc, 256>>>(bnw, bnb);
    final_kernel<<<(Bb*Cc*Nn/4)/256, 256>>>(x, out);
}

// round 10
// speedup vs baseline: 3.0853x; 1.1326x over previous
#include <cuda_runtime.h>
#include <cuda_bf16.h>
#include <math.h>
#include <cstdint>

constexpr int Bb  = 8;
constexpr int Cc  = 512;
constexpr int Nn  = 3136;
constexpr int ICc = 256;
constexpr int Np  = 3200;   // 25*128

// ---------------- scratch ----------------
__device__ __align__(256) __nv_bfloat16 g_xh[Bb*Cc*Np];
__device__ __align__(256) __nv_bfloat16 g_xl[Bb*Cc*Np];
__device__ __align__(256) __nv_bfloat16 g_wh[3*ICc*Cc];
__device__ __align__(256) __nv_bfloat16 g_wl[3*ICc*Cc];
__device__ __align__(256) __nv_bfloat16 g_wzh[Cc*ICc];
__device__ __align__(256) __nv_bfloat16 g_wzl[Cc*ICc];   // written by splitw; unused by wz 2-pass
__device__ __align__(256) __nv_bfloat16 g_Qh[Bb*Np*ICc];
__device__ __align__(256) __nv_bfloat16 g_Ql[Bb*Np*ICc];
__device__ __align__(256) __nv_bfloat16 g_Kh[Bb*Np*ICc];
__device__ __align__(256) __nv_bfloat16 g_Kl[Bb*Np*ICc];
__device__ __align__(256) __nv_bfloat16 g_Vth[Bb*ICc*Np];   // [b][d][n]
__device__ __align__(256) __nv_bfloat16 g_Vtl[Bb*ICc*Np];
__device__ __align__(256) float         g_S [(size_t)Bb*Np*Np];
__device__ __align__(256) __nv_bfloat16 g_Ph[(size_t)Bb*Np*Np];
__device__ __align__(256) __nv_bfloat16 g_Yh[Bb*Np*ICc];    // [b][n][ic]
__device__ __align__(256) __nv_bfloat16 g_Yl[Bb*Np*ICc];
__device__ __align__(256) float g_Z[Bb*Cc*Nn];              // [b][c][n]
__device__ float g_scaleC[Cc];
__device__ float g_shiftC[Cc];

// ---------------- helpers ----------------
__device__ __forceinline__ uint32_t smem_u32(const void* p) {
    uint32_t a;
    asm("{ .reg .u64 t; cvta.to.shared.u64 t, %1; cvt.u32.u64 %0, t; }" : "=r"(a) : "l"(p));
    return a;
}
__device__ __forceinline__ void ldsm_x4(uint32_t* r, uint32_t addr) {
    asm volatile("ldmatrix.sync.aligned.m8n8.x4.shared.b16 {%0,%1,%2,%3}, [%4];"
                 : "=r"(r[0]), "=r"(r[1]), "=r"(r[2]), "=r"(r[3]) : "r"(addr));
}
__device__ __forceinline__ void ldsm_x4_t(uint32_t* r, uint32_t addr) {
    asm volatile("ldmatrix.sync.aligned.m8n8.x4.trans.shared.b16 {%0,%1,%2,%3}, [%4];"
                 : "=r"(r[0]), "=r"(r[1]), "=r"(r[2]), "=r"(r[3]) : "r"(addr));
}
__device__ __forceinline__ void mma_bf16(float* d, const uint32_t* a, const uint32_t* b) {
    asm volatile("mma.sync.aligned.m16n8k16.row.col.f32.bf16.bf16.f32 "
                 "{%0,%1,%2,%3}, {%4,%5,%6,%7}, {%8,%9}, {%0,%1,%2,%3};"
                 : "+f"(d[0]), "+f"(d[1]), "+f"(d[2]), "+f"(d[3])
                 : "r"(a[0]), "r"(a[1]), "r"(a[2]), "r"(a[3]), "r"(b[0]), "r"(b[1]));
}
#define CP16(sm, gp)  asm volatile("cp.async.ca.shared.global [%0], [%1], 16;" :: "r"(sm), "l"(gp) : "memory")
#define CP_COMMIT()   asm volatile("cp.async.commit_group;" ::: "memory")
#define CP_WAIT1()    asm volatile("cp.async.wait_group 1;" ::: "memory")
#define CP_WAIT0()    asm volatile("cp.async.wait_group 0;" ::: "memory")

__device__ __forceinline__ void bsplit(float v, __nv_bfloat16& h, __nv_bfloat16& l) {
    h = __float2bfloat16(v);
    l = __float2bfloat16(v - __bfloat162float(h));
}
__device__ __forceinline__ uint32_t pkb2(__nv_bfloat16 a, __nv_bfloat16 b) {
    __nv_bfloat162 p = __halves2bfloat162(a, b);
    return *reinterpret_cast<unsigned int*>(&p);
}
__device__ __forceinline__ uint2 pk4b(__nv_bfloat16 a, __nv_bfloat16 b, __nv_bfloat16 c, __nv_bfloat16 d) {
    return make_uint2(pkb2(a, b), pkb2(c, d));
}

constexpr int TSTR = 40;                    // [rows][k32] tiles
constexpr int BUF_E = 128 * TSTR;
constexpr int STAGE_E = 4 * BUF_E;
constexpr int GEMM_SMEM = 2 * STAGE_E * 2;  // 81920 B (sgemm, 4-buffer stages)
constexpr int STAGE3_E = 3 * BUF_E;
constexpr int GEMM3_SMEM = 2 * STAGE3_E * 2; // 61440 B (pv/wz, 3-buffer stages)

constexpr int XSTR = 136;                   // x-tile [k32][n128]
constexpr int XBUF = 32 * XSTR;
constexpr int WBUF = 128 * TSTR;
constexpr int QSTAGE = 2 * XBUF + 2 * WBUF;
constexpr int QKV_SMEM = 2 * QSTAGE * 2;    // 75776 B (>= 128*129*4 V stage)

// async: [128 rows][32 cols] bf16 row-major -> smem [128][TSTR]  (128 threads)
__device__ __forceinline__ void ld32a(uint32_t dsm, const __nv_bfloat16* src, int ldg, int t) {
#pragma unroll
    for (int i = 0; i < 4; i++) {
        int u = t + 128 * i, row = u >> 2, cq = u & 3;
        CP16(dsm + row * (TSTR * 2) + cq * 16, src + (size_t)row * ldg + cq * 8);
    }
}
// async: x chunk [32 c-rows][128 n-cols] -> smem [32][XSTR]  (128 threads)
__device__ __forceinline__ void ldxa(uint32_t dsm, const __nv_bfloat16* src, int t) {
#pragma unroll
    for (int i = 0; i < 4; i++) {
        int u = t + 128 * i, row = u >> 4, cq = u & 15;
        CP16(dsm + row * (XSTR * 2) + cq * 16, src + (size_t)row * Np + cq * 8);
    }
}

// 32-k chunk, warp tile 64x64, 3-pass split (S path).
__device__ __forceinline__ void gemm_chunk(
    const __nv_bfloat16* Ah, const __nv_bfloat16* Al,
    const __nv_bfloat16* Bh, const __nv_bfloat16* Bl,
    int wm, int wn, int lane, float acc[4][8][4])
{
    const int lr = lane & 15, lc = lane >> 4;
#pragma unroll
    for (int kk = 0; kk < 32; kk += 16) {
        uint32_t ah[4][4], al[4][4], bh[8][2], bl[8][2];
#pragma unroll
        for (int i = 0; i < 4; i++) {
            ldsm_x4(ah[i], smem_u32(Ah + (wm*64 + i*16 + lr) * TSTR + kk + lc*8));
            ldsm_x4(al[i], smem_u32(Al + (wm*64 + i*16 + lr) * TSTR + kk + lc*8));
        }
#pragma unroll
        for (int jp = 0; jp < 4; jp++) {
            uint32_t r[4];
            ldsm_x4(r, smem_u32(Bh + (wn*64 + jp*16 + lr) * TSTR + kk + lc*8));
            bh[2*jp][0] = r[0]; bh[2*jp][1] = r[2];
            bh[2*jp+1][0] = r[1]; bh[2*jp+1][1] = r[3];
            ldsm_x4(r, smem_u32(Bl + (wn*64 + jp*16 + lr) * TSTR + kk + lc*8));
            bl[2*jp][0] = r[0]; bl[2*jp][1] = r[2];
            bl[2*jp+1][0] = r[1]; bl[2*jp+1][1] = r[3];
        }
#pragma unroll
        for (int i = 0; i < 4; i++)
#pragma unroll
            for (int j = 0; j < 8; j++) {
                mma_bf16(acc[i][j], ah[i], bh[j]);
                mma_bf16(acc[i][j], ah[i], bl[j]);
                mma_bf16(acc[i][j], al[i], bh[j]);
            }
    }
}

// 2-pass variant (linear path): acc += Ah*(Bh + Bl)
__device__ __forceinline__ void gemm_chunk2(
    const __nv_bfloat16* Ah,
    const __nv_bfloat16* Bh, const __nv_bfloat16* Bl,
    int wm, int wn, int lane, float acc[4][8][4])
{
    const int lr = lane & 15, lc = lane >> 4;
#pragma unroll
    for (int kk = 0; kk < 32; kk += 16) {
        uint32_t ah[4][4], bh[8][2], bl[8][2];
#pragma unroll
        for (int i = 0; i < 4; i++)
            ldsm_x4(ah[i], smem_u32(Ah + (wm*64 + i*16 + lr) * TSTR + kk + lc*8));
#pragma unroll
        for (int jp = 0; jp < 4; jp++) {
            uint32_t r[4];
            ldsm_x4(r, smem_u32(Bh + (wn*64 + jp*16 + lr) * TSTR + kk + lc*8));
            bh[2*jp][0] = r[0]; bh[2*jp][1] = r[2];
            bh[2*jp+1][0] = r[1]; bh[2*jp+1][1] = r[3];
            ldsm_x4(r, smem_u32(Bl + (wn*64 + jp*16 + lr) * TSTR + kk + lc*8));
            bl[2*jp][0] = r[0]; bl[2*jp][1] = r[2];
            bl[2*jp+1][0] = r[1]; bl[2*jp+1][1] = r[3];
        }
#pragma unroll
        for (int i = 0; i < 4; i++)
#pragma unroll
            for (int j = 0; j < 8; j++) {
                mma_bf16(acc[i][j], ah[i], bh[j]);
                mma_bf16(acc[i][j], ah[i], bl[j]);
            }
    }
}

// qkv 3-pass (A col-major via trans ldsm)
__device__ __forceinline__ void gemm_chunk_qkv3(
    const __nv_bfloat16* Xh, const __nv_bfloat16* Xl,
    const __nv_bfloat16* Wh, const __nv_bfloat16* Wl,
    int wm, int wn, int lane, float acc[4][8][4])
{
    const int lr = lane & 15, lc = lane >> 4;
    const int kr = (lane & 7) + ((lane >> 4) << 3);
    const int mo = ((lane >> 3) & 1) << 3;
#pragma unroll
    for (int kk = 0; kk < 32; kk += 16) {
        uint32_t ah[4][4], al[4][4], bh[8][2], bl[8][2];
#pragma unroll
        for (int i = 0; i < 4; i++) {
            ldsm_x4_t(ah[i], smem_u32(Xh + (kk + kr) * XSTR + wm*64 + i*16 + mo));
            ldsm_x4_t(al[i], smem_u32(Xl + (kk + kr) * XSTR + wm*64 + i*16 + mo));
        }
#pragma unroll
        for (int jp = 0; jp < 4; jp++) {
            uint32_t r[4];
            ldsm_x4(r, smem_u32(Wh + (wn*64 + jp*16 + lr) * TSTR + kk + lc*8));
            bh[2*jp][0] = r[0]; bh[2*jp][1] = r[2];
            bh[2*jp+1][0] = r[1]; bh[2*jp+1][1] = r[3];
            ldsm_x4(r, smem_u32(Wl + (wn*64 + jp*16 + lr) * TSTR + kk + lc*8));
            bl[2*jp][0] = r[0]; bl[2*jp][1] = r[2];
            bl[2*jp+1][0] = r[1]; bl[2*jp+1][1] = r[3];
        }
#pragma unroll
        for (int i = 0; i < 4; i++)
#pragma unroll
            for (int j = 0; j < 8; j++) {
                mma_bf16(acc[i][j], ah[i], bh[j]);
                mma_bf16(acc[i][j], ah[i], bl[j]);
                mma_bf16(acc[i][j], al[i], bh[j]);
            }
    }
}

// qkv 2-pass (V path): acc += Xh*(Wh + Wl)
__device__ __forceinline__ void gemm_chunk_qkv2(
    const __nv_bfloat16* Xh,
    const __nv_bfloat16* Wh, const __nv_bfloat16* Wl,
    int wm, int wn, int lane, float acc[4][8][4])
{
    const int lr = lane & 15, lc = lane >> 4;
    const int kr = (lane & 7) + ((lane >> 4) << 3);
    const int mo = ((lane >> 3) & 1) << 3;
#pragma unroll
    for (int kk = 0; kk < 32; kk += 16) {
        uint32_t ah[4][4], bh[8][2], bl[8][2];
#pragma unroll
        for (int i = 0; i < 4; i++)
            ldsm_x4_t(ah[i], smem_u32(Xh + (kk + kr) * XSTR + wm*64 + i*16 + mo));
#pragma unroll
        for (int jp = 0; jp < 4; jp++) {
            uint32_t r[4];
            ldsm_x4(r, smem_u32(Wh + (wn*64 + jp*16 + lr) * TSTR + kk + lc*8));
            bh[2*jp][0] = r[0]; bh[2*jp][1] = r[2];
            bh[2*jp+1][0] = r[1]; bh[2*jp+1][1] = r[3];
            ldsm_x4(r, smem_u32(Wl + (wn*64 + jp*16 + lr) * TSTR + kk + lc*8));
            bl[2*jp][0] = r[0]; bl[2*jp][1] = r[2];
            bl[2*jp+1][0] = r[1]; bl[2*jp+1][1] = r[3];
        }
#pragma unroll
        for (int i = 0; i < 4; i++)
#pragma unroll
            for (int j = 0; j < 8; j++) {
                mma_bf16(acc[i][j], ah[i], bh[j]);
                mma_bf16(acc[i][j], ah[i], bl[j]);
            }
    }
}

// =====================================================================
// K0a: split x ; K0b: split weights
// =====================================================================
__global__ __launch_bounds__(256) void splitx_kernel(const float* __restrict__ x)
{
    const int row = blockIdx.x, t = threadIdx.x;
    const float4* src = reinterpret_cast<const float4*>(x + (size_t)row * Nn);
    __nv_bfloat16* dh = g_xh + (size_t)row * Np;
    __nv_bfloat16* dl = g_xl + (size_t)row * Np;
    for (int n4 = t; n4 < Nn/4; n4 += 256) {
        float4 v = src[n4];
        __nv_bfloat16 h0,h1,h2,h3,l0,l1,l2,l3;
        bsplit(v.x,h0,l0); bsplit(v.y,h1,l1); bsplit(v.z,h2,l2); bsplit(v.w,h3,l3);
        *reinterpret_cast<uint2*>(dh + 4*n4) = pk4b(h0,h1,h2,h3);
        *reinterpret_cast<uint2*>(dl + 4*n4) = pk4b(l0,l1,l2,l3);
    }
}

__global__ __launch_bounds__(256) void splitw_kernel(
    const float* __restrict__ thw, const float* __restrict__ phw,
    const float* __restrict__ gw,  const float* __restrict__ wzw)
{
    int idx = blockIdx.x * 256 + threadIdx.x;
    int a = idx >> 15, off = idx & 32767;
    const float* src = (a == 0) ? thw : (a == 1) ? phw : (a == 2) ? gw : wzw;
    __nv_bfloat16* dh = (a < 3) ? g_wh + (size_t)a * ICc * Cc : g_wzh;
    __nv_bfloat16* dl = (a < 3) ? g_wl + (size_t)a * ICc * Cc : g_wzl;
    float4 v = reinterpret_cast<const float4*>(src)[off];
    __nv_bfloat16 h0,h1,h2,h3,l0,l1,l2,l3;
    bsplit(v.x,h0,l0); bsplit(v.y,h1,l1); bsplit(v.z,h2,l2); bsplit(v.w,h3,l3);
    *reinterpret_cast<uint2*>(dh + 4*off) = pk4b(h0,h1,h2,h3);
    *reinterpret_cast<uint2*>(dl + 4*off) = pk4b(l0,l1,l2,l3);
}

// =====================================================================
// K1: QKV via mma, 128 threads, warp 64x64. Q/K 3-pass; V 2-pass.
// =====================================================================
__global__ __launch_bounds__(128, 2) void qkv_mma_kernel(
    const float* __restrict__ thb, const float* __restrict__ phb,
    const float* __restrict__ gb)
{
    extern __shared__ __nv_bfloat16 dsm[];
    const uint32_t sb = smem_u32(dsm);
    const int t = threadIdx.x, lane = t & 31, wid = t >> 5;
    const int wm = wid & 1, wn = (wid >> 1) & 1;
    const int nt = blockIdx.x, w = blockIdx.y >> 1, it = blockIdx.y & 1, b = blockIdx.z;
    const int n0 = nt * 128, i0 = it * 128;

    const __nv_bfloat16* Xh = g_xh + (size_t)b * Cc * Np + n0;
    const __nv_bfloat16* Xl = g_xl + (size_t)b * Cc * Np + n0;
    const __nv_bfloat16* Wh = g_wh + (size_t)w * ICc * Cc + (size_t)i0 * Cc;
    const __nv_bfloat16* Wl = g_wl + (size_t)w * ICc * Cc + (size_t)i0 * Cc;

    float acc[4][8][4] = {};
    constexpr int NC = Cc / 32;  // 16

    {
        uint32_t d0 = sb;
        ldxa(d0, Xh, t);
        ldxa(d0 + 2*XBUF, Xl, t);
        ld32a(d0 + 2*2*XBUF, Wh, Cc, t);
        ld32a(d0 + 2*2*XBUF + 2*WBUF, Wl, Cc, t);
        CP_COMMIT();
    }
    for (int c = 0; c < NC; c++) {
        if (c + 1 < NC) {
            uint32_t ds = sb + ((c+1) & 1) * (2*QSTAGE);
            ldxa(ds,                      Xh + (size_t)(c+1)*32*Np, t);
            ldxa(ds + 2*XBUF,             Xl + (size_t)(c+1)*32*Np, t);
            ld32a(ds + 2*2*XBUF,          Wh + (c+1)*32, Cc, t);
            ld32a(ds + 2*2*XBUF + 2*WBUF, Wl + (c+1)*32, Cc, t);
            CP_COMMIT();
            CP_WAIT1();
        } else {
            CP_WAIT0();
        }
        __syncthreads();
        const __nv_bfloat16* st = dsm + (c & 1) * QSTAGE;
        if (w < 2)
            gemm_chunk_qkv3(st, st + XBUF, st + 2*XBUF, st + 2*XBUF + WBUF, wm, wn, lane, acc);
        else
            gemm_chunk_qkv2(st, st + 2*XBUF, st + 2*XBUF + WBUF, wm, wn, lane, acc);
        __syncthreads();
    }

    const float* bias = (w == 0) ? thb : (w == 1) ? phb : gb;
    const int lr4 = lane >> 2, cb = wn*64 + 2*(lane & 3);

    if (w < 2) {
        __nv_bfloat16* dh = (w == 0) ? g_Qh : g_Kh;
        __nv_bfloat16* dl = (w == 0) ? g_Ql : g_Kl;
#pragma unroll
        for (int i = 0; i < 4; i++)
#pragma unroll
            for (int j = 0; j < 8; j++) {
                int gc = i0 + cb + j*8;
                float b0v = bias[gc], b1v = bias[gc+1];
                int gr = n0 + wm*64 + i*16 + lr4;
                if (gr < Nn) {
                    __nv_bfloat16 h0,h1,l0,l1;
                    bsplit(acc[i][j][0] + b0v, h0, l0);
                    bsplit(acc[i][j][1] + b1v, h1, l1);
                    size_t off = ((size_t)b*Np + gr) * ICc + gc;
                    *reinterpret_cast<uint32_t*>(dh + off) = pkb2(h0, h1);
                    *reinterpret_cast<uint32_t*>(dl + off) = pkb2(l0, l1);
                }
                if (gr + 8 < Nn) {
                    __nv_bfloat16 h0,h1,l0,l1;
                    bsplit(acc[i][j][2] + b0v, h0, l0);
                    bsplit(acc[i][j][3] + b1v, h1, l1);
                    size_t off = ((size_t)b*Np + gr + 8) * ICc + gc;
                    *reinterpret_cast<uint32_t*>(dh + off) = pkb2(h0, h1);
                    *reinterpret_cast<uint32_t*>(dl + off) = pkb2(l0, l1);
                }
            }
    } else {
        // V: stage [n][i] fp32, then write transposed [i][n] hi/lo
        float* stg = reinterpret_cast<float*>(dsm);
        __syncthreads();
#pragma unroll
        for (int i = 0; i < 4; i++)
#pragma unroll
            for (int j = 0; j < 8; j++) {
                int ic = cb + j*8;
                float b0v = bias[i0 + ic], b1v = bias[i0 + ic + 1];
                int nl = wm*64 + i*16 + lr4;
                stg[nl*129 + ic]       = acc[i][j][0] + b0v;
                stg[nl*129 + ic + 1]   = acc[i][j][1] + b1v;
                stg[(nl+8)*129 + ic]   = acc[i][j][2] + b0v;
                stg[(nl+8)*129 + ic+1] = acc[i][j][3] + b1v;
            }
        __syncthreads();
#pragma unroll
        for (int k = 0; k < 64; k++) {
            int u = t + 128*k;
            int ir = u >> 6, np2 = u & 63;
            int gn = n0 + 2*np2;
            if (gn < Nn) {
                float v0 = stg[(2*np2)*129 + ir], v1 = stg[(2*np2+1)*129 + ir];
                __nv_bfloat16 h0,h1,l0,l1;
                bsplit(v0, h0, l0); bsplit(v1, h1, l1);
                size_t off = ((size_t)b*ICc + i0 + ir) * Np + gn;
                *reinterpret_cast<uint32_t*>(g_Vth + off) = pkb2(h0, h1);
                *reinterpret_cast<uint32_t*>(g_Vtl + off) = pkb2(l0, l1);
            }
        }
    }
}

// =====================================================================
// K2: S = Q K^T, 3-pass (unchanged — at HMMA roofline)
// =====================================================================
__global__ __launch_bounds__(128, 2) void sgemm_kernel()
{
    extern __shared__ __nv_bfloat16 dsm[];
    const uint32_t sb = smem_u32(dsm);
    const int t = threadIdx.x, lane = t & 31, wid = t >> 5;
    const int wm = wid & 1, wn = (wid >> 1) & 1;
    const int q0 = blockIdx.x * 128, n0 = blockIdx.y * 128, b = blockIdx.z;
    const __nv_bfloat16* Qh = g_Qh + ((size_t)b*Np + q0) * ICc;
    const __nv_bfloat16* Ql = g_Ql + ((size_t)b*Np + q0) * ICc;
    const __nv_bfloat16* Kh = g_Kh + ((size_t)b*Np + n0) * ICc;
    const __nv_bfloat16* Kl = g_Kl + ((size_t)b*Np + n0) * ICc;

    float acc[4][8][4] = {};
    constexpr int NC = ICc / 32;

    {
        uint32_t d0 = sb;
        ld32a(d0,             Qh, ICc, t);
        ld32a(d0 + 2*BUF_E,   Ql, ICc, t);
        ld32a(d0 + 2*2*BUF_E, Kh, ICc, t);
        ld32a(d0 + 2*3*BUF_E, Kl, ICc, t);
        CP_COMMIT();
    }
    for (int c = 0; c < NC; c++) {
        if (c + 1 < NC) {
            uint32_t ds = sb + ((c+1) & 1) * (2*STAGE_E);
            ld32a(ds,             Qh + (c+1)*32, ICc, t);
            ld32a(ds + 2*BUF_E,   Ql + (c+1)*32, ICc, t);
            ld32a(ds + 2*2*BUF_E, Kh + (c+1)*32, ICc, t);
            ld32a(ds + 2*3*BUF_E, Kl + (c+1)*32, ICc, t);
            CP_COMMIT();
            CP_WAIT1();
        } else {
            CP_WAIT0();
        }
        __syncthreads();
        const __nv_bfloat16* st = dsm + (c & 1) * STAGE_E;
        gemm_chunk(st, st + BUF_E, st + 2*BUF_E, st + 3*BUF_E, wm, wn, lane, acc);
        __syncthreads();
    }

    float* So = g_S + ((size_t)b*Np + q0) * Np + n0;
    const int r0 = wm*64 + (lane >> 2), cb = wn*64 + 2*(lane & 3);
#pragma unroll
    for (int i = 0; i < 4; i++)
#pragma unroll
        for (int j = 0; j < 8; j++) {
            *reinterpret_cast<float2*>(So + (size_t)(r0 + i*16) * Np + cb + j*8) =
                make_float2(acc[i][j][0], acc[i][j][1]);
            *reinterpret_cast<float2*>(So + (size_t)(r0 + i*16 + 8) * Np + cb + j*8) =
                make_float2(acc[i][j][2], acc[i][j][3]);
        }
}

// =====================================================================
// K3: row softmax -> Ph only (no lo split)
// =====================================================================
__global__ __launch_bounds__(256) void softmax_kernel()
{
    const int r = blockIdx.x, b = blockIdx.y, t = threadIdx.x;
    const float4* Sr = reinterpret_cast<const float4*>(g_S + ((size_t)b*Np + r) * Np);
    float4 v[4];
    float mx = -1e30f;
#pragma unroll
    for (int i = 0; i < 4; i++) {
        int idx = t + 256*i;
        if (idx < 784) {
            v[i] = Sr[idx];
            mx = fmaxf(mx, fmaxf(fmaxf(v[i].x, v[i].y), fmaxf(v[i].z, v[i].w)));
        }
    }
    __shared__ float rd[8], rd2[8];
    float m = mx;
#pragma unroll
    for (int o = 16; o; o >>= 1) m = fmaxf(m, __shfl_xor_sync(0xffffffffu, m, o));
    if ((t & 31) == 0) rd[t >> 5] = m;
    __syncthreads();
    m = rd[0];
#pragma unroll
    for (int w = 1; w < 8; w++) m = fmaxf(m, rd[w]);
    float s = 0.f;
#pragma unroll
    for (int i = 0; i < 4; i++) {
        int idx = t + 256*i;
        if (idx < 784) {
            v[i].x = __expf(v[i].x - m); v[i].y = __expf(v[i].y - m);
            v[i].z = __expf(v[i].z - m); v[i].w = __expf(v[i].w - m);
            s += (v[i].x + v[i].y) + (v[i].z + v[i].w);
        }
    }
#pragma unroll
    for (int o = 16; o; o >>= 1) s += __shfl_xor_sync(0xffffffffu, s, o);
    if ((t & 31) == 0) rd2[t >> 5] = s;
    __syncthreads();
    s = rd2[0];
#pragma unroll
    for (int w = 1; w < 8; w++) s += rd2[w];
    float inv = 1.0f / s;
    __nv_bfloat16* Ph = g_Ph + ((size_t)b*Np + r) * Np;
#pragma unroll
    for (int i = 0; i < 4; i++) {
        int idx = t + 256*i;
        if (idx < 784) {
            *reinterpret_cast<uint2*>(Ph + 4*idx) =
                pk4b(__float2bfloat16(v[i].x*inv), __float2bfloat16(v[i].y*inv),
                     __float2bfloat16(v[i].z*inv), __float2bfloat16(v[i].w*inv));
        } else if (idx < 800) {
            *reinterpret_cast<uint2*>(Ph + 4*idx) = make_uint2(0u, 0u);
        }
    }
}

// =====================================================================
// K4: Y = P V, 2-pass (Ph·Vh + Ph·Vl), 3 buffers, NC=98
// =====================================================================
__global__ __launch_bounds__(128, 2) void pv_kernel()
{
    extern __shared__ __nv_bfloat16 dsm[];
    const uint32_t sb = smem_u32(dsm);
    const int t = threadIdx.x, lane = t & 31, wid = t >> 5;
    const int wm = wid & 1, wn = (wid >> 1) & 1;
    const int q0 = blockIdx.x * 128, d0 = blockIdx.y * 128, b = blockIdx.z;
    const __nv_bfloat16* Ph = g_Ph + ((size_t)b*Np + q0) * Np;
    const __nv_bfloat16* Vh = g_Vth + ((size_t)b*ICc + d0) * Np;
    const __nv_bfloat16* Vl = g_Vtl + ((size_t)b*ICc + d0) * Np;

    float acc[4][8][4] = {};
    constexpr int NC = Nn / 32;  // 98 (skip zero pads)

    {
        uint32_t d0s = sb;
        ld32a(d0s,             Ph, Np, t);
        ld32a(d0s + 2*BUF_E,   Vh, Np, t);
        ld32a(d0s + 2*2*BUF_E, Vl, Np, t);
        CP_COMMIT();
    }
    for (int c = 0; c < NC; c++) {
        if (c + 1 < NC) {
            uint32_t ds = sb + ((c+1) & 1) * (2*STAGE3_E);
            ld32a(ds,             Ph + (c+1)*32, Np, t);
            ld32a(ds + 2*BUF_E,   Vh + (c+1)*32, Np, t);
            ld32a(ds + 2*2*BUF_E, Vl + (c+1)*32, Np, t);
            CP_COMMIT();
            CP_WAIT1();
        } else {
            CP_WAIT0();
        }
        __syncthreads();
        const __nv_bfloat16* st = dsm + (c & 1) * STAGE3_E;
        gemm_chunk2(st, st + BUF_E, st + 2*BUF_E, wm, wn, lane, acc);
        __syncthreads();
    }

    const int r0 = wm*64 + (lane >> 2), cb = wn*64 + 2*(lane & 3);
#pragma unroll
    for (int i = 0; i < 4; i++)
#pragma unroll
        for (int j = 0; j < 8; j++) {
            int gc = d0 + cb + j*8;
            {
                int gr = q0 + r0 + i*16;
                __nv_bfloat16 h0,h1,l0,l1;
                bsplit(acc[i][j][0], h0, l0); bsplit(acc[i][j][1], h1, l1);
                size_t off = ((size_t)b*Np + gr) * ICc + gc;
                *reinterpret_cast<uint32_t*>(g_Yh + off) = pkb2(h0, h1);
                *reinterpret_cast<uint32_t*>(g_Yl + off) = pkb2(l0, l1);
            }
            {
                int gr = q0 + r0 + i*16 + 8;
                __nv_bfloat16 h0,h1,l0,l1;
                bsplit(acc[i][j][2], h0, l0); bsplit(acc[i][j][3], h1, l1);
                size_t off = ((size_t)b*Np + gr) * ICc + gc;
                *reinterpret_cast<uint32_t*>(g_Yh + off) = pkb2(h0, h1);
                *reinterpret_cast<uint32_t*>(g_Yl + off) = pkb2(l0, l1);
            }
        }
}

// =====================================================================
// K5: Z = Wz Y^T + b, 2-pass (Wzh·Yh + Wzh·Yl), 3 buffers
// =====================================================================
__global__ __launch_bounds__(128, 2) void wz_mma_kernel(const float* __restrict__ wzb)
{
    extern __shared__ __nv_bfloat16 dsm[];
    const uint32_t sb = smem_u32(dsm);
    const int t = threadIdx.x, lane = t & 31, wid = t >> 5;
    const int wm = wid & 1, wn = (wid >> 1) & 1;
    const int c0 = blockIdx.x * 128, n0 = blockIdx.y * 128, b = blockIdx.z;
    const __nv_bfloat16* Ahp = g_wzh + (size_t)c0 * ICc;
    const __nv_bfloat16* Bhp = g_Yh + ((size_t)b*Np + n0) * ICc;
    const __nv_bfloat16* Blp = g_Yl + ((size_t)b*Np + n0) * ICc;

    float acc[4][8][4] = {};
    constexpr int NC = ICc / 32;

    {
        uint32_t d0 = sb;
        ld32a(d0,             Ahp, ICc, t);
        ld32a(d0 + 2*BUF_E,   Bhp, ICc, t);
        ld32a(d0 + 2*2*BUF_E, Blp, ICc, t);
        CP_COMMIT();
    }
    for (int c = 0; c < NC; c++) {
        if (c + 1 < NC) {
            uint32_t ds = sb + ((c+1) & 1) * (2*STAGE3_E);
            ld32a(ds,             Ahp + (c+1)*32, ICc, t);
            ld32a(ds + 2*BUF_E,   Bhp + (c+1)*32, ICc, t);
            ld32a(ds + 2*2*BUF_E, Blp + (c+1)*32, ICc, t);
            CP_COMMIT();
            CP_WAIT1();
        } else {
            CP_WAIT0();
        }
        __syncthreads();
        const __nv_bfloat16* st = dsm + (c & 1) * STAGE3_E;
        gemm_chunk2(st, st + BUF_E, st + 2*BUF_E, wm, wn, lane, acc);
        __syncthreads();
    }

    float* Zb = g_Z + (size_t)b * Cc * Nn;
    const int r0 = c0 + wm*64 + (lane >> 2), cb = wn*64 + 2*(lane & 3);
#pragma unroll
    for (int i = 0; i < 4; i++) {
        float wb0 = wzb[r0 + i*16], wb1 = wzb[r0 + i*16 + 8];
#pragma unroll
        for (int j = 0; j < 8; j++) {
            int gn = n0 + cb + j*8;
            if (gn < Nn) {
                *reinterpret_cast<float2*>(Zb + (size_t)(r0 + i*16) * Nn + gn) =
                    make_float2(acc[i][j][0] + wb0, acc[i][j][1] + wb0);
                *reinterpret_cast<float2*>(Zb + (size_t)(r0 + i*16 + 8) * Nn + gn) =
                    make_float2(acc[i][j][2] + wb1, acc[i][j][3] + wb1);
            }
        }
    }
}

// =====================================================================
// K6: BN stats ; K7: final elementwise
// =====================================================================
__global__ __launch_bounds__(256) void bnstats_kernel(
    const float* __restrict__ bnw, const float* __restrict__ bnb)
{
    const int c = blockIdx.x, t = threadIdx.x;
    float s = 0.f, q = 0.f;
    for (int b = 0; b < Bb; b++) {
        const float4* row = reinterpret_cast<const float4*>(g_Z + ((size_t)b*Cc + c) * Nn);
        for (int n4 = t; n4 < Nn/4; n4 += 256) {
            float4 v = row[n4];
            s += (v.x+v.y)+(v.z+v.w);
            q += (v.x*v.x+v.y*v.y)+(v.z*v.z+v.w*v.w);
        }
    }
    __shared__ float ss[256], qs[256];
    ss[t] = s; qs[t] = q;
    __syncthreads();
    for (int o = 128; o > 0; o >>= 1) {
        if (t < o) { ss[t] += ss[t+o]; qs[t] += qs[t+o]; }
        __syncthreads();
    }
    if (t == 0) {
        const float inv_n = 1.0f / (float)(Bb * Nn);
        float mean = ss[0]*inv_n, var = qs[0]*inv_n - mean*mean;
        float sc = bnw[c] * rsqrtf(var + 1e-5f);
        g_scaleC[c] = sc;
        g_shiftC[c] = bnb[c] - mean*sc;
    }
}

__global__ __launch_bounds__(256) void final_kernel(
    const float* __restrict__ x, float* __restrict__ out)
{
    int i = blockIdx.x * 256 + threadIdx.x;
    int c = (i / (Nn/4)) & (Cc-1);
    float sc = g_scaleC[c], sh = g_shiftC[c];
    float4 z = reinterpret_cast<const float4*>(g_Z)[i];
    float4 xv = reinterpret_cast<const float4*>(x)[i];
    float4 o;
    o.x = fmaf(z.x, sc, sh) + xv.x; o.y = fmaf(z.y, sc, sh) + xv.y;
    o.z = fmaf(z.z, sc, sh) + xv.z; o.w = fmaf(z.w, sc, sh) + xv.w;
    reinterpret_cast<float4*>(out)[i] = o;
}

// =====================================================================
extern "C" void kernel_launch(void* const* d_in, const int* in_sizes, int n_in,
                              void* d_out, int out_size)
{
    (void)in_sizes; (void)n_in; (void)out_size;
    const float* x   = (const float*)d_in[0];
    const float* thw = (const float*)d_in[1];
    const float* thb = (const float*)d_in[2];
    const float* phw = (const float*)d_in[3];
    const float* phb = (const float*)d_in[4];
    const float* gw  = (const float*)d_in[5];
    const float* gbb = (const float*)d_in[6];
    const float* wzw = (const float*)d_in[7];
    const float* wzb = (const float*)d_in[8];
    const float* bnw = (const float*)d_in[9];
    const float* bnb = (const float*)d_in[10];
    float* out = (float*)d_out;

    cudaFuncSetAttribute(qkv_mma_kernel, cudaFuncAttributeMaxDynamicSharedMemorySize, QKV_SMEM);
    cudaFuncSetAttribute(sgemm_kernel,   cudaFuncAttributeMaxDynamicSharedMemorySize, GEMM_SMEM);
    cudaFuncSetAttribute(pv_kernel,      cudaFuncAttributeMaxDynamicSharedMemorySize, GEMM3_SMEM);
    cudaFuncSetAttribute(wz_mma_kernel,  cudaFuncAttributeMaxDynamicSharedMemorySize, GEMM3_SMEM);

    splitx_kernel<<<Bb*Cc, 256>>>(x);
    splitw_kernel<<<512, 256>>>(thw, phw, gw, wzw);
    qkv_mma_kernel<<<dim3(Np/128, 6, Bb), 128, QKV_SMEM>>>(thb, phb, gbb);
    sgemm_kernel<<<dim3(Np/128, Np/128, Bb), 128, GEMM_SMEM>>>();
    softmax_kernel<<<dim3(Nn, Bb), 256>>>();
    pv_kernel<<<dim3(Np/128, ICc/128, Bb), 128, GEMM3_SMEM>>>();
    wz_mma_kernel<<<dim3(Cc/128, Np/128, Bb), 128, GEMM3_SMEM>>>(wzb);
    bnstats_kernel<<<Cc, 256>>>(bnw, bnb);
    final_kernel<<<(Bb*Cc*Nn/4)/256, 256>>>(x, out);
}

// round 11
// speedup vs baseline: 3.2350x; 1.0485x over previous
#include <cuda_runtime.h>
#include <cuda_bf16.h>
#include <math.h>
#include <cstdint>

constexpr int Bb  = 8;
constexpr int Cc  = 512;
constexpr int Nn  = 3136;
constexpr int ICc = 256;
constexpr int Np  = 3200;   // 25*128

// ---------------- scratch ----------------
__device__ __align__(256) __nv_bfloat16 g_xh[Bb*Cc*Np];
__device__ __align__(256) __nv_bfloat16 g_xl[Bb*Cc*Np];
__device__ __align__(256) __nv_bfloat16 g_wh[3*ICc*Cc];
__device__ __align__(256) __nv_bfloat16 g_wl[3*ICc*Cc];
__device__ __align__(256) __nv_bfloat16 g_wzh[Cc*ICc];
__device__ __align__(256) __nv_bfloat16 g_wzl[Cc*ICc];
__device__ __align__(256) __nv_bfloat16 g_Qh[Bb*Np*ICc];
__device__ __align__(256) __nv_bfloat16 g_Ql[Bb*Np*ICc];
__device__ __align__(256) __nv_bfloat16 g_Kh[Bb*Np*ICc];
__device__ __align__(256) __nv_bfloat16 g_Kl[Bb*Np*ICc];
__device__ __align__(256) __nv_bfloat16 g_Vth[Bb*ICc*Np];   // [b][d][n]
__device__ __align__(256) __nv_bfloat16 g_Vtl[Bb*ICc*Np];
__device__ __align__(256) float         g_S [(size_t)Bb*Np*Np];
__device__ __align__(256) __nv_bfloat16 g_Ph[(size_t)Bb*Np*Np];
__device__ __align__(256) __nv_bfloat16 g_Yh[Bb*Np*ICc];    // [b][n][ic]
__device__ __align__(256) __nv_bfloat16 g_Yl[Bb*Np*ICc];
__device__ __align__(256) float g_Z[Bb*Cc*Nn];              // [b][c][n]
__device__ float g_scaleC[Cc];
__device__ float g_shiftC[Cc];

// ---------------- helpers ----------------
__device__ __forceinline__ uint32_t smem_u32(const void* p) {
    uint32_t a;
    asm("{ .reg .u64 t; cvta.to.shared.u64 t, %1; cvt.u32.u64 %0, t; }" : "=r"(a) : "l"(p));
    return a;
}
__device__ __forceinline__ void ldsm_x4(uint32_t* r, uint32_t addr) {
    asm volatile("ldmatrix.sync.aligned.m8n8.x4.shared.b16 {%0,%1,%2,%3}, [%4];"
                 : "=r"(r[0]), "=r"(r[1]), "=r"(r[2]), "=r"(r[3]) : "r"(addr));
}
__device__ __forceinline__ void ldsm_x4_t(uint32_t* r, uint32_t addr) {
    asm volatile("ldmatrix.sync.aligned.m8n8.x4.trans.shared.b16 {%0,%1,%2,%3}, [%4];"
                 : "=r"(r[0]), "=r"(r[1]), "=r"(r[2]), "=r"(r[3]) : "r"(addr));
}
__device__ __forceinline__ void mma_bf16(float* d, const uint32_t* a, const uint32_t* b) {
    asm volatile("mma.sync.aligned.m16n8k16.row.col.f32.bf16.bf16.f32 "
                 "{%0,%1,%2,%3}, {%4,%5,%6,%7}, {%8,%9}, {%0,%1,%2,%3};"
                 : "+f"(d[0]), "+f"(d[1]), "+f"(d[2]), "+f"(d[3])
                 : "r"(a[0]), "r"(a[1]), "r"(a[2]), "r"(a[3]), "r"(b[0]), "r"(b[1]));
}
#define CP16(sm, gp)  asm volatile("cp.async.ca.shared.global [%0], [%1], 16;" :: "r"(sm), "l"(gp) : "memory")
#define CP_COMMIT()   asm volatile("cp.async.commit_group;" ::: "memory")
#define CP_WAIT1()    asm volatile("cp.async.wait_group 1;" ::: "memory")
#define CP_WAIT0()    asm volatile("cp.async.wait_group 0;" ::: "memory")

__device__ __forceinline__ void bsplit(float v, __nv_bfloat16& h, __nv_bfloat16& l) {
    h = __float2bfloat16(v);
    l = __float2bfloat16(v - __bfloat162float(h));
}
__device__ __forceinline__ uint32_t pkb2(__nv_bfloat16 a, __nv_bfloat16 b) {
    __nv_bfloat162 p = __halves2bfloat162(a, b);
    return *reinterpret_cast<unsigned int*>(&p);
}
__device__ __forceinline__ uint2 pk4b(__nv_bfloat16 a, __nv_bfloat16 b, __nv_bfloat16 c, __nv_bfloat16 d) {
    return make_uint2(pkb2(a, b), pkb2(c, d));
}

constexpr int TSTR = 40;                         // [rows][k32] tile row stride (elems)
constexpr uint32_t TROW = TSTR * 2;              // bytes per row
constexpr uint32_t BUF_B = 128 * TROW;           // 10240 B per buffer
constexpr uint32_t STG4_B = 4 * BUF_B;           // sgemm stage
constexpr uint32_t STG3_B = 3 * BUF_B;           // pv/wz stage
constexpr int GEMM_SMEM  = 2 * STG4_B;           // 81920 B
constexpr int GEMM3_SMEM = 2 * STG3_B;           // 61440 B

constexpr int XSTR = 136;                        // x-tile [k32][n128]
constexpr uint32_t XROW = XSTR * 2;
constexpr uint32_t XBUF_B = 32 * XROW;           // 8704 B
constexpr uint32_t QSTG_B = 2 * XBUF_B + 2 * BUF_B;  // 37888 B
constexpr int QKV_SMEM = 2 * QSTG_B;             // 75776 B (>= 128*129*4 V stage)

// ---------------- GEMM chunk cores (u32 smem addrs, immediate offsets) ----------------
// 3-pass: acc += Ah*Bh + Ah*Bl + Al*Bh
__device__ __forceinline__ void chunk3(uint32_t aH, uint32_t aL, uint32_t bH, uint32_t bL,
                                       float acc[4][8][4])
{
#pragma unroll
    for (int kb = 0; kb < 64; kb += 32) {
        uint32_t ah[4][4], al[4][4], bh[8][2], bl[8][2];
#pragma unroll
        for (int i = 0; i < 4; i++) {
            ldsm_x4(ah[i], aH + i*(16*TROW) + kb);
            ldsm_x4(al[i], aL + i*(16*TROW) + kb);
        }
#pragma unroll
        for (int jp = 0; jp < 4; jp++) {
            uint32_t r[4];
            ldsm_x4(r, bH + jp*(16*TROW) + kb);
            bh[2*jp][0]=r[0]; bh[2*jp][1]=r[2]; bh[2*jp+1][0]=r[1]; bh[2*jp+1][1]=r[3];
            ldsm_x4(r, bL + jp*(16*TROW) + kb);
            bl[2*jp][0]=r[0]; bl[2*jp][1]=r[2]; bl[2*jp+1][0]=r[1]; bl[2*jp+1][1]=r[3];
        }
#pragma unroll
        for (int i = 0; i < 4; i++)
#pragma unroll
            for (int j = 0; j < 8; j++) {
                mma_bf16(acc[i][j], ah[i], bh[j]);
                mma_bf16(acc[i][j], ah[i], bl[j]);
                mma_bf16(acc[i][j], al[i], bh[j]);
            }
    }
}
// 2-pass: acc += Ah*(Bh + Bl)
__device__ __forceinline__ void chunk2(uint32_t aH, uint32_t bH, uint32_t bL,
                                       float acc[4][8][4])
{
#pragma unroll
    for (int kb = 0; kb < 64; kb += 32) {
        uint32_t ah[4][4], bh[8][2], bl[8][2];
#pragma unroll
        for (int i = 0; i < 4; i++)
            ldsm_x4(ah[i], aH + i*(16*TROW) + kb);
#pragma unroll
        for (int jp = 0; jp < 4; jp++) {
            uint32_t r[4];
            ldsm_x4(r, bH + jp*(16*TROW) + kb);
            bh[2*jp][0]=r[0]; bh[2*jp][1]=r[2]; bh[2*jp+1][0]=r[1]; bh[2*jp+1][1]=r[3];
            ldsm_x4(r, bL + jp*(16*TROW) + kb);
            bl[2*jp][0]=r[0]; bl[2*jp][1]=r[2]; bl[2*jp+1][0]=r[1]; bl[2*jp+1][1]=r[3];
        }
#pragma unroll
        for (int i = 0; i < 4; i++)
#pragma unroll
            for (int j = 0; j < 8; j++) {
                mma_bf16(acc[i][j], ah[i], bh[j]);
                mma_bf16(acc[i][j], ah[i], bl[j]);
            }
    }
}
// qkv 3-pass: A col-major [k32][m128] via trans ldsm; aT pre-offset per thread
__device__ __forceinline__ void chunkq3(uint32_t aH, uint32_t aL, uint32_t bH, uint32_t bL,
                                        float acc[4][8][4])
{
#pragma unroll
    for (int ks = 0; ks < 2; ks++) {
        const uint32_t ka = ks * (16*XROW), kb = ks * 32;
        uint32_t ah[4][4], al[4][4], bh[8][2], bl[8][2];
#pragma unroll
        for (int i = 0; i < 4; i++) {
            ldsm_x4_t(ah[i], aH + ka + i*32);
            ldsm_x4_t(al[i], aL + ka + i*32);
        }
#pragma unroll
        for (int jp = 0; jp < 4; jp++) {
            uint32_t r[4];
            ldsm_x4(r, bH + jp*(16*TROW) + kb);
            bh[2*jp][0]=r[0]; bh[2*jp][1]=r[2]; bh[2*jp+1][0]=r[1]; bh[2*jp+1][1]=r[3];
            ldsm_x4(r, bL + jp*(16*TROW) + kb);
            bl[2*jp][0]=r[0]; bl[2*jp][1]=r[2]; bl[2*jp+1][0]=r[1]; bl[2*jp+1][1]=r[3];
        }
#pragma unroll
        for (int i = 0; i < 4; i++)
#pragma unroll
            for (int j = 0; j < 8; j++) {
                mma_bf16(acc[i][j], ah[i], bh[j]);
                mma_bf16(acc[i][j], ah[i], bl[j]);
                mma_bf16(acc[i][j], al[i], bh[j]);
            }
    }
}
// qkv 2-pass (V): acc += Xh*(Wh + Wl)
__device__ __forceinline__ void chunkq2(uint32_t aH, uint32_t bH, uint32_t bL,
                                        float acc[4][8][4])
{
#pragma unroll
    for (int ks = 0; ks < 2; ks++) {
        const uint32_t ka = ks * (16*XROW), kb = ks * 32;
        uint32_t ah[4][4], bh[8][2], bl[8][2];
#pragma unroll
        for (int i = 0; i < 4; i++)
            ldsm_x4_t(ah[i], aH + ka + i*32);
#pragma unroll
        for (int jp = 0; jp < 4; jp++) {
            uint32_t r[4];
            ldsm_x4(r, bH + jp*(16*TROW) + kb);
            bh[2*jp][0]=r[0]; bh[2*jp][1]=r[2]; bh[2*jp+1][0]=r[1]; bh[2*jp+1][1]=r[3];
            ldsm_x4(r, bL + jp*(16*TROW) + kb);
            bl[2*jp][0]=r[0]; bl[2*jp][1]=r[2]; bl[2*jp+1][0]=r[1]; bl[2*jp+1][1]=r[3];
        }
#pragma unroll
        for (int i = 0; i < 4; i++)
#pragma unroll
            for (int j = 0; j < 8; j++) {
                mma_bf16(acc[i][j], ah[i], bh[j]);
                mma_bf16(acc[i][j], ah[i], bl[j]);
            }
    }
}

// =====================================================================
// K0a: split x ; K0b: split weights
// =====================================================================
__global__ __launch_bounds__(256) void splitx_kernel(const float* __restrict__ x)
{
    const int row = blockIdx.x, t = threadIdx.x;
    const float4* src = reinterpret_cast<const float4*>(x + (size_t)row * Nn);
    __nv_bfloat16* dh = g_xh + (size_t)row * Np;
    __nv_bfloat16* dl = g_xl + (size_t)row * Np;
    for (int n4 = t; n4 < Nn/4; n4 += 256) {
        float4 v = src[n4];
        __nv_bfloat16 h0,h1,h2,h3,l0,l1,l2,l3;
        bsplit(v.x,h0,l0); bsplit(v.y,h1,l1); bsplit(v.z,h2,l2); bsplit(v.w,h3,l3);
        *reinterpret_cast<uint2*>(dh + 4*n4) = pk4b(h0,h1,h2,h3);
        *reinterpret_cast<uint2*>(dl + 4*n4) = pk4b(l0,l1,l2,l3);
    }
}

__global__ __launch_bounds__(256) void splitw_kernel(
    const float* __restrict__ thw, const float* __restrict__ phw,
    const float* __restrict__ gw,  const float* __restrict__ wzw)
{
    int idx = blockIdx.x * 256 + threadIdx.x;
    int a = idx >> 15, off = idx & 32767;
    const float* src = (a == 0) ? thw : (a == 1) ? phw : (a == 2) ? gw : wzw;
    __nv_bfloat16* dh = (a < 3) ? g_wh + (size_t)a * ICc * Cc : g_wzh;
    __nv_bfloat16* dl = (a < 3) ? g_wl + (size_t)a * ICc * Cc : g_wzl;
    float4 v = reinterpret_cast<const float4*>(src)[off];
    __nv_bfloat16 h0,h1,h2,h3,l0,l1,l2,l3;
    bsplit(v.x,h0,l0); bsplit(v.y,h1,l1); bsplit(v.z,h2,l2); bsplit(v.w,h3,l3);
    *reinterpret_cast<uint2*>(dh + 4*off) = pk4b(h0,h1,h2,h3);
    *reinterpret_cast<uint2*>(dl + 4*off) = pk4b(l0,l1,l2,l3);
}

// =====================================================================
// K1: QKV via mma. Q/K 3-pass; V 2-pass. Hoisted addressing.
// =====================================================================
__global__ __launch_bounds__(128, 2) void qkv_mma_kernel(
    const float* __restrict__ thb, const float* __restrict__ phb,
    const float* __restrict__ gb)
{
    extern __shared__ __nv_bfloat16 dsm[];
    const uint32_t sb = smem_u32(dsm);
    const int t = threadIdx.x, lane = t & 31, wid = t >> 5;
    const int wm = wid & 1, wn = (wid >> 1) & 1;
    const int lr = lane & 15, lc = lane >> 4;
    const int nt = blockIdx.x, w = blockIdx.y >> 1, it = blockIdx.y & 1, b = blockIdx.z;
    const int n0 = nt * 128, i0 = it * 128;

    // gmem per-thread pointers
    const int rx = t >> 4, cx = t & 15;          // x loader: rows rx+8i, col cx*8
    const int rw = t >> 2, cw = t & 3;           // w loader: rows rw+32i, col cw*8
    const __nv_bfloat16* pXh = g_xh + (size_t)b*Cc*Np + n0 + (size_t)rx*Np + cx*8;
    const __nv_bfloat16* pXl = g_xl + (size_t)b*Cc*Np + n0 + (size_t)rx*Np + cx*8;
    const __nv_bfloat16* pWh = g_wh + (size_t)w*ICc*Cc + (size_t)(i0+rw)*Cc + cw*8;
    const __nv_bfloat16* pWl = g_wl + (size_t)w*ICc*Cc + (size_t)(i0+rw)*Cc + cw*8;
    const uint32_t dstX = sb + rx*XROW + cx*16;
    const uint32_t dstW = sb + 2*XBUF_B + rw*TROW + cw*16;

    // ldsm per-thread bases
    const int kr = (lane & 7) + ((lane >> 4) << 3);
    const int mo = ((lane >> 3) & 1) << 3;
    const uint32_t aoff = (uint32_t)(kr*XSTR + wm*64 + mo) * 2;
    const uint32_t boff = 2*XBUF_B + (uint32_t)((wn*64 + lr)*TSTR + lc*8) * 2;

    float acc[4][8][4] = {};
    constexpr int NC = Cc / 32;  // 16

    {
#pragma unroll
        for (int i = 0; i < 4; i++) {
            CP16(dstX + i*(8*XROW),          pXh + (size_t)i*8*Np);
            CP16(dstX + XBUF_B + i*(8*XROW), pXl + (size_t)i*8*Np);
            CP16(dstW + i*(32*TROW),         pWh + i*32*Cc);
            CP16(dstW + BUF_B + i*(32*TROW), pWl + i*32*Cc);
        }
        CP_COMMIT();
        pXh += (size_t)32*Np; pXl += (size_t)32*Np; pWh += 32; pWl += 32;
    }
    for (int c = 0; c < NC; c++) {
        if (c + 1 < NC) {
            const uint32_t so = ((c+1) & 1) * QSTG_B;
#pragma unroll
            for (int i = 0; i < 4; i++) {
                CP16(dstX + so + i*(8*XROW),          pXh + (size_t)i*8*Np);
                CP16(dstX + so + XBUF_B + i*(8*XROW), pXl + (size_t)i*8*Np);
                CP16(dstW + so + i*(32*TROW),         pWh + i*32*Cc);
                CP16(dstW + so + BUF_B + i*(32*TROW), pWl + i*32*Cc);
            }
            CP_COMMIT();
            pXh += (size_t)32*Np; pXl += (size_t)32*Np; pWh += 32; pWl += 32;
            CP_WAIT1();
        } else CP_WAIT0();
        __syncthreads();
        const uint32_t s = sb + (c & 1) * QSTG_B;
        if (w < 2) chunkq3(s + aoff, s + XBUF_B + aoff, s + boff, s + BUF_B + boff, acc);
        else       chunkq2(s + aoff, s + boff, s + BUF_B + boff, acc);
        __syncthreads();
    }

    const float* bias = (w == 0) ? thb : (w == 1) ? phb : gb;
    const int lr4 = lane >> 2, cb = wn*64 + 2*(lane & 3);

    if (w < 2) {
        __nv_bfloat16* dh = (w == 0) ? g_Qh : g_Kh;
        __nv_bfloat16* dl = (w == 0) ? g_Ql : g_Kl;
#pragma unroll
        for (int i = 0; i < 4; i++)
#pragma unroll
            for (int j = 0; j < 8; j++) {
                int gc = i0 + cb + j*8;
                float b0v = bias[gc], b1v = bias[gc+1];
                int gr = n0 + wm*64 + i*16 + lr4;
                if (gr < Nn) {
                    __nv_bfloat16 h0,h1,l0,l1;
                    bsplit(acc[i][j][0] + b0v, h0, l0);
                    bsplit(acc[i][j][1] + b1v, h1, l1);
                    size_t off = ((size_t)b*Np + gr) * ICc + gc;
                    *reinterpret_cast<uint32_t*>(dh + off) = pkb2(h0, h1);
                    *reinterpret_cast<uint32_t*>(dl + off) = pkb2(l0, l1);
                }
                if (gr + 8 < Nn) {
                    __nv_bfloat16 h0,h1,l0,l1;
                    bsplit(acc[i][j][2] + b0v, h0, l0);
                    bsplit(acc[i][j][3] + b1v, h1, l1);
                    size_t off = ((size_t)b*Np + gr + 8) * ICc + gc;
                    *reinterpret_cast<uint32_t*>(dh + off) = pkb2(h0, h1);
                    *reinterpret_cast<uint32_t*>(dl + off) = pkb2(l0, l1);
                }
            }
    } else {
        float* stg = reinterpret_cast<float*>(dsm);
        __syncthreads();
#pragma unroll
        for (int i = 0; i < 4; i++)
#pragma unroll
            for (int j = 0; j < 8; j++) {
                int ic = cb + j*8;
                float b0v = bias[i0 + ic], b1v = bias[i0 + ic + 1];
                int nl = wm*64 + i*16 + lr4;
                stg[nl*129 + ic]       = acc[i][j][0] + b0v;
                stg[nl*129 + ic + 1]   = acc[i][j][1] + b1v;
                stg[(nl+8)*129 + ic]   = acc[i][j][2] + b0v;
                stg[(nl+8)*129 + ic+1] = acc[i][j][3] + b1v;
            }
        __syncthreads();
#pragma unroll
        for (int k = 0; k < 64; k++) {
            int u = t + 128*k;
            int ir = u >> 6, np2 = u & 63;
            int gn = n0 + 2*np2;
            if (gn < Nn) {
                float v0 = stg[(2*np2)*129 + ir], v1 = stg[(2*np2+1)*129 + ir];
                __nv_bfloat16 h0,h1,l0,l1;
                bsplit(v0, h0, l0); bsplit(v1, h1, l1);
                size_t off = ((size_t)b*ICc + i0 + ir) * Np + gn;
                *reinterpret_cast<uint32_t*>(g_Vth + off) = pkb2(h0, h1);
                *reinterpret_cast<uint32_t*>(g_Vtl + off) = pkb2(l0, l1);
            }
        }
    }
}

// =====================================================================
// K2: S = Q K^T, 3-pass, hoisted addressing.
// =====================================================================
__global__ __launch_bounds__(128, 2) void sgemm_kernel()
{
    extern __shared__ __nv_bfloat16 dsm[];
    const uint32_t sb = smem_u32(dsm);
    const int t = threadIdx.x, lane = t & 31, wid = t >> 5;
    const int wm = wid & 1, wn = (wid >> 1) & 1;
    const int lr = lane & 15, lc = lane >> 4;
    const int q0 = blockIdx.x * 128, n0 = blockIdx.y * 128, b = blockIdx.z;

    const int rw = t >> 2, cw = t & 3;
    const size_t go = (size_t)rw * ICc + cw * 8;
    const __nv_bfloat16* pQh = g_Qh + ((size_t)b*Np + q0) * ICc + go;
    const __nv_bfloat16* pQl = g_Ql + ((size_t)b*Np + q0) * ICc + go;
    const __nv_bfloat16* pKh = g_Kh + ((size_t)b*Np + n0) * ICc + go;
    const __nv_bfloat16* pKl = g_Kl + ((size_t)b*Np + n0) * ICc + go;
    const uint32_t dst0 = sb + rw*TROW + cw*16;

    const uint32_t aoff = (uint32_t)((wm*64 + lr)*TSTR + lc*8) * 2;
    const uint32_t boff = 2*BUF_B + (uint32_t)((wn*64 + lr)*TSTR + lc*8) * 2;

    float acc[4][8][4] = {};
    constexpr int NC = ICc / 32;  // 8

    {
#pragma unroll
        for (int i = 0; i < 4; i++) {
            CP16(dst0 + i*(32*TROW),           pQh + i*32*ICc);
            CP16(dst0 + BUF_B + i*(32*TROW),   pQl + i*32*ICc);
            CP16(dst0 + 2*BUF_B + i*(32*TROW), pKh + i*32*ICc);
            CP16(dst0 + 3*BUF_B + i*(32*TROW), pKl + i*32*ICc);
        }
        CP_COMMIT();
        pQh += 32; pQl += 32; pKh += 32; pKl += 32;
    }
    for (int c = 0; c < NC; c++) {
        if (c + 1 < NC) {
            const uint32_t so = ((c+1) & 1) * STG4_B;
#pragma unroll
            for (int i = 0; i < 4; i++) {
                CP16(dst0 + so + i*(32*TROW),           pQh + i*32*ICc);
                CP16(dst0 + so + BUF_B + i*(32*TROW),   pQl + i*32*ICc);
                CP16(dst0 + so + 2*BUF_B + i*(32*TROW), pKh + i*32*ICc);
                CP16(dst0 + so + 3*BUF_B + i*(32*TROW), pKl + i*32*ICc);
            }
            CP_COMMIT();
            pQh += 32; pQl += 32; pKh += 32; pKl += 32;
            CP_WAIT1();
        } else CP_WAIT0();
        __syncthreads();
        const uint32_t s = sb + (c & 1) * STG4_B;
        chunk3(s + aoff, s + BUF_B + aoff, s + boff, s + BUF_B + boff, acc);
        __syncthreads();
    }

    float* So = g_S + ((size_t)b*Np + q0) * Np + n0;
    const int r0 = wm*64 + (lane >> 2), cb = wn*64 + 2*(lane & 3);
#pragma unroll
    for (int i = 0; i < 4; i++)
#pragma unroll
        for (int j = 0; j < 8; j++) {
            *reinterpret_cast<float2*>(So + (size_t)(r0 + i*16) * Np + cb + j*8) =
                make_float2(acc[i][j][0], acc[i][j][1]);
            *reinterpret_cast<float2*>(So + (size_t)(r0 + i*16 + 8) * Np + cb + j*8) =
                make_float2(acc[i][j][2], acc[i][j][3]);
        }
}

// =====================================================================
// K3: row softmax -> Ph only
// =====================================================================
__global__ __launch_bounds__(256) void softmax_kernel()
{
    const int r = blockIdx.x, b = blockIdx.y, t = threadIdx.x;
    const float4* Sr = reinterpret_cast<const float4*>(g_S + ((size_t)b*Np + r) * Np);
    float4 v[4];
    float mx = -1e30f;
#pragma unroll
    for (int i = 0; i < 4; i++) {
        int idx = t + 256*i;
        if (idx < 784) {
            v[i] = Sr[idx];
            mx = fmaxf(mx, fmaxf(fmaxf(v[i].x, v[i].y), fmaxf(v[i].z, v[i].w)));
        }
    }
    __shared__ float rd[8], rd2[8];
    float m = mx;
#pragma unroll
    for (int o = 16; o; o >>= 1) m = fmaxf(m, __shfl_xor_sync(0xffffffffu, m, o));
    if ((t & 31) == 0) rd[t >> 5] = m;
    __syncthreads();
    m = rd[0];
#pragma unroll
    for (int w = 1; w < 8; w++) m = fmaxf(m, rd[w]);
    float s = 0.f;
#pragma unroll
    for (int i = 0; i < 4; i++) {
        int idx = t + 256*i;
        if (idx < 784) {
            v[i].x = __expf(v[i].x - m); v[i].y = __expf(v[i].y - m);
            v[i].z = __expf(v[i].z - m); v[i].w = __expf(v[i].w - m);
            s += (v[i].x + v[i].y) + (v[i].z + v[i].w);
        }
    }
#pragma unroll
    for (int o = 16; o; o >>= 1) s += __shfl_xor_sync(0xffffffffu, s, o);
    if ((t & 31) == 0) rd2[t >> 5] = s;
    __syncthreads();
    s = rd2[0];
#pragma unroll
    for (int w = 1; w < 8; w++) s += rd2[w];
    float inv = 1.0f / s;
    __nv_bfloat16* Ph = g_Ph + ((size_t)b*Np + r) * Np;
#pragma unroll
    for (int i = 0; i < 4; i++) {
        int idx = t + 256*i;
        if (idx < 784) {
            *reinterpret_cast<uint2*>(Ph + 4*idx) =
                pk4b(__float2bfloat16(v[i].x*inv), __float2bfloat16(v[i].y*inv),
                     __float2bfloat16(v[i].z*inv), __float2bfloat16(v[i].w*inv));
        } else if (idx < 800) {
            *reinterpret_cast<uint2*>(Ph + 4*idx) = make_uint2(0u, 0u);
        }
    }
}

// =====================================================================
// K4: Y = P V, 2-pass, hoisted addressing, NC=98
// =====================================================================
__global__ __launch_bounds__(128, 2) void pv_kernel()
{
    extern __shared__ __nv_bfloat16 dsm[];
    const uint32_t sb = smem_u32(dsm);
    const int t = threadIdx.x, lane = t & 31, wid = t >> 5;
    const int wm = wid & 1, wn = (wid >> 1) & 1;
    const int lr = lane & 15, lc = lane >> 4;
    const int q0 = blockIdx.x * 128, d0 = blockIdx.y * 128, b = blockIdx.z;

    const int rw = t >> 2, cw = t & 3;
    const size_t go = (size_t)rw * Np + cw * 8;
    const __nv_bfloat16* pP = g_Ph + ((size_t)b*Np + q0) * Np + go;
    const __nv_bfloat16* pVh = g_Vth + ((size_t)b*ICc + d0) * Np + go;
    const __nv_bfloat16* pVl = g_Vtl + ((size_t)b*ICc + d0) * Np + go;
    const uint32_t dst0 = sb + rw*TROW + cw*16;

    const uint32_t aoff = (uint32_t)((wm*64 + lr)*TSTR + lc*8) * 2;
    const uint32_t boff = BUF_B + (uint32_t)((wn*64 + lr)*TSTR + lc*8) * 2;

    float acc[4][8][4] = {};
    constexpr int NC = Nn / 32;  // 98

    {
#pragma unroll
        for (int i = 0; i < 4; i++) {
            CP16(dst0 + i*(32*TROW),           pP  + (size_t)i*32*Np);
            CP16(dst0 + BUF_B + i*(32*TROW),   pVh + (size_t)i*32*Np);
            CP16(dst0 + 2*BUF_B + i*(32*TROW), pVl + (size_t)i*32*Np);
        }
        CP_COMMIT();
        pP += 32; pVh += 32; pVl += 32;
    }
    for (int c = 0; c < NC; c++) {
        if (c + 1 < NC) {
            const uint32_t so = ((c+1) & 1) * STG3_B;
#pragma unroll
            for (int i = 0; i < 4; i++) {
                CP16(dst0 + so + i*(32*TROW),           pP  + (size_t)i*32*Np);
                CP16(dst0 + so + BUF_B + i*(32*TROW),   pVh + (size_t)i*32*Np);
                CP16(dst0 + so + 2*BUF_B + i*(32*TROW), pVl + (size_t)i*32*Np);
            }
            CP_COMMIT();
            pP += 32; pVh += 32; pVl += 32;
            CP_WAIT1();
        } else CP_WAIT0();
        __syncthreads();
        const uint32_t s = sb + (c & 1) * STG3_B;
        chunk2(s + aoff, s + boff, s + BUF_B + boff, acc);
        __syncthreads();
    }

    const int r0 = wm*64 + (lane >> 2), cb = wn*64 + 2*(lane & 3);
#pragma unroll
    for (int i = 0; i < 4; i++)
#pragma unroll
        for (int j = 0; j < 8; j++) {
            int gc = d0 + cb + j*8;
            {
                int gr = q0 + r0 + i*16;
                __nv_bfloat16 h0,h1,l0,l1;
                bsplit(acc[i][j][0], h0, l0); bsplit(acc[i][j][1], h1, l1);
                size_t off = ((size_t)b*Np + gr) * ICc + gc;
                *reinterpret_cast<uint32_t*>(g_Yh + off) = pkb2(h0, h1);
                *reinterpret_cast<uint32_t*>(g_Yl + off) = pkb2(l0, l1);
            }
            {
                int gr = q0 + r0 + i*16 + 8;
                __nv_bfloat16 h0,h1,l0,l1;
                bsplit(acc[i][j][2], h0, l0); bsplit(acc[i][j][3], h1, l1);
                size_t off = ((size_t)b*Np + gr) * ICc + gc;
                *reinterpret_cast<uint32_t*>(g_Yh + off) = pkb2(h0, h1);
                *reinterpret_cast<uint32_t*>(g_Yl + off) = pkb2(l0, l1);
            }
        }
}

// =====================================================================
// K5: Z = Wz Y^T + b, 2-pass, hoisted addressing
// =====================================================================
__global__ __launch_bounds__(128, 2) void wz_mma_kernel(const float* __restrict__ wzb)
{
    extern __shared__ __nv_bfloat16 dsm[];
    const uint32_t sb = smem_u32(dsm);
    const int t = threadIdx.x, lane = t & 31, wid = t >> 5;
    const int wm = wid & 1, wn = (wid >> 1) & 1;
    const int lr = lane & 15, lc = lane >> 4;
    const int c0 = blockIdx.x * 128, n0 = blockIdx.y * 128, b = blockIdx.z;

    const int rw = t >> 2, cw = t & 3;
    const size_t go = (size_t)rw * ICc + cw * 8;
    const __nv_bfloat16* pA = g_wzh + (size_t)c0 * ICc + go;
    const __nv_bfloat16* pBh = g_Yh + ((size_t)b*Np + n0) * ICc + go;
    const __nv_bfloat16* pBl = g_Yl + ((size_t)b*Np + n0) * ICc + go;
    const uint32_t dst0 = sb + rw*TROW + cw*16;

    const uint32_t aoff = (uint32_t)((wm*64 + lr)*TSTR + lc*8) * 2;
    const uint32_t boff = BUF_B + (uint32_t)((wn*64 + lr)*TSTR + lc*8) * 2;

    float acc[4][8][4] = {};
    constexpr int NC = ICc / 32;  // 8

    {
#pragma unroll
        for (int i = 0; i < 4; i++) {
            CP16(dst0 + i*(32*TROW),           pA  + i*32*ICc);
            CP16(dst0 + BUF_B + i*(32*TROW),   pBh + i*32*ICc);
            CP16(dst0 + 2*BUF_B + i*(32*TROW), pBl + i*32*ICc);
        }
        CP_COMMIT();
        pA += 32; pBh += 32; pBl += 32;
    }
    for (int c = 0; c < NC; c++) {
        if (c + 1 < NC) {
            const uint32_t so = ((c+1) & 1) * STG3_B;
#pragma unroll
            for (int i = 0; i < 4; i++) {
                CP16(dst0 + so + i*(32*TROW),           pA  + i*32*ICc);
                CP16(dst0 + so + BUF_B + i*(32*TROW),   pBh + i*32*ICc);
                CP16(dst0 + so + 2*BUF_B + i*(32*TROW), pBl + i*32*ICc);
            }
            CP_COMMIT();
            pA += 32; pBh += 32; pBl += 32;
            CP_WAIT1();
        } else CP_WAIT0();
        __syncthreads();
        const uint32_t s = sb + (c & 1) * STG3_B;
        chunk2(s + aoff, s + boff, s + BUF_B + boff, acc);
        __syncthreads();
    }

    float* Zb = g_Z + (size_t)b * Cc * Nn;
    const int r0 = c0 + wm*64 + (lane >> 2), cb = wn*64 + 2*(lane & 3);
#pragma unroll
    for (int i = 0; i < 4; i++) {
        float wb0 = wzb[r0 + i*16], wb1 = wzb[r0 + i*16 + 8];
#pragma unroll
        for (int j = 0; j < 8; j++) {
            int gn = n0 + cb + j*8;
            if (gn < Nn) {
                *reinterpret_cast<float2*>(Zb + (size_t)(r0 + i*16) * Nn + gn) =
                    make_float2(acc[i][j][0] + wb0, acc[i][j][1] + wb0);
                *reinterpret_cast<float2*>(Zb + (size_t)(r0 + i*16 + 8) * Nn + gn) =
                    make_float2(acc[i][j][2] + wb1, acc[i][j][3] + wb1);
            }
        }
    }
}

// =====================================================================
// K6: BN stats ; K7: final elementwise
// =====================================================================
__global__ __launch_bounds__(256) void bnstats_kernel(
    const float* __restrict__ bnw, const float* __restrict__ bnb)
{
    const int c = blockIdx.x, t = threadIdx.x;
    float s = 0.f, q = 0.f;
    for (int b = 0; b < Bb; b++) {
        const float4* row = reinterpret_cast<const float4*>(g_Z + ((size_t)b*Cc + c) * Nn);
        for (int n4 = t; n4 < Nn/4; n4 += 256) {
            float4 v = row[n4];
            s += (v.x+v.y)+(v.z+v.w);
            q += (v.x*v.x+v.y*v.y)+(v.z*v.z+v.w*v.w);
        }
    }
    __shared__ float ss[256], qs[256];
    ss[t] = s; qs[t] = q;
    __syncthreads();
    for (int o = 128; o > 0; o >>= 1) {
        if (t < o) { ss[t] += ss[t+o]; qs[t] += qs[t+o]; }
        __syncthreads();
    }
    if (t == 0) {
        const float inv_n = 1.0f / (float)(Bb * Nn);
        float mean = ss[0]*inv_n, var = qs[0]*inv_n - mean*mean;
        float sc = bnw[c] * rsqrtf(var + 1e-5f);
        g_scaleC[c] = sc;
        g_shiftC[c] = bnb[c] - mean*sc;
    }
}

__global__ __launch_bounds__(256) void final_kernel(
    const float* __restrict__ x, float* __restrict__ out)
{
    int i = blockIdx.x * 256 + threadIdx.x;
    int c = (i / (Nn/4)) & (Cc-1);
    float sc = g_scaleC[c], sh = g_shiftC[c];
    float4 z = reinterpret_cast<const float4*>(g_Z)[i];
    float4 xv = reinterpret_cast<const float4*>(x)[i];
    float4 o;
    o.x = fmaf(z.x, sc, sh) + xv.x; o.y = fmaf(z.y, sc, sh) + xv.y;
    o.z = fmaf(z.z, sc, sh) + xv.z; o.w = fmaf(z.w, sc, sh) + xv.w;
    reinterpret_cast<float4*>(out)[i] = o;
}

// =====================================================================
extern "C" void kernel_launch(void* const* d_in, const int* in_sizes, int n_in,
                              void* d_out, int out_size)
{
    (void)in_sizes; (void)n_in; (void)out_size;
    const float* x   = (const float*)d_in[0];
    const float* thw = (const float*)d_in[1];
    const float* thb = (const float*)d_in[2];
    const float* phw = (const float*)d_in[3];
    const float* phb = (const float*)d_in[4];
    const float* gw  = (const float*)d_in[5];
    const float* gbb = (const float*)d_in[6];
    const float* wzw = (const float*)d_in[7];
    const float* wzb = (const float*)d_in[8];
    const float* bnw = (const float*)d_in[9];
    const float* bnb = (const float*)d_in[10];
    float* out = (float*)d_out;

    cudaFuncSetAttribute(qkv_mma_kernel, cudaFuncAttributeMaxDynamicSharedMemorySize, QKV_SMEM);
    cudaFuncSetAttribute(sgemm_kernel,   cudaFuncAttributeMaxDynamicSharedMemorySize, GEMM_SMEM);
    cudaFuncSetAttribute(pv_kernel,      cudaFuncAttributeMaxDynamicSharedMemorySize, GEMM3_SMEM);
    cudaFuncSetAttribute(wz_mma_kernel,  cudaFuncAttributeMaxDynamicSharedMemorySize, GEMM3_SMEM);

    splitx_kernel<<<Bb*Cc, 256>>>(x);
    splitw_kernel<<<512, 256>>>(thw, phw, gw, wzw);
    qkv_mma_kernel<<<dim3(Np/128, 6, Bb), 128, QKV_SMEM>>>(thb, phb, gbb);
    sgemm_kernel<<<dim3(Np/128, Np/128, Bb), 128, GEMM_SMEM>>>();
    softmax_kernel<<<dim3(Nn, Bb), 256>>>();
    pv_kernel<<<dim3(Np/128, ICc/128, Bb), 128, GEMM3_SMEM>>>();
    wz_mma_kernel<<<dim3(Cc/128, Np/128, Bb), 128, GEMM3_SMEM>>>(wzb);
    bnstats_kernel<<<Cc, 256>>>(bnw, bnb);
    final_kernel<<<(Bb*Cc*Nn/4)/256, 256>>>(x, out);
}